// round 11
// baseline (speedup 1.0000x reference)
#include <cuda_runtime.h>
#include <cuda_bf16.h>
#include <math.h>
#include <cstdint>

#define B_   2
#define S_   2048
#define E_   2048
#define H_   16
#define KVH_ 4
#define HD_  128
#define REP_ 4
#define M_   (B_*S_)     // 4096
#define NQKV 3072        // 2048 Q + 512 K + 512 V

// ---------------------------------------------------------------------------
// Scratch (__device__ globals; no allocations allowed)
// ---------------------------------------------------------------------------
__device__ float g_QKV[M_*NQKV];

__device__ __nv_bfloat16 g_xhi[M_*E_],  g_xlo[M_*E_];
__device__ __nv_bfloat16 g_aohi[M_*E_], g_aolo[M_*E_];
__device__ __nv_bfloat16 g_wqT_hi[E_*E_],        g_wqT_lo[E_*E_];
__device__ __nv_bfloat16 g_wkT_hi[KVH_*HD_*E_],  g_wkT_lo[KVH_*HD_*E_];
__device__ __nv_bfloat16 g_wvT_hi[KVH_*HD_*E_],  g_wvT_lo[KVH_*HD_*E_];
__device__ __nv_bfloat16 g_woT_hi[E_*E_],        g_woT_lo[E_*E_];

// flash operand layouts: Q [B][H][S][HD], K/V [B][KVH][S][HD]
__device__ __nv_bfloat16 g_Qbh[M_*H_*HD_],   g_Qbl[M_*H_*HD_];
__device__ __nv_bfloat16 g_Kbh[M_*KVH_*HD_], g_Kbl[M_*KVH_*HD_];
__device__ __nv_bfloat16 g_Vbh[M_*KVH_*HD_], g_Vbl[M_*KVH_*HD_];

// ---------------------------------------------------------------------------
// PTX helpers (non-'a' ISA only: mma.sync / ldmatrix / cp.async)
// ---------------------------------------------------------------------------
__device__ __forceinline__ uint32_t smem_to_u32(const void* p) {
    uint32_t a;
    asm("{ .reg .u64 t; cvta.to.shared.u64 t, %1; cvt.u32.u64 %0, t; }" : "=r"(a) : "l"(p));
    return a;
}
__device__ __forceinline__ void cp_async16(uint32_t saddr, const void* gptr) {
    asm volatile("cp.async.cg.shared.global [%0], [%1], 16;\n" :: "r"(saddr), "l"(gptr));
}
#define CP_COMMIT() asm volatile("cp.async.commit_group;\n" ::: "memory")
#define CP_WAIT(n)  asm volatile("cp.async.wait_group %0;\n" :: "n"(n) : "memory")

__device__ __forceinline__ void ldmatrix_x4(uint32_t* r, uint32_t addr) {
    asm volatile("ldmatrix.sync.aligned.m8n8.x4.shared.b16 {%0,%1,%2,%3}, [%4];\n"
                 : "=r"(r[0]), "=r"(r[1]), "=r"(r[2]), "=r"(r[3]) : "r"(addr));
}
__device__ __forceinline__ void ldmatrix_x4_trans(uint32_t* r, uint32_t addr) {
    asm volatile("ldmatrix.sync.aligned.m8n8.x4.trans.shared.b16 {%0,%1,%2,%3}, [%4];\n"
                 : "=r"(r[0]), "=r"(r[1]), "=r"(r[2]), "=r"(r[3]) : "r"(addr));
}
__device__ __forceinline__ void ldmatrix_x2(uint32_t* r, uint32_t addr) {
    asm volatile("ldmatrix.sync.aligned.m8n8.x2.shared.b16 {%0,%1}, [%2];\n"
                 : "=r"(r[0]), "=r"(r[1]) : "r"(addr));
}
__device__ __forceinline__ void mma_bf16(float* c, const uint32_t* a, const uint32_t* b) {
    asm volatile(
        "mma.sync.aligned.m16n8k16.row.col.f32.bf16.bf16.f32 "
        "{%0,%1,%2,%3}, {%4,%5,%6,%7}, {%8,%9}, {%0,%1,%2,%3};\n"
        : "+f"(c[0]), "+f"(c[1]), "+f"(c[2]), "+f"(c[3])
        : "r"(a[0]), "r"(a[1]), "r"(a[2]), "r"(a[3]), "r"(b[0]), "r"(b[1]));
}
__device__ __forceinline__ void split2(float a, float b, uint32_t& hi, uint32_t& lo) {
    __nv_bfloat162 h = __floats2bfloat162_rn(a, b);
    __nv_bfloat162 l = __floats2bfloat162_rn(a - __bfloat162float(h.x),
                                             b - __bfloat162float(h.y));
    hi = *(uint32_t*)&h;
    lo = *(uint32_t*)&l;
}

// ---------------------------------------------------------------------------
// Conversion kernels
// ---------------------------------------------------------------------------
__global__ void convert_hilo_kernel(const float* __restrict__ in,
                                    __nv_bfloat16* __restrict__ hi,
                                    __nv_bfloat16* __restrict__ lo, int n4)
{
    int i = blockIdx.x * blockDim.x + threadIdx.x;
    if (i >= n4) return;
    float4 v = ((const float4*)in)[i];
    float a[4] = {v.x, v.y, v.z, v.w};
    __nv_bfloat16 h[4], l[4];
    #pragma unroll
    for (int j = 0; j < 4; j++) {
        h[j] = __float2bfloat16_rn(a[j]);
        l[j] = __float2bfloat16_rn(a[j] - __bfloat162float(h[j]));
    }
    __nv_bfloat162* ph = (__nv_bfloat162*)(hi + 4 * (size_t)i);
    __nv_bfloat162* pl = (__nv_bfloat162*)(lo + 4 * (size_t)i);
    ph[0] = __nv_bfloat162{h[0], h[1]}; ph[1] = __nv_bfloat162{h[2], h[3]};
    pl[0] = __nv_bfloat162{l[0], l[1]}; pl[1] = __nv_bfloat162{l[2], l[3]};
}

// W[K x N] fp32 -> WT_hi/lo[N x K] bf16
__global__ void transpose_hilo_kernel(const float* __restrict__ W,
                                      __nv_bfloat16* __restrict__ Thi,
                                      __nv_bfloat16* __restrict__ Tlo,
                                      int K, int N)
{
    __shared__ float tile[32][33];
    int n0 = blockIdx.x * 32, k0 = blockIdx.y * 32;
    int tx = threadIdx.x, ty = threadIdx.y;
    #pragma unroll
    for (int r = 0; r < 4; r++)
        tile[ty + r * 8][tx] = W[(size_t)(k0 + ty + r * 8) * N + n0 + tx];
    __syncthreads();
    #pragma unroll
    for (int r = 0; r < 4; r++) {
        float v = tile[tx][ty + r * 8];
        __nv_bfloat16 h = __float2bfloat16_rn(v);
        __nv_bfloat16 l = __float2bfloat16_rn(v - __bfloat162float(h));
        size_t o = (size_t)(n0 + ty + r * 8) * K + k0 + tx;
        Thi[o] = h; Tlo[o] = l;
    }
}

// merged K/V weight transpose (z selects tensor) — same math as above
__global__ void transpose_hilo_kv_kernel(const float* __restrict__ Wk,
                                         const float* __restrict__ Wv,
                                         __nv_bfloat16* __restrict__ Kh, __nv_bfloat16* __restrict__ Kl,
                                         __nv_bfloat16* __restrict__ Vh, __nv_bfloat16* __restrict__ Vl)
{
    const int K = E_, N = KVH_ * HD_;
    const float* W = blockIdx.z ? Wv : Wk;
    __nv_bfloat16* Thi = blockIdx.z ? Vh : Kh;
    __nv_bfloat16* Tlo = blockIdx.z ? Vl : Kl;
    __shared__ float tile[32][33];
    int n0 = blockIdx.x * 32, k0 = blockIdx.y * 32;
    int tx = threadIdx.x, ty = threadIdx.y;
    #pragma unroll
    for (int r = 0; r < 4; r++)
        tile[ty + r * 8][tx] = W[(size_t)(k0 + ty + r * 8) * N + n0 + tx];
    __syncthreads();
    #pragma unroll
    for (int r = 0; r < 4; r++) {
        float v = tile[tx][ty + r * 8];
        __nv_bfloat16 h = __float2bfloat16_rn(v);
        __nv_bfloat16 l = __float2bfloat16_rn(v - __bfloat162float(h));
        size_t o = (size_t)(n0 + ty + r * 8) * K + k0 + tx;
        Thi[o] = h; Tlo[o] = l;
    }
}

// RoPE + hi/lo split; src = QKV buffer (row stride NQKV, col base h*HD)
__global__ void rope_split_kernel(const float* __restrict__ in,
                                  __nv_bfloat16* __restrict__ outh,
                                  __nv_bfloat16* __restrict__ outl,
                                  int nh, float scale)
{
    int idx = blockIdx.x * blockDim.x + threadIdx.x;
    int total = B_ * S_ * nh * (HD_ / 2);
    if (idx >= total) return;
    int d2 = idx & 63;
    int h  = (idx >> 6) % nh;
    int s  = (idx / (64 * nh)) % S_;
    int b  = idx / (64 * nh * S_);
    float p    = powf(100000.0f, (float)(2 * d2));   // inf for 2*d2 >= 8
    float freq = 1.0f / p;                           // 0 when p == inf
    float ang  = (float)s * freq;
    float sn, cs;
    sincosf(ang, &sn, &cs);
    size_t src = (size_t)(b * S_ + s) * NQKV + h * HD_ + 2 * d2;
    float tr = in[src], ti = in[src + 1];
    float o0 = (tr * cs - ti * sn) * scale;
    float o1 = (tr * sn + ti * cs) * scale;
    uint32_t hi, lo;
    split2(o0, o1, hi, lo);
    size_t dst = ((size_t)(b * nh + h) * S_ + s) * HD_ + 2 * d2;
    *(uint32_t*)(outh + dst) = hi;
    *(uint32_t*)(outl + dst) = lo;
}

// V: hi/lo split + relayout from QKV buffer
__global__ void v_split_kernel(const float* __restrict__ in,
                               __nv_bfloat16* __restrict__ outh,
                               __nv_bfloat16* __restrict__ outl)
{
    int idx = blockIdx.x * blockDim.x + threadIdx.x;
    int total = B_ * S_ * KVH_ * (HD_ / 2);
    if (idx >= total) return;
    int d2 = idx & 63;
    int g  = (idx >> 6) % KVH_;
    int s  = (idx / (64 * KVH_)) % S_;
    int b  = idx / (64 * KVH_ * S_);
    size_t src = (size_t)(b * S_ + s) * NQKV + g * HD_ + 2 * d2;
    float2 v = *(const float2*)(in + src);
    uint32_t hi, lo;
    split2(v.x, v.y, hi, lo);
    size_t dst = ((size_t)(b * KVH_ + g) * S_ + s) * HD_ + 2 * d2;
    *(uint32_t*)(outh + dst) = hi;
    *(uint32_t*)(outl + dst) = lo;
}

// ---------------------------------------------------------------------------
// Split-bf16 HMMA GEMM mainloop: 256x128 tile (2x arithmetic intensity),
// K chunks of 32, 3 stages, single sync per chunk. 8 warps, warp tile 64x64.
// ---------------------------------------------------------------------------
#define GBK      32
#define GROWB    80                    // 64B data + 16 pad
#define GARR_A   (256 * GROWB)         // 20480
#define GARR_B   (128 * GROWB)         // 10240
#define GSTAGE   (2 * GARR_A + 2 * GARR_B)  // 61440
#define GSTAGES  3
#define GSMEM    (GSTAGES * GSTAGE)    // 184320

__device__ __forceinline__ void gemm_mainloop(
    const __nv_bfloat16* __restrict__ Ahi, const __nv_bfloat16* __restrict__ Alo,
    const __nv_bfloat16* __restrict__ Bhi, const __nv_bfloat16* __restrict__ Blo,
    int rowA0, int rowB0, int K, uint32_t sb, int tid, float acc[4][8][4])
{
    const int wid  = tid >> 5;
    const int lane = tid & 31;
    const int warp_m = wid >> 1;        // 0..3 -> 64 rows each
    const int warp_n = wid & 1;         // 0..1 -> 64 cols each
    const int nchunks = K / GBK;

    const int a_lr = lane & 15;
    const int a_kc = (lane >> 4) * 8;
    const int b_lr = lane & 7;
    const int b_kc = ((lane >> 3) & 3) * 8;

    auto load_stage = [&](int chunk, int stage) {
        const int k0 = chunk * GBK;
        uint32_t s = sb + stage * GSTAGE;
        // A arrays: 256 rows x 4 16B-chunks = 1024 per array
        #pragma unroll
        for (int t = 0; t < 4; t++) {
            int u = t * 256 + tid;
            int r = u >> 2, c = u & 3;
            cp_async16(s + r * GROWB + c * 16,
                       Ahi + (size_t)(rowA0 + r) * K + k0 + c * 8);
            cp_async16(s + GARR_A + r * GROWB + c * 16,
                       Alo + (size_t)(rowA0 + r) * K + k0 + c * 8);
        }
        // B arrays: 128 rows x 4 = 512 per array
        #pragma unroll
        for (int t = 0; t < 2; t++) {
            int u = t * 256 + tid;
            int r = u >> 2, c = u & 3;
            cp_async16(s + 2 * GARR_A + r * GROWB + c * 16,
                       Bhi + (size_t)(rowB0 + r) * K + k0 + c * 8);
            cp_async16(s + 2 * GARR_A + GARR_B + r * GROWB + c * 16,
                       Blo + (size_t)(rowB0 + r) * K + k0 + c * 8);
        }
    };

    // prologue: stages 0 .. S-2
    #pragma unroll
    for (int s = 0; s < GSTAGES - 1; s++) { load_stage(s, s); CP_COMMIT(); }

    for (int i = 0; i < nchunks; i++) {
        CP_WAIT(GSTAGES - 2);
        __syncthreads();

        if (i + GSTAGES - 1 < nchunks)
            load_stage(i + GSTAGES - 1, (i + GSTAGES - 1) % GSTAGES);
        CP_COMMIT();

        const int stage = i % GSTAGES;
        const uint32_t sAhi = sb + stage * GSTAGE;
        const uint32_t sAlo = sAhi + GARR_A;
        const uint32_t sBhi = sAlo + GARR_A;
        const uint32_t sBlo = sBhi + GARR_B;

        #pragma unroll
        for (int ks = 0; ks < 2; ks++) {
            const int kb = ks * 32;
            uint32_t ah[4][4], al[4][4], bh[8][2], bl[8][2];
            #pragma unroll
            for (int mt = 0; mt < 4; mt++) {
                uint32_t aoff = (uint32_t)(warp_m * 64 + mt * 16 + a_lr) * GROWB + a_kc * 2 + kb;
                ldmatrix_x4(ah[mt], sAhi + aoff);
                ldmatrix_x4(al[mt], sAlo + aoff);
            }
            #pragma unroll
            for (int nt = 0; nt < 8; nt++) {
                uint32_t boff = (uint32_t)(warp_n * 64 + nt * 8 + b_lr) * GROWB + b_kc * 2 + kb;
                ldmatrix_x2(bh[nt], sBhi + boff);
                ldmatrix_x2(bl[nt], sBlo + boff);
            }
            #pragma unroll
            for (int mt = 0; mt < 4; mt++)
                #pragma unroll
                for (int nt = 0; nt < 8; nt++) {
                    mma_bf16(acc[mt][nt], ah[mt], bh[nt]);
                    mma_bf16(acc[mt][nt], ah[mt], bl[nt]);
                    mma_bf16(acc[mt][nt], al[mt], bh[nt]);
                }
        }
    }
}

// Generic GEMM (O projection): C[M,N] row stride N, M-tile = 256
__global__ void __launch_bounds__(256, 1)
gemm_bf16x3_kernel(const __nv_bfloat16* __restrict__ Ahi,
                   const __nv_bfloat16* __restrict__ Alo,
                   const __nv_bfloat16* __restrict__ Bhi,
                   const __nv_bfloat16* __restrict__ Blo,
                   const float* __restrict__ bias,
                   float* __restrict__ C,
                   int M, int N, int K)
{
    extern __shared__ char smem[];
    const uint32_t sb = smem_to_u32(smem);
    const int tid  = threadIdx.x;
    const int wid  = tid >> 5;
    const int lane = tid & 31;
    const int rowA0 = blockIdx.y * 256;
    const int rowB0 = blockIdx.x * 128;

    float acc[4][8][4];
    #pragma unroll
    for (int i = 0; i < 4; i++)
        #pragma unroll
        for (int j = 0; j < 8; j++)
            #pragma unroll
            for (int k = 0; k < 4; k++) acc[i][j][k] = 0.0f;

    gemm_mainloop(Ahi, Alo, Bhi, Blo, rowA0, rowB0, K, sb, tid, acc);

    const int warp_m = wid >> 1, warp_n = wid & 1;
    #pragma unroll
    for (int mt = 0; mt < 4; mt++)
        #pragma unroll
        for (int nt = 0; nt < 8; nt++) {
            int row = rowA0 + warp_m * 64 + mt * 16 + (lane >> 2);
            int col = rowB0 + warp_n * 64 + nt * 8 + (lane & 3) * 2;
            float2 b01 = *(const float2*)&bias[col];
            float2 o0 = {acc[mt][nt][0] + b01.x, acc[mt][nt][1] + b01.y};
            float2 o1 = {acc[mt][nt][2] + b01.x, acc[mt][nt][3] + b01.y};
            *(float2*)&C[(size_t)row * N + col]       = o0;
            *(float2*)&C[(size_t)(row + 8) * N + col] = o1;
        }
}

// Fused QKV projection: writes into QKV buffer [M][3072], M-tile = 256
__global__ void __launch_bounds__(256, 1)
gemm_qkv_kernel(const __nv_bfloat16* __restrict__ xhi,
                const __nv_bfloat16* __restrict__ xlo,
                const __nv_bfloat16* __restrict__ wqh, const __nv_bfloat16* __restrict__ wql,
                const __nv_bfloat16* __restrict__ wkh, const __nv_bfloat16* __restrict__ wkl,
                const __nv_bfloat16* __restrict__ wvh, const __nv_bfloat16* __restrict__ wvl,
                const float* __restrict__ bq, const float* __restrict__ bk,
                const float* __restrict__ bv,
                float* __restrict__ C)
{
    extern __shared__ char smem[];
    const uint32_t sb = smem_to_u32(smem);
    const int tid  = threadIdx.x;
    const int wid  = tid >> 5;
    const int lane = tid & 31;
    const int cCol = blockIdx.x;         // 0..23 (128-wide each)
    const int rowA0 = blockIdx.y * 256;

    const __nv_bfloat16 *Bh, *Bl;
    const float* bias;
    int rowB0;
    if (cCol < 16)      { Bh = wqh; Bl = wql; bias = bq; rowB0 = cCol * 128; }
    else if (cCol < 20) { Bh = wkh; Bl = wkl; bias = bk; rowB0 = (cCol - 16) * 128; }
    else                { Bh = wvh; Bl = wvl; bias = bv; rowB0 = (cCol - 20) * 128; }

    float acc[4][8][4];
    #pragma unroll
    for (int i = 0; i < 4; i++)
        #pragma unroll
        for (int j = 0; j < 8; j++)
            #pragma unroll
            for (int k = 0; k < 4; k++) acc[i][j][k] = 0.0f;

    gemm_mainloop(xhi, xlo, Bh, Bl, rowA0, rowB0, E_, sb, tid, acc);

    const int warp_m = wid >> 1, warp_n = wid & 1;
    #pragma unroll
    for (int mt = 0; mt < 4; mt++)
        #pragma unroll
        for (int nt = 0; nt < 8; nt++) {
            int row  = rowA0 + warp_m * 64 + mt * 16 + (lane >> 2);
            int bcol = rowB0 + warp_n * 64 + nt * 8 + (lane & 3) * 2;        // within bias
            int col  = cCol * 128 + warp_n * 64 + nt * 8 + (lane & 3) * 2;   // within QKV
            float2 b01 = *(const float2*)&bias[bcol];
            float2 o0 = {acc[mt][nt][0] + b01.x, acc[mt][nt][1] + b01.y};
            float2 o1 = {acc[mt][nt][2] + b01.x, acc[mt][nt][3] + b01.y};
            *(float2*)&C[(size_t)row * NQKV + col]       = o0;
            *(float2*)&C[(size_t)(row + 8) * NQKV + col] = o1;
        }
}

// ---------------------------------------------------------------------------
// Flash attention, split-bf16 HMMA. Br=128, Bc=64, HD=128, 8 warps.
// ---------------------------------------------------------------------------
#define FROWB  272
#define QARR   (128 * FROWB)        // 34816
#define KARR   (64 * FROWB)         // 17408
#define FSTG   (4 * KARR)           // 69632 (Kh,Kl,Vh,Vl)
#define FSMEM  (2 * QARR + 2 * FSTG)  // 208896

__global__ void __launch_bounds__(256, 1)
flash_mma_kernel(const __nv_bfloat16* __restrict__ Qh, const __nv_bfloat16* __restrict__ Ql,
                 const __nv_bfloat16* __restrict__ Kh, const __nv_bfloat16* __restrict__ Kl,
                 const __nv_bfloat16* __restrict__ Vh, const __nv_bfloat16* __restrict__ Vl,
                 __nv_bfloat16* __restrict__ Ohi, __nv_bfloat16* __restrict__ Olo)
{
    extern __shared__ char smem[];
    const uint32_t sb = smem_to_u32(smem);
    const int tid  = threadIdx.x;
    const int lane = tid & 31;
    const int warp = tid >> 5;
    const int qt = (int)gridDim.x - 1 - (int)blockIdx.x;   // heavy tiles first
    const int h = blockIdx.y, b = blockIdx.z;
    const int g  = h >> 2;
    const int q0 = qt * 128;
    const int nkv = 2 * qt + 2;

    const uint32_t sQh = sb, sQl = sb + QARR;
    const uint32_t sKV0 = sb + 2 * QARR;

    const size_t qbase  = ((size_t)(b * H_ + h) * S_ + q0) * HD_;
    const size_t kvbase = ((size_t)(b * KVH_ + g) * S_) * HD_;

    const uint32_t q_off = (uint32_t)(lane & 15) * FROWB + (lane >> 4) * 16;
    const uint32_t k_off = (uint32_t)((lane & 7) | ((lane >> 1) & 8)) * FROWB + ((lane >> 3) & 1) * 16;

    // -- prologue: Q tile (128 rows) + KV stage 0 --
    #pragma unroll
    for (int t = 0; t < 8; t++) {
        int u = t * 256 + tid;                  // 0..2047
        int r = u >> 4, cb = (u & 15) * 16, ce = (u & 15) * 8;
        cp_async16(sQh + r * FROWB + cb, Qh + qbase + (size_t)r * HD_ + ce);
        cp_async16(sQl + r * FROWB + cb, Ql + qbase + (size_t)r * HD_ + ce);
    }
    auto load_kv = [&](int kt, int buf) {
        uint32_t s = sKV0 + buf * FSTG;
        const size_t base = kvbase + (size_t)kt * 64 * HD_;
        #pragma unroll
        for (int t = 0; t < 4; t++) {
            int u = t * 256 + tid;              // 0..1023
            int r = u >> 4, cb = (u & 15) * 16, ce = (u & 15) * 8;
            size_t go = base + (size_t)r * HD_ + ce;
            uint32_t so = r * FROWB + cb;
            cp_async16(s + so,            Kh + go);
            cp_async16(s + KARR + so,     Kl + go);
            cp_async16(s + 2 * KARR + so, Vh + go);
            cp_async16(s + 3 * KARR + so, Vl + go);
        }
    };
    load_kv(0, 0);
    CP_COMMIT();

    float oacc[16][4];
    #pragma unroll
    for (int i = 0; i < 16; i++)
        #pragma unroll
        for (int j = 0; j < 4; j++) oacc[i][j] = 0.0f;
    float m0 = -INFINITY, m1 = -INFINITY, l0 = 0.0f, l1 = 0.0f;

    for (int kt = 0; kt < nkv; kt++) {
        __syncthreads();
        if (kt + 1 < nkv) { load_kv(kt + 1, (kt + 1) & 1); CP_COMMIT(); CP_WAIT(1); }
        else              { CP_WAIT(0); }
        __syncthreads();

        const uint32_t st  = sKV0 + (kt & 1) * FSTG;
        const uint32_t sKh = st, sKl = st + KARR, sVh = st + 2 * KARR, sVl = st + 3 * KARR;

        // ---- S = Q K^T ----
        float sacc[8][4];
        #pragma unroll
        for (int i = 0; i < 8; i++)
            #pragma unroll
            for (int j = 0; j < 4; j++) sacc[i][j] = 0.0f;

        #pragma unroll
        for (int kk = 0; kk < 8; kk++) {
            const uint32_t kb = kk * 32;
            uint32_t qh[4], ql[4];
            ldmatrix_x4(qh, sQh + (uint32_t)warp * 16 * FROWB + q_off + kb);
            ldmatrix_x4(ql, sQl + (uint32_t)warp * 16 * FROWB + q_off + kb);
            #pragma unroll
            for (int np = 0; np < 4; np++) {
                uint32_t kh[4], kl[4];
                ldmatrix_x4(kh, sKh + (uint32_t)np * 16 * FROWB + k_off + kb);
                ldmatrix_x4(kl, sKl + (uint32_t)np * 16 * FROWB + k_off + kb);
                mma_bf16(sacc[2*np],   qh, &kh[0]);
                mma_bf16(sacc[2*np],   qh, &kl[0]);
                mma_bf16(sacc[2*np],   ql, &kh[0]);
                mma_bf16(sacc[2*np+1], qh, &kh[2]);
                mma_bf16(sacc[2*np+1], qh, &kl[2]);
                mma_bf16(sacc[2*np+1], ql, &kh[2]);
            }
        }

        // ---- causal mask (diagonal region spans kv chunks 2qt, 2qt+1) ----
        if (kt >= 2 * qt) {
            const int rg0 = q0 + warp * 16 + (lane >> 2);
            const int cg0 = kt * 64 + (lane & 3) * 2;
            #pragma unroll
            for (int nt = 0; nt < 8; nt++)
                #pragma unroll
                for (int j = 0; j < 4; j++) {
                    int col = cg0 + nt * 8 + (j & 1);
                    int row = rg0 + (j >> 1) * 8;
                    if (col > row) sacc[nt][j] = -INFINITY;
                }
        }

        // ---- online softmax ----
        float mx0 = -INFINITY, mx1 = -INFINITY;
        #pragma unroll
        for (int nt = 0; nt < 8; nt++) {
            mx0 = fmaxf(mx0, fmaxf(sacc[nt][0], sacc[nt][1]));
            mx1 = fmaxf(mx1, fmaxf(sacc[nt][2], sacc[nt][3]));
        }
        mx0 = fmaxf(mx0, __shfl_xor_sync(0xFFFFFFFF, mx0, 1));
        mx0 = fmaxf(mx0, __shfl_xor_sync(0xFFFFFFFF, mx0, 2));
        mx1 = fmaxf(mx1, __shfl_xor_sync(0xFFFFFFFF, mx1, 1));
        mx1 = fmaxf(mx1, __shfl_xor_sync(0xFFFFFFFF, mx1, 2));
        float mn0 = fmaxf(m0, mx0), mn1 = fmaxf(m1, mx1);
        float al0 = __expf(m0 - mn0), al1 = __expf(m1 - mn1);
        m0 = mn0; m1 = mn1;

        float ps0 = 0.0f, ps1 = 0.0f;
        #pragma unroll
        for (int nt = 0; nt < 8; nt++) {
            float p0 = __expf(sacc[nt][0] - mn0);
            float p1 = __expf(sacc[nt][1] - mn0);
            float p2 = __expf(sacc[nt][2] - mn1);
            float p3 = __expf(sacc[nt][3] - mn1);
            sacc[nt][0] = p0; sacc[nt][1] = p1; sacc[nt][2] = p2; sacc[nt][3] = p3;
            ps0 += p0 + p1; ps1 += p2 + p3;
        }
        ps0 += __shfl_xor_sync(0xFFFFFFFF, ps0, 1);
        ps0 += __shfl_xor_sync(0xFFFFFFFF, ps0, 2);
        ps1 += __shfl_xor_sync(0xFFFFFFFF, ps1, 1);
        ps1 += __shfl_xor_sync(0xFFFFFFFF, ps1, 2);
        l0 = l0 * al0 + ps0;
        l1 = l1 * al1 + ps1;

        #pragma unroll
        for (int i = 0; i < 16; i++) {
            oacc[i][0] *= al0; oacc[i][1] *= al0;
            oacc[i][2] *= al1; oacc[i][3] *= al1;
        }

        // ---- O += P V ----
        #pragma unroll
        for (int tk = 0; tk < 4; tk++) {
            uint32_t ah[4], al_[4];
            split2(sacc[2*tk][0],   sacc[2*tk][1],   ah[0], al_[0]);
            split2(sacc[2*tk][2],   sacc[2*tk][3],   ah[1], al_[1]);
            split2(sacc[2*tk+1][0], sacc[2*tk+1][1], ah[2], al_[2]);
            split2(sacc[2*tk+1][2], sacc[2*tk+1][3], ah[3], al_[3]);
            #pragma unroll
            for (int dp = 0; dp < 8; dp++) {
                uint32_t vh[4], vl[4];
                const uint32_t vo = (uint32_t)tk * 16 * FROWB + q_off + dp * 32;
                ldmatrix_x4_trans(vh, sVh + vo);
                ldmatrix_x4_trans(vl, sVl + vo);
                mma_bf16(oacc[2*dp],   ah,  &vh[0]);
                mma_bf16(oacc[2*dp],   ah,  &vl[0]);
                mma_bf16(oacc[2*dp],   al_, &vh[0]);
                mma_bf16(oacc[2*dp+1], ah,  &vh[2]);
                mma_bf16(oacc[2*dp+1], ah,  &vl[2]);
                mma_bf16(oacc[2*dp+1], al_, &vh[2]);
            }
        }
    }

    // ---- epilogue: O / l -> hi/lo bf16 at [b][s][h*HD] ----
    const float il0 = 1.0f / l0, il1 = 1.0f / l1;
    const int r0 = q0 + warp * 16 + (lane >> 2);
    const int c0 = h * HD_ + (lane & 3) * 2;
    #pragma unroll
    for (int nt = 0; nt < 16; nt++) {
        float o0 = oacc[nt][0] * il0, o1 = oacc[nt][1] * il0;
        float o2 = oacc[nt][2] * il1, o3 = oacc[nt][3] * il1;
        uint32_t h0, l0r, h1, l1r;
        split2(o0, o1, h0, l0r);
        split2(o2, o3, h1, l1r);
        size_t i0 = (size_t)(b * S_ + r0)     * E_ + c0 + nt * 8;
        size_t i1 = (size_t)(b * S_ + r0 + 8) * E_ + c0 + nt * 8;
        *(uint32_t*)(Ohi + i0) = h0; *(uint32_t*)(Olo + i0) = l0r;
        *(uint32_t*)(Ohi + i1) = h1; *(uint32_t*)(Olo + i1) = l1r;
    }
}

// ---------------------------------------------------------------------------
extern "C" void kernel_launch(void* const* d_in, const int* in_sizes, int n_in,
                              void* d_out, int out_size)
{
    const float* x  = (const float*)d_in[0];
    const float* wq = (const float*)d_in[1];
    const float* bq = (const float*)d_in[2];
    const float* wk = (const float*)d_in[3];
    const float* bk = (const float*)d_in[4];
    const float* wv = (const float*)d_in[5];
    const float* bv = (const float*)d_in[6];
    const float* wo = (const float*)d_in[7];
    const float* bo = (const float*)d_in[8];
    float* out = (float*)d_out;

    float* QKVp;
    cudaGetSymbolAddress((void**)&QKVp, g_QKV);
    __nv_bfloat16 *xhi, *xlo, *aohi, *aolo;
    __nv_bfloat16 *wqh, *wql, *wkh, *wkl, *wvh, *wvl, *woh, *wol;
    __nv_bfloat16 *qbh, *qbl, *kbh, *kbl, *vbh, *vbl;
    cudaGetSymbolAddress((void**)&xhi,  g_xhi);
    cudaGetSymbolAddress((void**)&xlo,  g_xlo);
    cudaGetSymbolAddress((void**)&aohi, g_aohi);
    cudaGetSymbolAddress((void**)&aolo, g_aolo);
    cudaGetSymbolAddress((void**)&wqh, g_wqT_hi);
    cudaGetSymbolAddress((void**)&wql, g_wqT_lo);
    cudaGetSymbolAddress((void**)&wkh, g_wkT_hi);
    cudaGetSymbolAddress((void**)&wkl, g_wkT_lo);
    cudaGetSymbolAddress((void**)&wvh, g_wvT_hi);
    cudaGetSymbolAddress((void**)&wvl, g_wvT_lo);
    cudaGetSymbolAddress((void**)&woh, g_woT_hi);
    cudaGetSymbolAddress((void**)&wol, g_woT_lo);
    cudaGetSymbolAddress((void**)&qbh, g_Qbh);
    cudaGetSymbolAddress((void**)&qbl, g_Qbl);
    cudaGetSymbolAddress((void**)&kbh, g_Kbh);
    cudaGetSymbolAddress((void**)&kbl, g_Kbl);
    cudaGetSymbolAddress((void**)&vbh, g_Vbh);
    cudaGetSymbolAddress((void**)&vbl, g_Vbl);

    cudaFuncSetAttribute(gemm_qkv_kernel,
                         cudaFuncAttributeMaxDynamicSharedMemorySize, GSMEM);
    cudaFuncSetAttribute(gemm_bf16x3_kernel,
                         cudaFuncAttributeMaxDynamicSharedMemorySize, GSMEM);
    cudaFuncSetAttribute(flash_mma_kernel,
                         cudaFuncAttributeMaxDynamicSharedMemorySize, FSMEM);

    // conversions (K/V transposes merged into one launch)
    {
        int n4 = M_ * E_ / 4;
        convert_hilo_kernel<<<(n4 + 255) / 256, 256>>>(x, xhi, xlo, n4);
        dim3 blk(32, 8);
        transpose_hilo_kernel<<<dim3(E_ / 32, E_ / 32), blk>>>(wq, wqh, wql, E_, E_);
        transpose_hilo_kv_kernel<<<dim3((KVH_ * HD_) / 32, E_ / 32, 2), blk>>>(
            wk, wv, wkh, wkl, wvh, wvl);
    }

    // Fused QKV projection (N = 3072, M-tile 256)
    gemm_qkv_kernel<<<dim3(NQKV / 128, M_ / 256), 256, GSMEM>>>(
        xhi, xlo, wqh, wql, wkh, wkl, wvh, wvl, bq, bk, bv, QKVp);

    // RoPE + split + relayout (reads QKV buffer)
    {
        int totq = B_ * S_ * H_ * (HD_ / 2);
        int totk = B_ * S_ * KVH_ * (HD_ / 2);
        float qscale = 1.0f / sqrtf((float)HD_);
        rope_split_kernel<<<(totq + 255) / 256, 256>>>(QKVp, qbh, qbl, H_, qscale);
        rope_split_kernel<<<(totk + 255) / 256, 256>>>(QKVp + 2048, kbh, kbl, KVH_, 1.0f);
        v_split_kernel<<<(totk + 255) / 256, 256>>>(QKVp + 2560, vbh, vbl);
    }

    // Flash attention (HMMA split-bf16, Br=128)
    flash_mma_kernel<<<dim3(S_ / 128, H_, B_), 256, FSMEM>>>(
        qbh, qbl, kbh, kbl, vbh, vbl, aohi, aolo);

    // wo transpose (deferred; only needed by O-proj)
    {
        dim3 blk(32, 8);
        transpose_hilo_kernel<<<dim3(E_ / 32, E_ / 32), blk>>>(wo, woh, wol, E_, E_);
    }

    // Output projection -> d_out (M-tile 256)
    gemm_bf16x3_kernel<<<dim3(E_ / 128, M_ / 256), 256, GSMEM>>>(
        aohi, aolo, woh, wol, bo, out, M_, E_, E_);
}

// round 12
// speedup vs baseline: 1.0043x; 1.0043x over previous
#include <cuda_runtime.h>
#include <cuda_bf16.h>
#include <math.h>
#include <cstdint>

#define B_   2
#define S_   2048
#define E_   2048
#define H_   16
#define KVH_ 4
#define HD_  128
#define REP_ 4
#define M_   (B_*S_)     // 4096
#define NQKV 3072        // 2048 Q + 512 K + 512 V

// ---------------------------------------------------------------------------
// Scratch (__device__ globals; no allocations allowed)
// ---------------------------------------------------------------------------
__device__ float g_QKV[M_*NQKV];

__device__ __nv_bfloat16 g_xhi[M_*E_],  g_xlo[M_*E_];
__device__ __nv_bfloat16 g_aohi[M_*E_], g_aolo[M_*E_];
__device__ __nv_bfloat16 g_wqT_hi[E_*E_],        g_wqT_lo[E_*E_];
__device__ __nv_bfloat16 g_wkT_hi[KVH_*HD_*E_],  g_wkT_lo[KVH_*HD_*E_];
__device__ __nv_bfloat16 g_wvT_hi[KVH_*HD_*E_],  g_wvT_lo[KVH_*HD_*E_];
__device__ __nv_bfloat16 g_woT_hi[E_*E_],        g_woT_lo[E_*E_];

// flash operand layouts: Q [B][H][S][HD], K/V [B][KVH][S][HD]
__device__ __nv_bfloat16 g_Qbh[M_*H_*HD_],   g_Qbl[M_*H_*HD_];
__device__ __nv_bfloat16 g_Kbh[M_*KVH_*HD_], g_Kbl[M_*KVH_*HD_];
__device__ __nv_bfloat16 g_Vbh[M_*KVH_*HD_], g_Vbl[M_*KVH_*HD_];

// ---------------------------------------------------------------------------
// PTX helpers (non-'a' ISA only: mma.sync / ldmatrix / cp.async)
// ---------------------------------------------------------------------------
__device__ __forceinline__ uint32_t smem_to_u32(const void* p) {
    uint32_t a;
    asm("{ .reg .u64 t; cvta.to.shared.u64 t, %1; cvt.u32.u64 %0, t; }" : "=r"(a) : "l"(p));
    return a;
}
__device__ __forceinline__ void cp_async16(uint32_t saddr, const void* gptr) {
    asm volatile("cp.async.cg.shared.global [%0], [%1], 16;\n" :: "r"(saddr), "l"(gptr));
}
#define CP_COMMIT() asm volatile("cp.async.commit_group;\n" ::: "memory")
#define CP_WAIT(n)  asm volatile("cp.async.wait_group %0;\n" :: "n"(n) : "memory")

__device__ __forceinline__ void ldmatrix_x4(uint32_t* r, uint32_t addr) {
    asm volatile("ldmatrix.sync.aligned.m8n8.x4.shared.b16 {%0,%1,%2,%3}, [%4];\n"
                 : "=r"(r[0]), "=r"(r[1]), "=r"(r[2]), "=r"(r[3]) : "r"(addr));
}
__device__ __forceinline__ void ldmatrix_x4_trans(uint32_t* r, uint32_t addr) {
    asm volatile("ldmatrix.sync.aligned.m8n8.x4.trans.shared.b16 {%0,%1,%2,%3}, [%4];\n"
                 : "=r"(r[0]), "=r"(r[1]), "=r"(r[2]), "=r"(r[3]) : "r"(addr));
}
__device__ __forceinline__ void ldmatrix_x2(uint32_t* r, uint32_t addr) {
    asm volatile("ldmatrix.sync.aligned.m8n8.x2.shared.b16 {%0,%1}, [%2];\n"
                 : "=r"(r[0]), "=r"(r[1]) : "r"(addr));
}
__device__ __forceinline__ void mma_bf16(float* c, const uint32_t* a, const uint32_t* b) {
    asm volatile(
        "mma.sync.aligned.m16n8k16.row.col.f32.bf16.bf16.f32 "
        "{%0,%1,%2,%3}, {%4,%5,%6,%7}, {%8,%9}, {%0,%1,%2,%3};\n"
        : "+f"(c[0]), "+f"(c[1]), "+f"(c[2]), "+f"(c[3])
        : "r"(a[0]), "r"(a[1]), "r"(a[2]), "r"(a[3]), "r"(b[0]), "r"(b[1]));
}
__device__ __forceinline__ void split2(float a, float b, uint32_t& hi, uint32_t& lo) {
    __nv_bfloat162 h = __floats2bfloat162_rn(a, b);
    __nv_bfloat162 l = __floats2bfloat162_rn(a - __bfloat162float(h.x),
                                             b - __bfloat162float(h.y));
    hi = *(uint32_t*)&h;
    lo = *(uint32_t*)&l;
}

// ---------------------------------------------------------------------------
// Conversion kernels
// ---------------------------------------------------------------------------
__global__ void convert_hilo_kernel(const float* __restrict__ in,
                                    __nv_bfloat16* __restrict__ hi,
                                    __nv_bfloat16* __restrict__ lo, int n4)
{
    int i = blockIdx.x * blockDim.x + threadIdx.x;
    if (i >= n4) return;
    float4 v = ((const float4*)in)[i];
    float a[4] = {v.x, v.y, v.z, v.w};
    __nv_bfloat16 h[4], l[4];
    #pragma unroll
    for (int j = 0; j < 4; j++) {
        h[j] = __float2bfloat16_rn(a[j]);
        l[j] = __float2bfloat16_rn(a[j] - __bfloat162float(h[j]));
    }
    __nv_bfloat162* ph = (__nv_bfloat162*)(hi + 4 * (size_t)i);
    __nv_bfloat162* pl = (__nv_bfloat162*)(lo + 4 * (size_t)i);
    ph[0] = __nv_bfloat162{h[0], h[1]}; ph[1] = __nv_bfloat162{h[2], h[3]};
    pl[0] = __nv_bfloat162{l[0], l[1]}; pl[1] = __nv_bfloat162{l[2], l[3]};
}

// W[K x N] fp32 -> WT_hi/lo[N x K] bf16
__global__ void transpose_hilo_kernel(const float* __restrict__ W,
                                      __nv_bfloat16* __restrict__ Thi,
                                      __nv_bfloat16* __restrict__ Tlo,
                                      int K, int N)
{
    __shared__ float tile[32][33];
    int n0 = blockIdx.x * 32, k0 = blockIdx.y * 32;
    int tx = threadIdx.x, ty = threadIdx.y;
    #pragma unroll
    for (int r = 0; r < 4; r++)
        tile[ty + r * 8][tx] = W[(size_t)(k0 + ty + r * 8) * N + n0 + tx];
    __syncthreads();
    #pragma unroll
    for (int r = 0; r < 4; r++) {
        float v = tile[tx][ty + r * 8];
        __nv_bfloat16 h = __float2bfloat16_rn(v);
        __nv_bfloat16 l = __float2bfloat16_rn(v - __bfloat162float(h));
        size_t o = (size_t)(n0 + ty + r * 8) * K + k0 + tx;
        Thi[o] = h; Tlo[o] = l;
    }
}

// merged K/V weight transpose (z selects tensor)
__global__ void transpose_hilo_kv_kernel(const float* __restrict__ Wk,
                                         const float* __restrict__ Wv,
                                         __nv_bfloat16* __restrict__ Kh, __nv_bfloat16* __restrict__ Kl,
                                         __nv_bfloat16* __restrict__ Vh, __nv_bfloat16* __restrict__ Vl)
{
    const int K = E_, N = KVH_ * HD_;
    const float* W = blockIdx.z ? Wv : Wk;
    __nv_bfloat16* Thi = blockIdx.z ? Vh : Kh;
    __nv_bfloat16* Tlo = blockIdx.z ? Vl : Kl;
    __shared__ float tile[32][33];
    int n0 = blockIdx.x * 32, k0 = blockIdx.y * 32;
    int tx = threadIdx.x, ty = threadIdx.y;
    #pragma unroll
    for (int r = 0; r < 4; r++)
        tile[ty + r * 8][tx] = W[(size_t)(k0 + ty + r * 8) * N + n0 + tx];
    __syncthreads();
    #pragma unroll
    for (int r = 0; r < 4; r++) {
        float v = tile[tx][ty + r * 8];
        __nv_bfloat16 h = __float2bfloat16_rn(v);
        __nv_bfloat16 l = __float2bfloat16_rn(v - __bfloat162float(h));
        size_t o = (size_t)(n0 + ty + r * 8) * K + k0 + tx;
        Thi[o] = h; Tlo[o] = l;
    }
}

// RoPE + hi/lo split; src = QKV buffer (row stride NQKV, col base h*HD)
__global__ void rope_split_kernel(const float* __restrict__ in,
                                  __nv_bfloat16* __restrict__ outh,
                                  __nv_bfloat16* __restrict__ outl,
                                  int nh, float scale)
{
    int idx = blockIdx.x * blockDim.x + threadIdx.x;
    int total = B_ * S_ * nh * (HD_ / 2);
    if (idx >= total) return;
    int d2 = idx & 63;
    int h  = (idx >> 6) % nh;
    int s  = (idx / (64 * nh)) % S_;
    int b  = idx / (64 * nh * S_);
    float p    = powf(100000.0f, (float)(2 * d2));   // inf for 2*d2 >= 8
    float freq = 1.0f / p;                           // 0 when p == inf
    float ang  = (float)s * freq;
    float sn, cs;
    sincosf(ang, &sn, &cs);
    size_t src = (size_t)(b * S_ + s) * NQKV + h * HD_ + 2 * d2;
    float tr = in[src], ti = in[src + 1];
    float o0 = (tr * cs - ti * sn) * scale;
    float o1 = (tr * sn + ti * cs) * scale;
    uint32_t hi, lo;
    split2(o0, o1, hi, lo);
    size_t dst = ((size_t)(b * nh + h) * S_ + s) * HD_ + 2 * d2;
    *(uint32_t*)(outh + dst) = hi;
    *(uint32_t*)(outl + dst) = lo;
}

// V: hi/lo split + relayout from QKV buffer
__global__ void v_split_kernel(const float* __restrict__ in,
                               __nv_bfloat16* __restrict__ outh,
                               __nv_bfloat16* __restrict__ outl)
{
    int idx = blockIdx.x * blockDim.x + threadIdx.x;
    int total = B_ * S_ * KVH_ * (HD_ / 2);
    if (idx >= total) return;
    int d2 = idx & 63;
    int g  = (idx >> 6) % KVH_;
    int s  = (idx / (64 * KVH_)) % S_;
    int b  = idx / (64 * KVH_ * S_);
    size_t src = (size_t)(b * S_ + s) * NQKV + g * HD_ + 2 * d2;
    float2 v = *(const float2*)(in + src);
    uint32_t hi, lo;
    split2(v.x, v.y, hi, lo);
    size_t dst = ((size_t)(b * KVH_ + g) * S_ + s) * HD_ + 2 * d2;
    *(uint32_t*)(outh + dst) = hi;
    *(uint32_t*)(outl + dst) = lo;
}

// ---------------------------------------------------------------------------
// Split-bf16 HMMA GEMM mainloop: 256x128 tile, K chunks of 32, 3 stages,
// single sync per chunk, FLASH-STYLE fine interleave: A frags up front,
// then per nt-step 2 B-LDSMs (pipelined one step ahead) + 12 MMAs.
// ---------------------------------------------------------------------------
#define GBK      32
#define GROWB    80                    // 64B data + 16 pad
#define GARR_A   (256 * GROWB)         // 20480
#define GARR_B   (128 * GROWB)         // 10240
#define GSTAGE   (2 * GARR_A + 2 * GARR_B)  // 61440
#define GSTAGES  3
#define GSMEM    (GSTAGES * GSTAGE)    // 184320

__device__ __forceinline__ void gemm_mainloop(
    const __nv_bfloat16* __restrict__ Ahi, const __nv_bfloat16* __restrict__ Alo,
    const __nv_bfloat16* __restrict__ Bhi, const __nv_bfloat16* __restrict__ Blo,
    int rowA0, int rowB0, int K, uint32_t sb, int tid, float acc[4][8][4])
{
    const int wid  = tid >> 5;
    const int lane = tid & 31;
    const int warp_m = wid >> 1;        // 0..3 -> 64 rows each
    const int warp_n = wid & 1;         // 0..1 -> 64 cols each
    const int nchunks = K / GBK;

    const int a_lr = lane & 15;
    const int a_kc = (lane >> 4) * 8;
    const int b_lr = lane & 7;
    const int b_kc = ((lane >> 3) & 3) * 8;

    auto load_stage = [&](int chunk, int stage) {
        const int k0 = chunk * GBK;
        uint32_t s = sb + stage * GSTAGE;
        #pragma unroll
        for (int t = 0; t < 4; t++) {
            int u = t * 256 + tid;
            int r = u >> 2, c = u & 3;
            cp_async16(s + r * GROWB + c * 16,
                       Ahi + (size_t)(rowA0 + r) * K + k0 + c * 8);
            cp_async16(s + GARR_A + r * GROWB + c * 16,
                       Alo + (size_t)(rowA0 + r) * K + k0 + c * 8);
        }
        #pragma unroll
        for (int t = 0; t < 2; t++) {
            int u = t * 256 + tid;
            int r = u >> 2, c = u & 3;
            cp_async16(s + 2 * GARR_A + r * GROWB + c * 16,
                       Bhi + (size_t)(rowB0 + r) * K + k0 + c * 8);
            cp_async16(s + 2 * GARR_A + GARR_B + r * GROWB + c * 16,
                       Blo + (size_t)(rowB0 + r) * K + k0 + c * 8);
        }
    };

    #pragma unroll
    for (int s = 0; s < GSTAGES - 1; s++) { load_stage(s, s); CP_COMMIT(); }

    for (int i = 0; i < nchunks; i++) {
        CP_WAIT(GSTAGES - 2);
        __syncthreads();

        if (i + GSTAGES - 1 < nchunks)
            load_stage(i + GSTAGES - 1, (i + GSTAGES - 1) % GSTAGES);
        CP_COMMIT();

        const int stage = i % GSTAGES;
        const uint32_t sAhi = sb + stage * GSTAGE;
        const uint32_t sAlo = sAhi + GARR_A;
        const uint32_t sBhi = sAlo + GARR_A;
        const uint32_t sBlo = sBhi + GARR_B;

        #pragma unroll
        for (int ks = 0; ks < 2; ks++) {
            const int kb = ks * 32;
            uint32_t ah[4][4], al[4][4];
            #pragma unroll
            for (int mt = 0; mt < 4; mt++) {
                uint32_t aoff = (uint32_t)(warp_m * 64 + mt * 16 + a_lr) * GROWB + a_kc * 2 + kb;
                ldmatrix_x4(ah[mt], sAhi + aoff);
                ldmatrix_x4(al[mt], sAlo + aoff);
            }
            // B frags: double-buffered, loaded one nt-step ahead, interleaved
            uint32_t bh[2][2], bl[2][2];
            {
                uint32_t boff = (uint32_t)(warp_n * 64 + b_lr) * GROWB + b_kc * 2 + kb;
                ldmatrix_x2(bh[0], sBhi + boff);
                ldmatrix_x2(bl[0], sBlo + boff);
            }
            #pragma unroll
            for (int nt = 0; nt < 8; nt++) {
                const int cur = nt & 1;
                if (nt < 7) {
                    uint32_t boff = (uint32_t)(warp_n * 64 + (nt + 1) * 8 + b_lr) * GROWB + b_kc * 2 + kb;
                    ldmatrix_x2(bh[cur ^ 1], sBhi + boff);
                    ldmatrix_x2(bl[cur ^ 1], sBlo + boff);
                }
                #pragma unroll
                for (int mt = 0; mt < 4; mt++) {
                    mma_bf16(acc[mt][nt], ah[mt], bh[cur]);
                    mma_bf16(acc[mt][nt], ah[mt], bl[cur]);
                    mma_bf16(acc[mt][nt], al[mt], bh[cur]);
                }
            }
        }
    }
}

// Generic GEMM (O projection): C[M,N] row stride N, M-tile = 256
__global__ void __launch_bounds__(256, 1)
gemm_bf16x3_kernel(const __nv_bfloat16* __restrict__ Ahi,
                   const __nv_bfloat16* __restrict__ Alo,
                   const __nv_bfloat16* __restrict__ Bhi,
                   const __nv_bfloat16* __restrict__ Blo,
                   const float* __restrict__ bias,
                   float* __restrict__ C,
                   int M, int N, int K)
{
    extern __shared__ char smem[];
    const uint32_t sb = smem_to_u32(smem);
    const int tid  = threadIdx.x;
    const int wid  = tid >> 5;
    const int lane = tid & 31;
    const int rowA0 = blockIdx.y * 256;
    const int rowB0 = blockIdx.x * 128;

    float acc[4][8][4];
    #pragma unroll
    for (int i = 0; i < 4; i++)
        #pragma unroll
        for (int j = 0; j < 8; j++)
            #pragma unroll
            for (int k = 0; k < 4; k++) acc[i][j][k] = 0.0f;

    gemm_mainloop(Ahi, Alo, Bhi, Blo, rowA0, rowB0, K, sb, tid, acc);

    const int warp_m = wid >> 1, warp_n = wid & 1;
    #pragma unroll
    for (int mt = 0; mt < 4; mt++)
        #pragma unroll
        for (int nt = 0; nt < 8; nt++) {
            int row = rowA0 + warp_m * 64 + mt * 16 + (lane >> 2);
            int col = rowB0 + warp_n * 64 + nt * 8 + (lane & 3) * 2;
            float2 b01 = *(const float2*)&bias[col];
            float2 o0 = {acc[mt][nt][0] + b01.x, acc[mt][nt][1] + b01.y};
            float2 o1 = {acc[mt][nt][2] + b01.x, acc[mt][nt][3] + b01.y};
            *(float2*)&C[(size_t)row * N + col]       = o0;
            *(float2*)&C[(size_t)(row + 8) * N + col] = o1;
        }
}

// Fused QKV projection: writes into QKV buffer [M][3072], M-tile = 256
__global__ void __launch_bounds__(256, 1)
gemm_qkv_kernel(const __nv_bfloat16* __restrict__ xhi,
                const __nv_bfloat16* __restrict__ xlo,
                const __nv_bfloat16* __restrict__ wqh, const __nv_bfloat16* __restrict__ wql,
                const __nv_bfloat16* __restrict__ wkh, const __nv_bfloat16* __restrict__ wkl,
                const __nv_bfloat16* __restrict__ wvh, const __nv_bfloat16* __restrict__ wvl,
                const float* __restrict__ bq, const float* __restrict__ bk,
                const float* __restrict__ bv,
                float* __restrict__ C)
{
    extern __shared__ char smem[];
    const uint32_t sb = smem_to_u32(smem);
    const int tid  = threadIdx.x;
    const int wid  = tid >> 5;
    const int lane = tid & 31;
    const int cCol = blockIdx.x;         // 0..23
    const int rowA0 = blockIdx.y * 256;

    const __nv_bfloat16 *Bh, *Bl;
    const float* bias;
    int rowB0;
    if (cCol < 16)      { Bh = wqh; Bl = wql; bias = bq; rowB0 = cCol * 128; }
    else if (cCol < 20) { Bh = wkh; Bl = wkl; bias = bk; rowB0 = (cCol - 16) * 128; }
    else                { Bh = wvh; Bl = wvl; bias = bv; rowB0 = (cCol - 20) * 128; }

    float acc[4][8][4];
    #pragma unroll
    for (int i = 0; i < 4; i++)
        #pragma unroll
        for (int j = 0; j < 8; j++)
            #pragma unroll
            for (int k = 0; k < 4; k++) acc[i][j][k] = 0.0f;

    gemm_mainloop(xhi, xlo, Bh, Bl, rowA0, rowB0, E_, sb, tid, acc);

    const int warp_m = wid >> 1, warp_n = wid & 1;
    #pragma unroll
    for (int mt = 0; mt < 4; mt++)
        #pragma unroll
        for (int nt = 0; nt < 8; nt++) {
            int row  = rowA0 + warp_m * 64 + mt * 16 + (lane >> 2);
            int bcol = rowB0 + warp_n * 64 + nt * 8 + (lane & 3) * 2;
            int col  = cCol * 128 + warp_n * 64 + nt * 8 + (lane & 3) * 2;
            float2 b01 = *(const float2*)&bias[bcol];
            float2 o0 = {acc[mt][nt][0] + b01.x, acc[mt][nt][1] + b01.y};
            float2 o1 = {acc[mt][nt][2] + b01.x, acc[mt][nt][3] + b01.y};
            *(float2*)&C[(size_t)row * NQKV + col]       = o0;
            *(float2*)&C[(size_t)(row + 8) * NQKV + col] = o1;
        }
}

// ---------------------------------------------------------------------------
// Flash attention, split-bf16 HMMA. Br=128, Bc=64, HD=128, 8 warps.
// ---------------------------------------------------------------------------
#define FROWB  272
#define QARR   (128 * FROWB)        // 34816
#define KARR   (64 * FROWB)         // 17408
#define FSTG   (4 * KARR)           // 69632 (Kh,Kl,Vh,Vl)
#define FSMEM  (2 * QARR + 2 * FSTG)  // 208896

__global__ void __launch_bounds__(256, 1)
flash_mma_kernel(const __nv_bfloat16* __restrict__ Qh, const __nv_bfloat16* __restrict__ Ql,
                 const __nv_bfloat16* __restrict__ Kh, const __nv_bfloat16* __restrict__ Kl,
                 const __nv_bfloat16* __restrict__ Vh, const __nv_bfloat16* __restrict__ Vl,
                 __nv_bfloat16* __restrict__ Ohi, __nv_bfloat16* __restrict__ Olo)
{
    extern __shared__ char smem[];
    const uint32_t sb = smem_to_u32(smem);
    const int tid  = threadIdx.x;
    const int lane = tid & 31;
    const int warp = tid >> 5;
    const int qt = (int)gridDim.x - 1 - (int)blockIdx.x;   // heavy tiles first
    const int h = blockIdx.y, b = blockIdx.z;
    const int g  = h >> 2;
    const int q0 = qt * 128;
    const int nkv = 2 * qt + 2;

    const uint32_t sQh = sb, sQl = sb + QARR;
    const uint32_t sKV0 = sb + 2 * QARR;

    const size_t qbase  = ((size_t)(b * H_ + h) * S_ + q0) * HD_;
    const size_t kvbase = ((size_t)(b * KVH_ + g) * S_) * HD_;

    const uint32_t q_off = (uint32_t)(lane & 15) * FROWB + (lane >> 4) * 16;
    const uint32_t k_off = (uint32_t)((lane & 7) | ((lane >> 1) & 8)) * FROWB + ((lane >> 3) & 1) * 16;

    // -- prologue: Q tile (128 rows) + KV stage 0 --
    #pragma unroll
    for (int t = 0; t < 8; t++) {
        int u = t * 256 + tid;                  // 0..2047
        int r = u >> 4, cb = (u & 15) * 16, ce = (u & 15) * 8;
        cp_async16(sQh + r * FROWB + cb, Qh + qbase + (size_t)r * HD_ + ce);
        cp_async16(sQl + r * FROWB + cb, Ql + qbase + (size_t)r * HD_ + ce);
    }
    auto load_kv = [&](int kt, int buf) {
        uint32_t s = sKV0 + buf * FSTG;
        const size_t base = kvbase + (size_t)kt * 64 * HD_;
        #pragma unroll
        for (int t = 0; t < 4; t++) {
            int u = t * 256 + tid;              // 0..1023
            int r = u >> 4, cb = (u & 15) * 16, ce = (u & 15) * 8;
            size_t go = base + (size_t)r * HD_ + ce;
            uint32_t so = r * FROWB + cb;
            cp_async16(s + so,            Kh + go);
            cp_async16(s + KARR + so,     Kl + go);
            cp_async16(s + 2 * KARR + so, Vh + go);
            cp_async16(s + 3 * KARR + so, Vl + go);
        }
    };
    load_kv(0, 0);
    CP_COMMIT();

    float oacc[16][4];
    #pragma unroll
    for (int i = 0; i < 16; i++)
        #pragma unroll
        for (int j = 0; j < 4; j++) oacc[i][j] = 0.0f;
    float m0 = -INFINITY, m1 = -INFINITY, l0 = 0.0f, l1 = 0.0f;

    for (int kt = 0; kt < nkv; kt++) {
        __syncthreads();
        if (kt + 1 < nkv) { load_kv(kt + 1, (kt + 1) & 1); CP_COMMIT(); CP_WAIT(1); }
        else              { CP_WAIT(0); }
        __syncthreads();

        const uint32_t st  = sKV0 + (kt & 1) * FSTG;
        const uint32_t sKh = st, sKl = st + KARR, sVh = st + 2 * KARR, sVl = st + 3 * KARR;

        // ---- S = Q K^T ----
        float sacc[8][4];
        #pragma unroll
        for (int i = 0; i < 8; i++)
            #pragma unroll
            for (int j = 0; j < 4; j++) sacc[i][j] = 0.0f;

        #pragma unroll
        for (int kk = 0; kk < 8; kk++) {
            const uint32_t kb = kk * 32;
            uint32_t qh[4], ql[4];
            ldmatrix_x4(qh, sQh + (uint32_t)warp * 16 * FROWB + q_off + kb);
            ldmatrix_x4(ql, sQl + (uint32_t)warp * 16 * FROWB + q_off + kb);
            #pragma unroll
            for (int np = 0; np < 4; np++) {
                uint32_t kh[4], kl[4];
                ldmatrix_x4(kh, sKh + (uint32_t)np * 16 * FROWB + k_off + kb);
                ldmatrix_x4(kl, sKl + (uint32_t)np * 16 * FROWB + k_off + kb);
                mma_bf16(sacc[2*np],   qh, &kh[0]);
                mma_bf16(sacc[2*np],   qh, &kl[0]);
                mma_bf16(sacc[2*np],   ql, &kh[0]);
                mma_bf16(sacc[2*np+1], qh, &kh[2]);
                mma_bf16(sacc[2*np+1], qh, &kl[2]);
                mma_bf16(sacc[2*np+1], ql, &kh[2]);
            }
        }

        // ---- causal mask (diagonal region spans kv chunks 2qt, 2qt+1) ----
        if (kt >= 2 * qt) {
            const int rg0 = q0 + warp * 16 + (lane >> 2);
            const int cg0 = kt * 64 + (lane & 3) * 2;
            #pragma unroll
            for (int nt = 0; nt < 8; nt++)
                #pragma unroll
                for (int j = 0; j < 4; j++) {
                    int col = cg0 + nt * 8 + (j & 1);
                    int row = rg0 + (j >> 1) * 8;
                    if (col > row) sacc[nt][j] = -INFINITY;
                }
        }

        // ---- online softmax ----
        float mx0 = -INFINITY, mx1 = -INFINITY;
        #pragma unroll
        for (int nt = 0; nt < 8; nt++) {
            mx0 = fmaxf(mx0, fmaxf(sacc[nt][0], sacc[nt][1]));
            mx1 = fmaxf(mx1, fmaxf(sacc[nt][2], sacc[nt][3]));
        }
        mx0 = fmaxf(mx0, __shfl_xor_sync(0xFFFFFFFF, mx0, 1));
        mx0 = fmaxf(mx0, __shfl_xor_sync(0xFFFFFFFF, mx0, 2));
        mx1 = fmaxf(mx1, __shfl_xor_sync(0xFFFFFFFF, mx1, 1));
        mx1 = fmaxf(mx1, __shfl_xor_sync(0xFFFFFFFF, mx1, 2));
        float mn0 = fmaxf(m0, mx0), mn1 = fmaxf(m1, mx1);
        float al0 = __expf(m0 - mn0), al1 = __expf(m1 - mn1);
        m0 = mn0; m1 = mn1;

        float ps0 = 0.0f, ps1 = 0.0f;
        #pragma unroll
        for (int nt = 0; nt < 8; nt++) {
            float p0 = __expf(sacc[nt][0] - mn0);
            float p1 = __expf(sacc[nt][1] - mn0);
            float p2 = __expf(sacc[nt][2] - mn1);
            float p3 = __expf(sacc[nt][3] - mn1);
            sacc[nt][0] = p0; sacc[nt][1] = p1; sacc[nt][2] = p2; sacc[nt][3] = p3;
            ps0 += p0 + p1; ps1 += p2 + p3;
        }
        ps0 += __shfl_xor_sync(0xFFFFFFFF, ps0, 1);
        ps0 += __shfl_xor_sync(0xFFFFFFFF, ps0, 2);
        ps1 += __shfl_xor_sync(0xFFFFFFFF, ps1, 1);
        ps1 += __shfl_xor_sync(0xFFFFFFFF, ps1, 2);
        l0 = l0 * al0 + ps0;
        l1 = l1 * al1 + ps1;

        #pragma unroll
        for (int i = 0; i < 16; i++) {
            oacc[i][0] *= al0; oacc[i][1] *= al0;
            oacc[i][2] *= al1; oacc[i][3] *= al1;
        }

        // ---- O += P V ----
        #pragma unroll
        for (int tk = 0; tk < 4; tk++) {
            uint32_t ah[4], al_[4];
            split2(sacc[2*tk][0],   sacc[2*tk][1],   ah[0], al_[0]);
            split2(sacc[2*tk][2],   sacc[2*tk][3],   ah[1], al_[1]);
            split2(sacc[2*tk+1][0], sacc[2*tk+1][1], ah[2], al_[2]);
            split2(sacc[2*tk+1][2], sacc[2*tk+1][3], ah[3], al_[3]);
            #pragma unroll
            for (int dp = 0; dp < 8; dp++) {
                uint32_t vh[4], vl[4];
                const uint32_t vo = (uint32_t)tk * 16 * FROWB + q_off + dp * 32;
                ldmatrix_x4_trans(vh, sVh + vo);
                ldmatrix_x4_trans(vl, sVl + vo);
                mma_bf16(oacc[2*dp],   ah,  &vh[0]);
                mma_bf16(oacc[2*dp],   ah,  &vl[0]);
                mma_bf16(oacc[2*dp],   al_, &vh[0]);
                mma_bf16(oacc[2*dp+1], ah,  &vh[2]);
                mma_bf16(oacc[2*dp+1], ah,  &vl[2]);
                mma_bf16(oacc[2*dp+1], al_, &vh[2]);
            }
        }
    }

    // ---- epilogue: O / l -> hi/lo bf16 at [b][s][h*HD] ----
    const float il0 = 1.0f / l0, il1 = 1.0f / l1;
    const int r0 = q0 + warp * 16 + (lane >> 2);
    const int c0 = h * HD_ + (lane & 3) * 2;
    #pragma unroll
    for (int nt = 0; nt < 16; nt++) {
        float o0 = oacc[nt][0] * il0, o1 = oacc[nt][1] * il0;
        float o2 = oacc[nt][2] * il1, o3 = oacc[nt][3] * il1;
        uint32_t h0, l0r, h1, l1r;
        split2(o0, o1, h0, l0r);
        split2(o2, o3, h1, l1r);
        size_t i0 = (size_t)(b * S_ + r0)     * E_ + c0 + nt * 8;
        size_t i1 = (size_t)(b * S_ + r0 + 8) * E_ + c0 + nt * 8;
        *(uint32_t*)(Ohi + i0) = h0; *(uint32_t*)(Olo + i0) = l0r;
        *(uint32_t*)(Ohi + i1) = h1; *(uint32_t*)(Olo + i1) = l1r;
    }
}

// ---------------------------------------------------------------------------
extern "C" void kernel_launch(void* const* d_in, const int* in_sizes, int n_in,
                              void* d_out, int out_size)
{
    const float* x  = (const float*)d_in[0];
    const float* wq = (const float*)d_in[1];
    const float* bq = (const float*)d_in[2];
    const float* wk = (const float*)d_in[3];
    const float* bk = (const float*)d_in[4];
    const float* wv = (const float*)d_in[5];
    const float* bv = (const float*)d_in[6];
    const float* wo = (const float*)d_in[7];
    const float* bo = (const float*)d_in[8];
    float* out = (float*)d_out;

    float* QKVp;
    cudaGetSymbolAddress((void**)&QKVp, g_QKV);
    __nv_bfloat16 *xhi, *xlo, *aohi, *aolo;
    __nv_bfloat16 *wqh, *wql, *wkh, *wkl, *wvh, *wvl, *woh, *wol;
    __nv_bfloat16 *qbh, *qbl, *kbh, *kbl, *vbh, *vbl;
    cudaGetSymbolAddress((void**)&xhi,  g_xhi);
    cudaGetSymbolAddress((void**)&xlo,  g_xlo);
    cudaGetSymbolAddress((void**)&aohi, g_aohi);
    cudaGetSymbolAddress((void**)&aolo, g_aolo);
    cudaGetSymbolAddress((void**)&wqh, g_wqT_hi);
    cudaGetSymbolAddress((void**)&wql, g_wqT_lo);
    cudaGetSymbolAddress((void**)&wkh, g_wkT_hi);
    cudaGetSymbolAddress((void**)&wkl, g_wkT_lo);
    cudaGetSymbolAddress((void**)&wvh, g_wvT_hi);
    cudaGetSymbolAddress((void**)&wvl, g_wvT_lo);
    cudaGetSymbolAddress((void**)&woh, g_woT_hi);
    cudaGetSymbolAddress((void**)&wol, g_woT_lo);
    cudaGetSymbolAddress((void**)&qbh, g_Qbh);
    cudaGetSymbolAddress((void**)&qbl, g_Qbl);
    cudaGetSymbolAddress((void**)&kbh, g_Kbh);
    cudaGetSymbolAddress((void**)&kbl, g_Kbl);
    cudaGetSymbolAddress((void**)&vbh, g_Vbh);
    cudaGetSymbolAddress((void**)&vbl, g_Vbl);

    cudaFuncSetAttribute(gemm_qkv_kernel,
                         cudaFuncAttributeMaxDynamicSharedMemorySize, GSMEM);
    cudaFuncSetAttribute(gemm_bf16x3_kernel,
                         cudaFuncAttributeMaxDynamicSharedMemorySize, GSMEM);
    cudaFuncSetAttribute(flash_mma_kernel,
                         cudaFuncAttributeMaxDynamicSharedMemorySize, FSMEM);

    // conversions (K/V transposes merged into one launch)
    {
        int n4 = M_ * E_ / 4;
        convert_hilo_kernel<<<(n4 + 255) / 256, 256>>>(x, xhi, xlo, n4);
        dim3 blk(32, 8);
        transpose_hilo_kernel<<<dim3(E_ / 32, E_ / 32), blk>>>(wq, wqh, wql, E_, E_);
        transpose_hilo_kv_kernel<<<dim3((KVH_ * HD_) / 32, E_ / 32, 2), blk>>>(
            wk, wv, wkh, wkl, wvh, wvl);
    }

    // Fused QKV projection (N = 3072, M-tile 256)
    gemm_qkv_kernel<<<dim3(NQKV / 128, M_ / 256), 256, GSMEM>>>(
        xhi, xlo, wqh, wql, wkh, wkl, wvh, wvl, bq, bk, bv, QKVp);

    // RoPE + split + relayout (reads QKV buffer)
    {
        int totq = B_ * S_ * H_ * (HD_ / 2);
        int totk = B_ * S_ * KVH_ * (HD_ / 2);
        float qscale = 1.0f / sqrtf((float)HD_);
        rope_split_kernel<<<(totq + 255) / 256, 256>>>(QKVp, qbh, qbl, H_, qscale);
        rope_split_kernel<<<(totk + 255) / 256, 256>>>(QKVp + 2048, kbh, kbl, KVH_, 1.0f);
        v_split_kernel<<<(totk + 255) / 256, 256>>>(QKVp + 2560, vbh, vbl);
    }

    // Flash attention (HMMA split-bf16, Br=128)
    flash_mma_kernel<<<dim3(S_ / 128, H_, B_), 256, FSMEM>>>(
        qbh, qbl, kbh, kbl, vbh, vbl, aohi, aolo);

    // wo transpose (deferred; only needed by O-proj)
    {
        dim3 blk(32, 8);
        transpose_hilo_kernel<<<dim3(E_ / 32, E_ / 32), blk>>>(wo, woh, wol, E_, E_);
    }

    // Output projection -> d_out (M-tile 256)
    gemm_bf16x3_kernel<<<dim3(E_ / 128, M_ / 256), 256, GSMEM>>>(
        aohi, aolo, woh, wol, bo, out, M_, E_, E_);
}

// round 13
// speedup vs baseline: 1.2084x; 1.2033x over previous
#include <cuda_runtime.h>
#include <cuda_bf16.h>
#include <cuda_fp16.h>
#include <math.h>
#include <cstdint>

#define B_   2
#define S_   2048
#define E_   2048
#define H_   16
#define KVH_ 4
#define HD_  128
#define REP_ 4
#define M_   (B_*S_)     // 4096
#define NQKV 3072        // 2048 Q + 512 K + 512 V

// ---------------------------------------------------------------------------
// Scratch (__device__ globals; no allocations allowed)
// ---------------------------------------------------------------------------
__device__ float g_QKV[M_*NQKV];

// fp16 operands for projection GEMMs: A split hi/lo, weights single fp16
__device__ __half g_xhi[M_*E_],  g_xlo[M_*E_];
__device__ __half g_aohi[M_*E_], g_aolo[M_*E_];
__device__ __half g_wqT[E_*E_];
__device__ __half g_wkT[KVH_*HD_*E_];
__device__ __half g_wvT[KVH_*HD_*E_];
__device__ __half g_woT[E_*E_];

// flash operand layouts (bf16 3-term, unchanged): Q [B][H][S][HD], K/V [B][KVH][S][HD]
__device__ __nv_bfloat16 g_Qbh[M_*H_*HD_],   g_Qbl[M_*H_*HD_];
__device__ __nv_bfloat16 g_Kbh[M_*KVH_*HD_], g_Kbl[M_*KVH_*HD_];
__device__ __nv_bfloat16 g_Vbh[M_*KVH_*HD_], g_Vbl[M_*KVH_*HD_];

// ---------------------------------------------------------------------------
// PTX helpers (non-'a' ISA only: mma.sync / ldmatrix / cp.async)
// ---------------------------------------------------------------------------
__device__ __forceinline__ uint32_t smem_to_u32(const void* p) {
    uint32_t a;
    asm("{ .reg .u64 t; cvta.to.shared.u64 t, %1; cvt.u32.u64 %0, t; }" : "=r"(a) : "l"(p));
    return a;
}
__device__ __forceinline__ void cp_async16(uint32_t saddr, const void* gptr) {
    asm volatile("cp.async.cg.shared.global [%0], [%1], 16;\n" :: "r"(saddr), "l"(gptr));
}
#define CP_COMMIT() asm volatile("cp.async.commit_group;\n" ::: "memory")
#define CP_WAIT(n)  asm volatile("cp.async.wait_group %0;\n" :: "n"(n) : "memory")

__device__ __forceinline__ void ldmatrix_x4(uint32_t* r, uint32_t addr) {
    asm volatile("ldmatrix.sync.aligned.m8n8.x4.shared.b16 {%0,%1,%2,%3}, [%4];\n"
                 : "=r"(r[0]), "=r"(r[1]), "=r"(r[2]), "=r"(r[3]) : "r"(addr));
}
__device__ __forceinline__ void ldmatrix_x4_trans(uint32_t* r, uint32_t addr) {
    asm volatile("ldmatrix.sync.aligned.m8n8.x4.trans.shared.b16 {%0,%1,%2,%3}, [%4];\n"
                 : "=r"(r[0]), "=r"(r[1]), "=r"(r[2]), "=r"(r[3]) : "r"(addr));
}
__device__ __forceinline__ void ldmatrix_x2(uint32_t* r, uint32_t addr) {
    asm volatile("ldmatrix.sync.aligned.m8n8.x2.shared.b16 {%0,%1}, [%2];\n"
                 : "=r"(r[0]), "=r"(r[1]) : "r"(addr));
}
__device__ __forceinline__ void mma_bf16(float* c, const uint32_t* a, const uint32_t* b) {
    asm volatile(
        "mma.sync.aligned.m16n8k16.row.col.f32.bf16.bf16.f32 "
        "{%0,%1,%2,%3}, {%4,%5,%6,%7}, {%8,%9}, {%0,%1,%2,%3};\n"
        : "+f"(c[0]), "+f"(c[1]), "+f"(c[2]), "+f"(c[3])
        : "r"(a[0]), "r"(a[1]), "r"(a[2]), "r"(a[3]), "r"(b[0]), "r"(b[1]));
}
__device__ __forceinline__ void mma_f16(float* c, const uint32_t* a, const uint32_t* b) {
    asm volatile(
        "mma.sync.aligned.m16n8k16.row.col.f32.f16.f16.f32 "
        "{%0,%1,%2,%3}, {%4,%5,%6,%7}, {%8,%9}, {%0,%1,%2,%3};\n"
        : "+f"(c[0]), "+f"(c[1]), "+f"(c[2]), "+f"(c[3])
        : "r"(a[0]), "r"(a[1]), "r"(a[2]), "r"(a[3]), "r"(b[0]), "r"(b[1]));
}
// bf16 hi/lo (flash-internal P split)
__device__ __forceinline__ void split2(float a, float b, uint32_t& hi, uint32_t& lo) {
    __nv_bfloat162 h = __floats2bfloat162_rn(a, b);
    __nv_bfloat162 l = __floats2bfloat162_rn(a - __bfloat162float(h.x),
                                             b - __bfloat162float(h.y));
    hi = *(uint32_t*)&h;
    lo = *(uint32_t*)&l;
}
// fp16 hi/lo (projection A-operands)
__device__ __forceinline__ void split2h(float a, float b, uint32_t& hi, uint32_t& lo) {
    __half ha = __float2half_rn(a), hb = __float2half_rn(b);
    __half la = __float2half_rn(a - __half2float(ha));
    __half lb = __float2half_rn(b - __half2float(hb));
    __half2 h2 = __halves2half2(ha, hb);
    __half2 l2 = __halves2half2(la, lb);
    hi = *(uint32_t*)&h2;
    lo = *(uint32_t*)&l2;
}

// ---------------------------------------------------------------------------
// Conversion kernels
// ---------------------------------------------------------------------------
__global__ void convert_hilo_h_kernel(const float* __restrict__ in,
                                      __half* __restrict__ hi,
                                      __half* __restrict__ lo, int n4)
{
    int i = blockIdx.x * blockDim.x + threadIdx.x;
    if (i >= n4) return;
    float4 v = ((const float4*)in)[i];
    uint32_t h0, l0, h1, l1;
    split2h(v.x, v.y, h0, l0);
    split2h(v.z, v.w, h1, l1);
    uint32_t* ph = (uint32_t*)(hi + 4 * (size_t)i);
    uint32_t* pl = (uint32_t*)(lo + 4 * (size_t)i);
    ph[0] = h0; ph[1] = h1;
    pl[0] = l0; pl[1] = l1;
}

// W[K x N] fp32 -> WT[N x K] single fp16
__global__ void transpose_h_kernel(const float* __restrict__ W,
                                   __half* __restrict__ T,
                                   int K, int N)
{
    __shared__ float tile[32][33];
    int n0 = blockIdx.x * 32, k0 = blockIdx.y * 32;
    int tx = threadIdx.x, ty = threadIdx.y;
    #pragma unroll
    for (int r = 0; r < 4; r++)
        tile[ty + r * 8][tx] = W[(size_t)(k0 + ty + r * 8) * N + n0 + tx];
    __syncthreads();
    #pragma unroll
    for (int r = 0; r < 4; r++) {
        float v = tile[tx][ty + r * 8];
        T[(size_t)(n0 + ty + r * 8) * K + k0 + tx] = __float2half_rn(v);
    }
}

// merged K/V weight transpose (z selects tensor)
__global__ void transpose_h_kv_kernel(const float* __restrict__ Wk,
                                      const float* __restrict__ Wv,
                                      __half* __restrict__ Tk, __half* __restrict__ Tv)
{
    const int K = E_, N = KVH_ * HD_;
    const float* W = blockIdx.z ? Wv : Wk;
    __half* T = blockIdx.z ? Tv : Tk;
    __shared__ float tile[32][33];
    int n0 = blockIdx.x * 32, k0 = blockIdx.y * 32;
    int tx = threadIdx.x, ty = threadIdx.y;
    #pragma unroll
    for (int r = 0; r < 4; r++)
        tile[ty + r * 8][tx] = W[(size_t)(k0 + ty + r * 8) * N + n0 + tx];
    __syncthreads();
    #pragma unroll
    for (int r = 0; r < 4; r++) {
        float v = tile[tx][ty + r * 8];
        T[(size_t)(n0 + ty + r * 8) * K + k0 + tx] = __float2half_rn(v);
    }
}

// RoPE + bf16 hi/lo split; src = QKV buffer (row stride NQKV, col base h*HD)
__global__ void rope_split_kernel(const float* __restrict__ in,
                                  __nv_bfloat16* __restrict__ outh,
                                  __nv_bfloat16* __restrict__ outl,
                                  int nh, float scale)
{
    int idx = blockIdx.x * blockDim.x + threadIdx.x;
    int total = B_ * S_ * nh * (HD_ / 2);
    if (idx >= total) return;
    int d2 = idx & 63;
    int h  = (idx >> 6) % nh;
    int s  = (idx / (64 * nh)) % S_;
    int b  = idx / (64 * nh * S_);
    float p    = powf(100000.0f, (float)(2 * d2));   // inf for 2*d2 >= 8
    float freq = 1.0f / p;                           // 0 when p == inf
    float ang  = (float)s * freq;
    float sn, cs;
    sincosf(ang, &sn, &cs);
    size_t src = (size_t)(b * S_ + s) * NQKV + h * HD_ + 2 * d2;
    float tr = in[src], ti = in[src + 1];
    float o0 = (tr * cs - ti * sn) * scale;
    float o1 = (tr * sn + ti * cs) * scale;
    uint32_t hi, lo;
    split2(o0, o1, hi, lo);
    size_t dst = ((size_t)(b * nh + h) * S_ + s) * HD_ + 2 * d2;
    *(uint32_t*)(outh + dst) = hi;
    *(uint32_t*)(outl + dst) = lo;
}

// V: bf16 hi/lo split + relayout from QKV buffer
__global__ void v_split_kernel(const float* __restrict__ in,
                               __nv_bfloat16* __restrict__ outh,
                               __nv_bfloat16* __restrict__ outl)
{
    int idx = blockIdx.x * blockDim.x + threadIdx.x;
    int total = B_ * S_ * KVH_ * (HD_ / 2);
    if (idx >= total) return;
    int d2 = idx & 63;
    int g  = (idx >> 6) % KVH_;
    int s  = (idx / (64 * KVH_)) % S_;
    int b  = idx / (64 * KVH_ * S_);
    size_t src = (size_t)(b * S_ + s) * NQKV + g * HD_ + 2 * d2;
    float2 v = *(const float2*)(in + src);
    uint32_t hi, lo;
    split2(v.x, v.y, hi, lo);
    size_t dst = ((size_t)(b * KVH_ + g) * S_ + s) * HD_ + 2 * d2;
    *(uint32_t*)(outh + dst) = hi;
    *(uint32_t*)(outl + dst) = lo;
}

// ---------------------------------------------------------------------------
// fp16 2-MMA GEMM mainloop: C = (Ah+Al) @ B^T  (A split fp16, B single fp16)
// 256x128 tile, K chunks of 32, 3 stages, single sync per chunk.
// ---------------------------------------------------------------------------
#define GBK      32
#define GROWB    80                    // 64B data + 16 pad
#define GARR_A   (256 * GROWB)         // 20480
#define GARR_B   (128 * GROWB)         // 10240
#define GSTAGE   (2 * GARR_A + GARR_B) // 51200
#define GSTAGES  3
#define GSMEM    (GSTAGES * GSTAGE)    // 153600

__device__ __forceinline__ void gemm_mainloop(
    const __half* __restrict__ Ahi, const __half* __restrict__ Alo,
    const __half* __restrict__ Bw,
    int rowA0, int rowB0, int K, uint32_t sb, int tid, float acc[4][8][4])
{
    const int wid  = tid >> 5;
    const int lane = tid & 31;
    const int warp_m = wid >> 1;        // 0..3 -> 64 rows each
    const int warp_n = wid & 1;         // 0..1 -> 64 cols each
    const int nchunks = K / GBK;

    const int a_lr = lane & 15;
    const int a_kc = (lane >> 4) * 8;
    const int b_lr = lane & 7;
    const int b_kc = ((lane >> 3) & 3) * 8;

    auto load_stage = [&](int chunk, int stage) {
        const int k0 = chunk * GBK;
        uint32_t s = sb + stage * GSTAGE;
        #pragma unroll
        for (int t = 0; t < 4; t++) {
            int u = t * 256 + tid;
            int r = u >> 2, c = u & 3;
            cp_async16(s + r * GROWB + c * 16,
                       Ahi + (size_t)(rowA0 + r) * K + k0 + c * 8);
            cp_async16(s + GARR_A + r * GROWB + c * 16,
                       Alo + (size_t)(rowA0 + r) * K + k0 + c * 8);
        }
        #pragma unroll
        for (int t = 0; t < 2; t++) {
            int u = t * 256 + tid;
            int r = u >> 2, c = u & 3;
            cp_async16(s + 2 * GARR_A + r * GROWB + c * 16,
                       Bw + (size_t)(rowB0 + r) * K + k0 + c * 8);
        }
    };

    #pragma unroll
    for (int s = 0; s < GSTAGES - 1; s++) { load_stage(s, s); CP_COMMIT(); }

    for (int i = 0; i < nchunks; i++) {
        CP_WAIT(GSTAGES - 2);
        __syncthreads();

        if (i + GSTAGES - 1 < nchunks)
            load_stage(i + GSTAGES - 1, (i + GSTAGES - 1) % GSTAGES);
        CP_COMMIT();

        const int stage = i % GSTAGES;
        const uint32_t sAhi = sb + stage * GSTAGE;
        const uint32_t sAlo = sAhi + GARR_A;
        const uint32_t sBw  = sAlo + GARR_A;

        #pragma unroll
        for (int ks = 0; ks < 2; ks++) {
            const int kb = ks * 32;
            uint32_t ah[4][4], al[4][4];
            #pragma unroll
            for (int mt = 0; mt < 4; mt++) {
                uint32_t aoff = (uint32_t)(warp_m * 64 + mt * 16 + a_lr) * GROWB + a_kc * 2 + kb;
                ldmatrix_x4(ah[mt], sAhi + aoff);
                ldmatrix_x4(al[mt], sAlo + aoff);
            }
            uint32_t bw[2][2];
            {
                uint32_t boff = (uint32_t)(warp_n * 64 + b_lr) * GROWB + b_kc * 2 + kb;
                ldmatrix_x2(bw[0], sBw + boff);
            }
            #pragma unroll
            for (int nt = 0; nt < 8; nt++) {
                const int cur = nt & 1;
                if (nt < 7) {
                    uint32_t boff = (uint32_t)(warp_n * 64 + (nt + 1) * 8 + b_lr) * GROWB + b_kc * 2 + kb;
                    ldmatrix_x2(bw[cur ^ 1], sBw + boff);
                }
                #pragma unroll
                for (int mt = 0; mt < 4; mt++) {
                    mma_f16(acc[mt][nt], ah[mt], bw[cur]);
                    mma_f16(acc[mt][nt], al[mt], bw[cur]);
                }
            }
        }
    }
}

// Generic GEMM (O projection): C[M,N] row stride N, M-tile = 256
__global__ void __launch_bounds__(256, 1)
gemm_f16x2_kernel(const __half* __restrict__ Ahi,
                  const __half* __restrict__ Alo,
                  const __half* __restrict__ Bw,
                  const float* __restrict__ bias,
                  float* __restrict__ C,
                  int M, int N, int K)
{
    extern __shared__ char smem[];
    const uint32_t sb = smem_to_u32(smem);
    const int tid  = threadIdx.x;
    const int wid  = tid >> 5;
    const int lane = tid & 31;
    const int rowA0 = blockIdx.y * 256;
    const int rowB0 = blockIdx.x * 128;

    float acc[4][8][4];
    #pragma unroll
    for (int i = 0; i < 4; i++)
        #pragma unroll
        for (int j = 0; j < 8; j++)
            #pragma unroll
            for (int k = 0; k < 4; k++) acc[i][j][k] = 0.0f;

    gemm_mainloop(Ahi, Alo, Bw, rowA0, rowB0, K, sb, tid, acc);

    const int warp_m = wid >> 1, warp_n = wid & 1;
    #pragma unroll
    for (int mt = 0; mt < 4; mt++)
        #pragma unroll
        for (int nt = 0; nt < 8; nt++) {
            int row = rowA0 + warp_m * 64 + mt * 16 + (lane >> 2);
            int col = rowB0 + warp_n * 64 + nt * 8 + (lane & 3) * 2;
            float2 b01 = *(const float2*)&bias[col];
            float2 o0 = {acc[mt][nt][0] + b01.x, acc[mt][nt][1] + b01.y};
            float2 o1 = {acc[mt][nt][2] + b01.x, acc[mt][nt][3] + b01.y};
            *(float2*)&C[(size_t)row * N + col]       = o0;
            *(float2*)&C[(size_t)(row + 8) * N + col] = o1;
        }
}

// Fused QKV projection: writes into QKV buffer [M][3072], M-tile = 256
__global__ void __launch_bounds__(256, 1)
gemm_qkv_kernel(const __half* __restrict__ xhi,
                const __half* __restrict__ xlo,
                const __half* __restrict__ wqT,
                const __half* __restrict__ wkT,
                const __half* __restrict__ wvT,
                const float* __restrict__ bq, const float* __restrict__ bk,
                const float* __restrict__ bv,
                float* __restrict__ C)
{
    extern __shared__ char smem[];
    const uint32_t sb = smem_to_u32(smem);
    const int tid  = threadIdx.x;
    const int wid  = tid >> 5;
    const int lane = tid & 31;
    const int cCol = blockIdx.x;         // 0..23
    const int rowA0 = blockIdx.y * 256;

    const __half* Bw;
    const float* bias;
    int rowB0;
    if (cCol < 16)      { Bw = wqT; bias = bq; rowB0 = cCol * 128; }
    else if (cCol < 20) { Bw = wkT; bias = bk; rowB0 = (cCol - 16) * 128; }
    else                { Bw = wvT; bias = bv; rowB0 = (cCol - 20) * 128; }

    float acc[4][8][4];
    #pragma unroll
    for (int i = 0; i < 4; i++)
        #pragma unroll
        for (int j = 0; j < 8; j++)
            #pragma unroll
            for (int k = 0; k < 4; k++) acc[i][j][k] = 0.0f;

    gemm_mainloop(xhi, xlo, Bw, rowA0, rowB0, E_, sb, tid, acc);

    const int warp_m = wid >> 1, warp_n = wid & 1;
    #pragma unroll
    for (int mt = 0; mt < 4; mt++)
        #pragma unroll
        for (int nt = 0; nt < 8; nt++) {
            int row  = rowA0 + warp_m * 64 + mt * 16 + (lane >> 2);
            int bcol = rowB0 + warp_n * 64 + nt * 8 + (lane & 3) * 2;
            int col  = cCol * 128 + warp_n * 64 + nt * 8 + (lane & 3) * 2;
            float2 b01 = *(const float2*)&bias[bcol];
            float2 o0 = {acc[mt][nt][0] + b01.x, acc[mt][nt][1] + b01.y};
            float2 o1 = {acc[mt][nt][2] + b01.x, acc[mt][nt][3] + b01.y};
            *(float2*)&C[(size_t)row * NQKV + col]       = o0;
            *(float2*)&C[(size_t)(row + 8) * NQKV + col] = o1;
        }
}

// ---------------------------------------------------------------------------
// Flash attention, split-bf16 HMMA (unchanged math). Br=128, Bc=64, 8 warps.
// Epilogue now emits fp16 hi/lo for the O projection.
// ---------------------------------------------------------------------------
#define FROWB  272
#define QARR   (128 * FROWB)        // 34816
#define KARR   (64 * FROWB)         // 17408
#define FSTG   (4 * KARR)           // 69632 (Kh,Kl,Vh,Vl)
#define FSMEM  (2 * QARR + 2 * FSTG)  // 208896

__global__ void __launch_bounds__(256, 1)
flash_mma_kernel(const __nv_bfloat16* __restrict__ Qh, const __nv_bfloat16* __restrict__ Ql,
                 const __nv_bfloat16* __restrict__ Kh, const __nv_bfloat16* __restrict__ Kl,
                 const __nv_bfloat16* __restrict__ Vh, const __nv_bfloat16* __restrict__ Vl,
                 __half* __restrict__ Ohi, __half* __restrict__ Olo)
{
    extern __shared__ char smem[];
    const uint32_t sb = smem_to_u32(smem);
    const int tid  = threadIdx.x;
    const int lane = tid & 31;
    const int warp = tid >> 5;
    const int qt = (int)gridDim.x - 1 - (int)blockIdx.x;   // heavy tiles first
    const int h = blockIdx.y, b = blockIdx.z;
    const int g  = h >> 2;
    const int q0 = qt * 128;
    const int nkv = 2 * qt + 2;

    const uint32_t sQh = sb, sQl = sb + QARR;
    const uint32_t sKV0 = sb + 2 * QARR;

    const size_t qbase  = ((size_t)(b * H_ + h) * S_ + q0) * HD_;
    const size_t kvbase = ((size_t)(b * KVH_ + g) * S_) * HD_;

    const uint32_t q_off = (uint32_t)(lane & 15) * FROWB + (lane >> 4) * 16;
    const uint32_t k_off = (uint32_t)((lane & 7) | ((lane >> 1) & 8)) * FROWB + ((lane >> 3) & 1) * 16;

    // -- prologue: Q tile (128 rows) + KV stage 0 --
    #pragma unroll
    for (int t = 0; t < 8; t++) {
        int u = t * 256 + tid;                  // 0..2047
        int r = u >> 4, cb = (u & 15) * 16, ce = (u & 15) * 8;
        cp_async16(sQh + r * FROWB + cb, Qh + qbase + (size_t)r * HD_ + ce);
        cp_async16(sQl + r * FROWB + cb, Ql + qbase + (size_t)r * HD_ + ce);
    }
    auto load_kv = [&](int kt, int buf) {
        uint32_t s = sKV0 + buf * FSTG;
        const size_t base = kvbase + (size_t)kt * 64 * HD_;
        #pragma unroll
        for (int t = 0; t < 4; t++) {
            int u = t * 256 + tid;              // 0..1023
            int r = u >> 4, cb = (u & 15) * 16, ce = (u & 15) * 8;
            size_t go = base + (size_t)r * HD_ + ce;
            uint32_t so = r * FROWB + cb;
            cp_async16(s + so,            Kh + go);
            cp_async16(s + KARR + so,     Kl + go);
            cp_async16(s + 2 * KARR + so, Vh + go);
            cp_async16(s + 3 * KARR + so, Vl + go);
        }
    };
    load_kv(0, 0);
    CP_COMMIT();

    float oacc[16][4];
    #pragma unroll
    for (int i = 0; i < 16; i++)
        #pragma unroll
        for (int j = 0; j < 4; j++) oacc[i][j] = 0.0f;
    float m0 = -INFINITY, m1 = -INFINITY, l0 = 0.0f, l1 = 0.0f;

    for (int kt = 0; kt < nkv; kt++) {
        __syncthreads();
        if (kt + 1 < nkv) { load_kv(kt + 1, (kt + 1) & 1); CP_COMMIT(); CP_WAIT(1); }
        else              { CP_WAIT(0); }
        __syncthreads();

        const uint32_t st  = sKV0 + (kt & 1) * FSTG;
        const uint32_t sKh = st, sKl = st + KARR, sVh = st + 2 * KARR, sVl = st + 3 * KARR;

        // ---- S = Q K^T ----
        float sacc[8][4];
        #pragma unroll
        for (int i = 0; i < 8; i++)
            #pragma unroll
            for (int j = 0; j < 4; j++) sacc[i][j] = 0.0f;

        #pragma unroll
        for (int kk = 0; kk < 8; kk++) {
            const uint32_t kb = kk * 32;
            uint32_t qh[4], ql[4];
            ldmatrix_x4(qh, sQh + (uint32_t)warp * 16 * FROWB + q_off + kb);
            ldmatrix_x4(ql, sQl + (uint32_t)warp * 16 * FROWB + q_off + kb);
            #pragma unroll
            for (int np = 0; np < 4; np++) {
                uint32_t kh[4], kl[4];
                ldmatrix_x4(kh, sKh + (uint32_t)np * 16 * FROWB + k_off + kb);
                ldmatrix_x4(kl, sKl + (uint32_t)np * 16 * FROWB + k_off + kb);
                mma_bf16(sacc[2*np],   qh, &kh[0]);
                mma_bf16(sacc[2*np],   qh, &kl[0]);
                mma_bf16(sacc[2*np],   ql, &kh[0]);
                mma_bf16(sacc[2*np+1], qh, &kh[2]);
                mma_bf16(sacc[2*np+1], qh, &kl[2]);
                mma_bf16(sacc[2*np+1], ql, &kh[2]);
            }
        }

        // ---- causal mask (diagonal region spans kv chunks 2qt, 2qt+1) ----
        if (kt >= 2 * qt) {
            const int rg0 = q0 + warp * 16 + (lane >> 2);
            const int cg0 = kt * 64 + (lane & 3) * 2;
            #pragma unroll
            for (int nt = 0; nt < 8; nt++)
                #pragma unroll
                for (int j = 0; j < 4; j++) {
                    int col = cg0 + nt * 8 + (j & 1);
                    int row = rg0 + (j >> 1) * 8;
                    if (col > row) sacc[nt][j] = -INFINITY;
                }
        }

        // ---- online softmax ----
        float mx0 = -INFINITY, mx1 = -INFINITY;
        #pragma unroll
        for (int nt = 0; nt < 8; nt++) {
            mx0 = fmaxf(mx0, fmaxf(sacc[nt][0], sacc[nt][1]));
            mx1 = fmaxf(mx1, fmaxf(sacc[nt][2], sacc[nt][3]));
        }
        mx0 = fmaxf(mx0, __shfl_xor_sync(0xFFFFFFFF, mx0, 1));
        mx0 = fmaxf(mx0, __shfl_xor_sync(0xFFFFFFFF, mx0, 2));
        mx1 = fmaxf(mx1, __shfl_xor_sync(0xFFFFFFFF, mx1, 1));
        mx1 = fmaxf(mx1, __shfl_xor_sync(0xFFFFFFFF, mx1, 2));
        float mn0 = fmaxf(m0, mx0), mn1 = fmaxf(m1, mx1);
        float al0 = __expf(m0 - mn0), al1 = __expf(m1 - mn1);
        m0 = mn0; m1 = mn1;

        float ps0 = 0.0f, ps1 = 0.0f;
        #pragma unroll
        for (int nt = 0; nt < 8; nt++) {
            float p0 = __expf(sacc[nt][0] - mn0);
            float p1 = __expf(sacc[nt][1] - mn0);
            float p2 = __expf(sacc[nt][2] - mn1);
            float p3 = __expf(sacc[nt][3] - mn1);
            sacc[nt][0] = p0; sacc[nt][1] = p1; sacc[nt][2] = p2; sacc[nt][3] = p3;
            ps0 += p0 + p1; ps1 += p2 + p3;
        }
        ps0 += __shfl_xor_sync(0xFFFFFFFF, ps0, 1);
        ps0 += __shfl_xor_sync(0xFFFFFFFF, ps0, 2);
        ps1 += __shfl_xor_sync(0xFFFFFFFF, ps1, 1);
        ps1 += __shfl_xor_sync(0xFFFFFFFF, ps1, 2);
        l0 = l0 * al0 + ps0;
        l1 = l1 * al1 + ps1;

        #pragma unroll
        for (int i = 0; i < 16; i++) {
            oacc[i][0] *= al0; oacc[i][1] *= al0;
            oacc[i][2] *= al1; oacc[i][3] *= al1;
        }

        // ---- O += P V ----
        #pragma unroll
        for (int tk = 0; tk < 4; tk++) {
            uint32_t ah[4], al_[4];
            split2(sacc[2*tk][0],   sacc[2*tk][1],   ah[0], al_[0]);
            split2(sacc[2*tk][2],   sacc[2*tk][3],   ah[1], al_[1]);
            split2(sacc[2*tk+1][0], sacc[2*tk+1][1], ah[2], al_[2]);
            split2(sacc[2*tk+1][2], sacc[2*tk+1][3], ah[3], al_[3]);
            #pragma unroll
            for (int dp = 0; dp < 8; dp++) {
                uint32_t vh[4], vl[4];
                const uint32_t vo = (uint32_t)tk * 16 * FROWB + q_off + dp * 32;
                ldmatrix_x4_trans(vh, sVh + vo);
                ldmatrix_x4_trans(vl, sVl + vo);
                mma_bf16(oacc[2*dp],   ah,  &vh[0]);
                mma_bf16(oacc[2*dp],   ah,  &vl[0]);
                mma_bf16(oacc[2*dp],   al_, &vh[0]);
                mma_bf16(oacc[2*dp+1], ah,  &vh[2]);
                mma_bf16(oacc[2*dp+1], ah,  &vl[2]);
                mma_bf16(oacc[2*dp+1], al_, &vh[2]);
            }
        }
    }

    // ---- epilogue: O / l -> fp16 hi/lo at [b][s][h*HD] ----
    const float il0 = 1.0f / l0, il1 = 1.0f / l1;
    const int r0 = q0 + warp * 16 + (lane >> 2);
    const int c0 = h * HD_ + (lane & 3) * 2;
    #pragma unroll
    for (int nt = 0; nt < 16; nt++) {
        float o0 = oacc[nt][0] * il0, o1 = oacc[nt][1] * il0;
        float o2 = oacc[nt][2] * il1, o3 = oacc[nt][3] * il1;
        uint32_t h0, l0r, h1, l1r;
        split2h(o0, o1, h0, l0r);
        split2h(o2, o3, h1, l1r);
        size_t i0 = (size_t)(b * S_ + r0)     * E_ + c0 + nt * 8;
        size_t i1 = (size_t)(b * S_ + r0 + 8) * E_ + c0 + nt * 8;
        *(uint32_t*)(Ohi + i0) = h0; *(uint32_t*)(Olo + i0) = l0r;
        *(uint32_t*)(Ohi + i1) = h1; *(uint32_t*)(Olo + i1) = l1r;
    }
}

// ---------------------------------------------------------------------------
extern "C" void kernel_launch(void* const* d_in, const int* in_sizes, int n_in,
                              void* d_out, int out_size)
{
    const float* x  = (const float*)d_in[0];
    const float* wq = (const float*)d_in[1];
    const float* bq = (const float*)d_in[2];
    const float* wk = (const float*)d_in[3];
    const float* bk = (const float*)d_in[4];
    const float* wv = (const float*)d_in[5];
    const float* bv = (const float*)d_in[6];
    const float* wo = (const float*)d_in[7];
    const float* bo = (const float*)d_in[8];
    float* out = (float*)d_out;

    float* QKVp;
    cudaGetSymbolAddress((void**)&QKVp, g_QKV);
    __half *xhi, *xlo, *aohi, *aolo, *wqT, *wkT, *wvT, *woT;
    __nv_bfloat16 *qbh, *qbl, *kbh, *kbl, *vbh, *vbl;
    cudaGetSymbolAddress((void**)&xhi,  g_xhi);
    cudaGetSymbolAddress((void**)&xlo,  g_xlo);
    cudaGetSymbolAddress((void**)&aohi, g_aohi);
    cudaGetSymbolAddress((void**)&aolo, g_aolo);
    cudaGetSymbolAddress((void**)&wqT, g_wqT);
    cudaGetSymbolAddress((void**)&wkT, g_wkT);
    cudaGetSymbolAddress((void**)&wvT, g_wvT);
    cudaGetSymbolAddress((void**)&woT, g_woT);
    cudaGetSymbolAddress((void**)&qbh, g_Qbh);
    cudaGetSymbolAddress((void**)&qbl, g_Qbl);
    cudaGetSymbolAddress((void**)&kbh, g_Kbh);
    cudaGetSymbolAddress((void**)&kbl, g_Kbl);
    cudaGetSymbolAddress((void**)&vbh, g_Vbh);
    cudaGetSymbolAddress((void**)&vbl, g_Vbl);

    cudaFuncSetAttribute(gemm_qkv_kernel,
                         cudaFuncAttributeMaxDynamicSharedMemorySize, GSMEM);
    cudaFuncSetAttribute(gemm_f16x2_kernel,
                         cudaFuncAttributeMaxDynamicSharedMemorySize, GSMEM);
    cudaFuncSetAttribute(flash_mma_kernel,
                         cudaFuncAttributeMaxDynamicSharedMemorySize, FSMEM);

    // conversions
    {
        int n4 = M_ * E_ / 4;
        convert_hilo_h_kernel<<<(n4 + 255) / 256, 256>>>(x, xhi, xlo, n4);
        dim3 blk(32, 8);
        transpose_h_kernel<<<dim3(E_ / 32, E_ / 32), blk>>>(wq, wqT, E_, E_);
        transpose_h_kv_kernel<<<dim3((KVH_ * HD_) / 32, E_ / 32, 2), blk>>>(
            wk, wv, wkT, wvT);
    }

    // Fused QKV projection (N = 3072, M-tile 256)
    gemm_qkv_kernel<<<dim3(NQKV / 128, M_ / 256), 256, GSMEM>>>(
        xhi, xlo, wqT, wkT, wvT, bq, bk, bv, QKVp);

    // RoPE + split + relayout (reads QKV buffer)
    {
        int totq = B_ * S_ * H_ * (HD_ / 2);
        int totk = B_ * S_ * KVH_ * (HD_ / 2);
        float qscale = 1.0f / sqrtf((float)HD_);
        rope_split_kernel<<<(totq + 255) / 256, 256>>>(QKVp, qbh, qbl, H_, qscale);
        rope_split_kernel<<<(totk + 255) / 256, 256>>>(QKVp + 2048, kbh, kbl, KVH_, 1.0f);
        v_split_kernel<<<(totk + 255) / 256, 256>>>(QKVp + 2560, vbh, vbl);
    }

    // Flash attention (HMMA split-bf16, Br=128) -> fp16 hi/lo output
    flash_mma_kernel<<<dim3(S_ / 128, H_, B_), 256, FSMEM>>>(
        qbh, qbl, kbh, kbl, vbh, vbl, aohi, aolo);

    // wo transpose (deferred; only needed by O-proj)
    {
        dim3 blk(32, 8);
        transpose_h_kernel<<<dim3(E_ / 32, E_ / 32), blk>>>(wo, woT, E_, E_);
    }

    // Output projection -> d_out (M-tile 256)
    gemm_f16x2_kernel<<<dim3(E_ / 128, M_ / 256), 256, GSMEM>>>(
        aohi, aolo, woT, bo, out, M_, E_, E_);
}

// round 14
// speedup vs baseline: 1.2947x; 1.0714x over previous
#include <cuda_runtime.h>
#include <cuda_bf16.h>
#include <cuda_fp16.h>
#include <math.h>
#include <cstdint>

#define B_   2
#define S_   2048
#define E_   2048
#define H_   16
#define KVH_ 4
#define HD_  128
#define REP_ 4
#define M_   (B_*S_)     // 4096
#define NQKV 3072        // 2048 Q + 512 K + 512 V

// ---------------------------------------------------------------------------
// Scratch (__device__ globals; no allocations allowed)
// ---------------------------------------------------------------------------
__device__ float g_QKV[M_*NQKV];

// fp16 operands for projection GEMMs: A split hi/lo, weights single fp16
__device__ __half g_xhi[M_*E_],  g_xlo[M_*E_];
__device__ __half g_aohi[M_*E_], g_aolo[M_*E_];
__device__ __half g_wqT[E_*E_];
__device__ __half g_wkT[KVH_*HD_*E_];
__device__ __half g_wvT[KVH_*HD_*E_];
__device__ __half g_woT[E_*E_];

// flash operand layouts (bf16 3-term): Q [B][H][S][HD], K/V [B][KVH][S][HD]
__device__ __nv_bfloat16 g_Qbh[M_*H_*HD_],   g_Qbl[M_*H_*HD_];
__device__ __nv_bfloat16 g_Kbh[M_*KVH_*HD_], g_Kbl[M_*KVH_*HD_];
__device__ __nv_bfloat16 g_Vbh[M_*KVH_*HD_], g_Vbl[M_*KVH_*HD_];

// ---------------------------------------------------------------------------
// PTX helpers (non-'a' ISA only: mma.sync / ldmatrix / cp.async)
// ---------------------------------------------------------------------------
__device__ __forceinline__ uint32_t smem_to_u32(const void* p) {
    uint32_t a;
    asm("{ .reg .u64 t; cvta.to.shared.u64 t, %1; cvt.u32.u64 %0, t; }" : "=r"(a) : "l"(p));
    return a;
}
__device__ __forceinline__ void cp_async16(uint32_t saddr, const void* gptr) {
    asm volatile("cp.async.cg.shared.global [%0], [%1], 16;\n" :: "r"(saddr), "l"(gptr));
}
#define CP_COMMIT() asm volatile("cp.async.commit_group;\n" ::: "memory")
#define CP_WAIT(n)  asm volatile("cp.async.wait_group %0;\n" :: "n"(n) : "memory")

__device__ __forceinline__ void ldmatrix_x4(uint32_t* r, uint32_t addr) {
    asm volatile("ldmatrix.sync.aligned.m8n8.x4.shared.b16 {%0,%1,%2,%3}, [%4];\n"
                 : "=r"(r[0]), "=r"(r[1]), "=r"(r[2]), "=r"(r[3]) : "r"(addr));
}
__device__ __forceinline__ void ldmatrix_x4_trans(uint32_t* r, uint32_t addr) {
    asm volatile("ldmatrix.sync.aligned.m8n8.x4.trans.shared.b16 {%0,%1,%2,%3}, [%4];\n"
                 : "=r"(r[0]), "=r"(r[1]), "=r"(r[2]), "=r"(r[3]) : "r"(addr));
}
__device__ __forceinline__ void ldmatrix_x2(uint32_t* r, uint32_t addr) {
    asm volatile("ldmatrix.sync.aligned.m8n8.x2.shared.b16 {%0,%1}, [%2];\n"
                 : "=r"(r[0]), "=r"(r[1]) : "r"(addr));
}
__device__ __forceinline__ void mma_bf16(float* c, const uint32_t* a, const uint32_t* b) {
    asm volatile(
        "mma.sync.aligned.m16n8k16.row.col.f32.bf16.bf16.f32 "
        "{%0,%1,%2,%3}, {%4,%5,%6,%7}, {%8,%9}, {%0,%1,%2,%3};\n"
        : "+f"(c[0]), "+f"(c[1]), "+f"(c[2]), "+f"(c[3])
        : "r"(a[0]), "r"(a[1]), "r"(a[2]), "r"(a[3]), "r"(b[0]), "r"(b[1]));
}
__device__ __forceinline__ void mma_f16(float* c, const uint32_t* a, const uint32_t* b) {
    asm volatile(
        "mma.sync.aligned.m16n8k16.row.col.f32.f16.f16.f32 "
        "{%0,%1,%2,%3}, {%4,%5,%6,%7}, {%8,%9}, {%0,%1,%2,%3};\n"
        : "+f"(c[0]), "+f"(c[1]), "+f"(c[2]), "+f"(c[3])
        : "r"(a[0]), "r"(a[1]), "r"(a[2]), "r"(a[3]), "r"(b[0]), "r"(b[1]));
}
// bf16 hi/lo (flash-internal P split)
__device__ __forceinline__ void split2(float a, float b, uint32_t& hi, uint32_t& lo) {
    __nv_bfloat162 h = __floats2bfloat162_rn(a, b);
    __nv_bfloat162 l = __floats2bfloat162_rn(a - __bfloat162float(h.x),
                                             b - __bfloat162float(h.y));
    hi = *(uint32_t*)&h;
    lo = *(uint32_t*)&l;
}
// fp16 hi/lo (projection A-operands)
__device__ __forceinline__ void split2h(float a, float b, uint32_t& hi, uint32_t& lo) {
    __half ha = __float2half_rn(a), hb = __float2half_rn(b);
    __half la = __float2half_rn(a - __half2float(ha));
    __half lb = __float2half_rn(b - __half2float(hb));
    __half2 h2 = __halves2half2(ha, hb);
    __half2 l2 = __halves2half2(la, lb);
    hi = *(uint32_t*)&h2;
    lo = *(uint32_t*)&l2;
}

// ---------------------------------------------------------------------------
// Conversion kernels
// ---------------------------------------------------------------------------
__global__ void convert_hilo_h_kernel(const float* __restrict__ in,
                                      __half* __restrict__ hi,
                                      __half* __restrict__ lo, int n4)
{
    int i = blockIdx.x * blockDim.x + threadIdx.x;
    if (i >= n4) return;
    float4 v = ((const float4*)in)[i];
    uint32_t h0, l0, h1, l1;
    split2h(v.x, v.y, h0, l0);
    split2h(v.z, v.w, h1, l1);
    uint32_t* ph = (uint32_t*)(hi + 4 * (size_t)i);
    uint32_t* pl = (uint32_t*)(lo + 4 * (size_t)i);
    ph[0] = h0; ph[1] = h1;
    pl[0] = l0; pl[1] = l1;
}

// W[K x N] fp32 -> WT[N x K] single fp16
__global__ void transpose_h_kernel(const float* __restrict__ W,
                                   __half* __restrict__ T,
                                   int K, int N)
{
    __shared__ float tile[32][33];
    int n0 = blockIdx.x * 32, k0 = blockIdx.y * 32;
    int tx = threadIdx.x, ty = threadIdx.y;
    #pragma unroll
    for (int r = 0; r < 4; r++)
        tile[ty + r * 8][tx] = W[(size_t)(k0 + ty + r * 8) * N + n0 + tx];
    __syncthreads();
    #pragma unroll
    for (int r = 0; r < 4; r++) {
        float v = tile[tx][ty + r * 8];
        T[(size_t)(n0 + ty + r * 8) * K + k0 + tx] = __float2half_rn(v);
    }
}

// merged K/V weight transpose (z selects tensor)
__global__ void transpose_h_kv_kernel(const float* __restrict__ Wk,
                                      const float* __restrict__ Wv,
                                      __half* __restrict__ Tk, __half* __restrict__ Tv)
{
    const int K = E_, N = KVH_ * HD_;
    const float* W = blockIdx.z ? Wv : Wk;
    __half* T = blockIdx.z ? Tv : Tk;
    __shared__ float tile[32][33];
    int n0 = blockIdx.x * 32, k0 = blockIdx.y * 32;
    int tx = threadIdx.x, ty = threadIdx.y;
    #pragma unroll
    for (int r = 0; r < 4; r++)
        tile[ty + r * 8][tx] = W[(size_t)(k0 + ty + r * 8) * N + n0 + tx];
    __syncthreads();
    #pragma unroll
    for (int r = 0; r < 4; r++) {
        float v = tile[tx][ty + r * 8];
        T[(size_t)(n0 + ty + r * 8) * K + k0 + tx] = __float2half_rn(v);
    }
}

// RoPE + bf16 hi/lo split; src = QKV buffer (row stride NQKV, col base h*HD)
__global__ void rope_split_kernel(const float* __restrict__ in,
                                  __nv_bfloat16* __restrict__ outh,
                                  __nv_bfloat16* __restrict__ outl,
                                  int nh, float scale)
{
    int idx = blockIdx.x * blockDim.x + threadIdx.x;
    int total = B_ * S_ * nh * (HD_ / 2);
    if (idx >= total) return;
    int d2 = idx & 63;
    int h  = (idx >> 6) % nh;
    int s  = (idx / (64 * nh)) % S_;
    int b  = idx / (64 * nh * S_);
    float p    = powf(100000.0f, (float)(2 * d2));   // inf for 2*d2 >= 8
    float freq = 1.0f / p;                           // 0 when p == inf
    float ang  = (float)s * freq;
    float sn, cs;
    sincosf(ang, &sn, &cs);
    size_t src = (size_t)(b * S_ + s) * NQKV + h * HD_ + 2 * d2;
    float tr = in[src], ti = in[src + 1];
    float o0 = (tr * cs - ti * sn) * scale;
    float o1 = (tr * sn + ti * cs) * scale;
    uint32_t hi, lo;
    split2(o0, o1, hi, lo);
    size_t dst = ((size_t)(b * nh + h) * S_ + s) * HD_ + 2 * d2;
    *(uint32_t*)(outh + dst) = hi;
    *(uint32_t*)(outl + dst) = lo;
}

// V: bf16 hi/lo split + relayout from QKV buffer
__global__ void v_split_kernel(const float* __restrict__ in,
                               __nv_bfloat16* __restrict__ outh,
                               __nv_bfloat16* __restrict__ outl)
{
    int idx = blockIdx.x * blockDim.x + threadIdx.x;
    int total = B_ * S_ * KVH_ * (HD_ / 2);
    if (idx >= total) return;
    int d2 = idx & 63;
    int g  = (idx >> 6) % KVH_;
    int s  = (idx / (64 * KVH_)) % S_;
    int b  = idx / (64 * KVH_ * S_);
    size_t src = (size_t)(b * S_ + s) * NQKV + g * HD_ + 2 * d2;
    float2 v = *(const float2*)(in + src);
    uint32_t hi, lo;
    split2(v.x, v.y, hi, lo);
    size_t dst = ((size_t)(b * KVH_ + g) * S_ + s) * HD_ + 2 * d2;
    *(uint32_t*)(outh + dst) = hi;
    *(uint32_t*)(outl + dst) = lo;
}

// ---------------------------------------------------------------------------
// fp16 2-MMA GEMM mainloop: C = (Ah+Al) @ B^T
// 256x128 tile, K chunks of 64 (256 MMAs between syncs), 2 stages,
// single sync per chunk.
// ---------------------------------------------------------------------------
#define GBK      64
#define GROWB    144                   // 128B data + 16 pad
#define GARR_A   (256 * GROWB)         // 36864
#define GARR_B   (128 * GROWB)         // 18432
#define GSTAGE   (2 * GARR_A + GARR_B) // 92160
#define GSTAGES  2
#define GSMEM    (GSTAGES * GSTAGE)    // 184320

__device__ __forceinline__ void gemm_mainloop(
    const __half* __restrict__ Ahi, const __half* __restrict__ Alo,
    const __half* __restrict__ Bw,
    int rowA0, int rowB0, int K, uint32_t sb, int tid, float acc[4][8][4])
{
    const int wid  = tid >> 5;
    const int lane = tid & 31;
    const int warp_m = wid >> 1;        // 0..3 -> 64 rows each
    const int warp_n = wid & 1;         // 0..1 -> 64 cols each
    const int nchunks = K / GBK;

    const int a_lr = lane & 15;
    const int a_kc = (lane >> 4) * 8;
    const int b_lr = lane & 7;
    const int b_kc = ((lane >> 3) & 3) * 8;

    auto load_stage = [&](int chunk, int stage) {
        const int k0 = chunk * GBK;
        uint32_t s = sb + stage * GSTAGE;
        // A arrays: 256 rows x 8 16B-chunks = 2048 per array -> 8/thread
        #pragma unroll
        for (int t = 0; t < 8; t++) {
            int u = t * 256 + tid;
            int r = u >> 3, c = u & 7;
            cp_async16(s + r * GROWB + c * 16,
                       Ahi + (size_t)(rowA0 + r) * K + k0 + c * 8);
            cp_async16(s + GARR_A + r * GROWB + c * 16,
                       Alo + (size_t)(rowA0 + r) * K + k0 + c * 8);
        }
        // B array: 128 rows x 8 = 1024 -> 4/thread
        #pragma unroll
        for (int t = 0; t < 4; t++) {
            int u = t * 256 + tid;
            int r = u >> 3, c = u & 7;
            cp_async16(s + 2 * GARR_A + r * GROWB + c * 16,
                       Bw + (size_t)(rowB0 + r) * K + k0 + c * 8);
        }
    };

    // prologue: stage 0
    load_stage(0, 0);
    CP_COMMIT();

    for (int i = 0; i < nchunks; i++) {
        CP_WAIT(0);                // chunk i fully arrived
        __syncthreads();           // publish; all warps done with chunk i-1

        if (i + 1 < nchunks) load_stage(i + 1, (i + 1) & 1);
        CP_COMMIT();

        const int stage = i & 1;
        const uint32_t sAhi = sb + stage * GSTAGE;
        const uint32_t sAlo = sAhi + GARR_A;
        const uint32_t sBw  = sAlo + GARR_A;

        #pragma unroll
        for (int ks = 0; ks < 4; ks++) {
            const int kb = ks * 32;
            uint32_t ah[4][4], al[4][4];
            #pragma unroll
            for (int mt = 0; mt < 4; mt++) {
                uint32_t aoff = (uint32_t)(warp_m * 64 + mt * 16 + a_lr) * GROWB + a_kc * 2 + kb;
                ldmatrix_x4(ah[mt], sAhi + aoff);
                ldmatrix_x4(al[mt], sAlo + aoff);
            }
            uint32_t bw[2][2];
            {
                uint32_t boff = (uint32_t)(warp_n * 64 + b_lr) * GROWB + b_kc * 2 + kb;
                ldmatrix_x2(bw[0], sBw + boff);
            }
            #pragma unroll
            for (int nt = 0; nt < 8; nt++) {
                const int cur = nt & 1;
                if (nt < 7) {
                    uint32_t boff = (uint32_t)(warp_n * 64 + (nt + 1) * 8 + b_lr) * GROWB + b_kc * 2 + kb;
                    ldmatrix_x2(bw[cur ^ 1], sBw + boff);
                }
                #pragma unroll
                for (int mt = 0; mt < 4; mt++) {
                    mma_f16(acc[mt][nt], ah[mt], bw[cur]);
                    mma_f16(acc[mt][nt], al[mt], bw[cur]);
                }
            }
        }
    }
}

// Generic GEMM (O projection): C[M,N] row stride N, M-tile = 256
__global__ void __launch_bounds__(256, 1)
gemm_f16x2_kernel(const __half* __restrict__ Ahi,
                  const __half* __restrict__ Alo,
                  const __half* __restrict__ Bw,
                  const float* __restrict__ bias,
                  float* __restrict__ C,
                  int M, int N, int K)
{
    extern __shared__ char smem[];
    const uint32_t sb = smem_to_u32(smem);
    const int tid  = threadIdx.x;
    const int wid  = tid >> 5;
    const int lane = tid & 31;
    const int rowA0 = blockIdx.y * 256;
    const int rowB0 = blockIdx.x * 128;

    float acc[4][8][4];
    #pragma unroll
    for (int i = 0; i < 4; i++)
        #pragma unroll
        for (int j = 0; j < 8; j++)
            #pragma unroll
            for (int k = 0; k < 4; k++) acc[i][j][k] = 0.0f;

    gemm_mainloop(Ahi, Alo, Bw, rowA0, rowB0, K, sb, tid, acc);

    const int warp_m = wid >> 1, warp_n = wid & 1;
    #pragma unroll
    for (int mt = 0; mt < 4; mt++)
        #pragma unroll
        for (int nt = 0; nt < 8; nt++) {
            int row = rowA0 + warp_m * 64 + mt * 16 + (lane >> 2);
            int col = rowB0 + warp_n * 64 + nt * 8 + (lane & 3) * 2;
            float2 b01 = *(const float2*)&bias[col];
            float2 o0 = {acc[mt][nt][0] + b01.x, acc[mt][nt][1] + b01.y};
            float2 o1 = {acc[mt][nt][2] + b01.x, acc[mt][nt][3] + b01.y};
            *(float2*)&C[(size_t)row * N + col]       = o0;
            *(float2*)&C[(size_t)(row + 8) * N + col] = o1;
        }
}

// Fused QKV projection: writes into QKV buffer [M][3072], M-tile = 256
__global__ void __launch_bounds__(256, 1)
gemm_qkv_kernel(const __half* __restrict__ xhi,
                const __half* __restrict__ xlo,
                const __half* __restrict__ wqT,
                const __half* __restrict__ wkT,
                const __half* __restrict__ wvT,
                const float* __restrict__ bq, const float* __restrict__ bk,
                const float* __restrict__ bv,
                float* __restrict__ C)
{
    extern __shared__ char smem[];
    const uint32_t sb = smem_to_u32(smem);
    const int tid  = threadIdx.x;
    const int wid  = tid >> 5;
    const int lane = tid & 31;
    const int cCol = blockIdx.x;         // 0..23
    const int rowA0 = blockIdx.y * 256;

    const __half* Bw;
    const float* bias;
    int rowB0;
    if (cCol < 16)      { Bw = wqT; bias = bq; rowB0 = cCol * 128; }
    else if (cCol < 20) { Bw = wkT; bias = bk; rowB0 = (cCol - 16) * 128; }
    else                { Bw = wvT; bias = bv; rowB0 = (cCol - 20) * 128; }

    float acc[4][8][4];
    #pragma unroll
    for (int i = 0; i < 4; i++)
        #pragma unroll
        for (int j = 0; j < 8; j++)
            #pragma unroll
            for (int k = 0; k < 4; k++) acc[i][j][k] = 0.0f;

    gemm_mainloop(xhi, xlo, Bw, rowA0, rowB0, E_, sb, tid, acc);

    const int warp_m = wid >> 1, warp_n = wid & 1;
    #pragma unroll
    for (int mt = 0; mt < 4; mt++)
        #pragma unroll
        for (int nt = 0; nt < 8; nt++) {
            int row  = rowA0 + warp_m * 64 + mt * 16 + (lane >> 2);
            int bcol = rowB0 + warp_n * 64 + nt * 8 + (lane & 3) * 2;
            int col  = cCol * 128 + warp_n * 64 + nt * 8 + (lane & 3) * 2;
            float2 b01 = *(const float2*)&bias[bcol];
            float2 o0 = {acc[mt][nt][0] + b01.x, acc[mt][nt][1] + b01.y};
            float2 o1 = {acc[mt][nt][2] + b01.x, acc[mt][nt][3] + b01.y};
            *(float2*)&C[(size_t)row * NQKV + col]       = o0;
            *(float2*)&C[(size_t)(row + 8) * NQKV + col] = o1;
        }
}

// ---------------------------------------------------------------------------
// Flash attention, split-bf16 HMMA (unchanged). Br=128, Bc=64, 8 warps.
// Epilogue emits fp16 hi/lo for the O projection.
// ---------------------------------------------------------------------------
#define FROWB  272
#define QARR   (128 * FROWB)        // 34816
#define KARR   (64 * FROWB)         // 17408
#define FSTG   (4 * KARR)           // 69632 (Kh,Kl,Vh,Vl)
#define FSMEM  (2 * QARR + 2 * FSTG)  // 208896

__global__ void __launch_bounds__(256, 1)
flash_mma_kernel(const __nv_bfloat16* __restrict__ Qh, const __nv_bfloat16* __restrict__ Ql,
                 const __nv_bfloat16* __restrict__ Kh, const __nv_bfloat16* __restrict__ Kl,
                 const __nv_bfloat16* __restrict__ Vh, const __nv_bfloat16* __restrict__ Vl,
                 __half* __restrict__ Ohi, __half* __restrict__ Olo)
{
    extern __shared__ char smem[];
    const uint32_t sb = smem_to_u32(smem);
    const int tid  = threadIdx.x;
    const int lane = tid & 31;
    const int warp = tid >> 5;
    const int qt = (int)gridDim.x - 1 - (int)blockIdx.x;   // heavy tiles first
    const int h = blockIdx.y, b = blockIdx.z;
    const int g  = h >> 2;
    const int q0 = qt * 128;
    const int nkv = 2 * qt + 2;

    const uint32_t sQh = sb, sQl = sb + QARR;
    const uint32_t sKV0 = sb + 2 * QARR;

    const size_t qbase  = ((size_t)(b * H_ + h) * S_ + q0) * HD_;
    const size_t kvbase = ((size_t)(b * KVH_ + g) * S_) * HD_;

    const uint32_t q_off = (uint32_t)(lane & 15) * FROWB + (lane >> 4) * 16;
    const uint32_t k_off = (uint32_t)((lane & 7) | ((lane >> 1) & 8)) * FROWB + ((lane >> 3) & 1) * 16;

    #pragma unroll
    for (int t = 0; t < 8; t++) {
        int u = t * 256 + tid;
        int r = u >> 4, cb = (u & 15) * 16, ce = (u & 15) * 8;
        cp_async16(sQh + r * FROWB + cb, Qh + qbase + (size_t)r * HD_ + ce);
        cp_async16(sQl + r * FROWB + cb, Ql + qbase + (size_t)r * HD_ + ce);
    }
    auto load_kv = [&](int kt, int buf) {
        uint32_t s = sKV0 + buf * FSTG;
        const size_t base = kvbase + (size_t)kt * 64 * HD_;
        #pragma unroll
        for (int t = 0; t < 4; t++) {
            int u = t * 256 + tid;
            int r = u >> 4, cb = (u & 15) * 16, ce = (u & 15) * 8;
            size_t go = base + (size_t)r * HD_ + ce;
            uint32_t so = r * FROWB + cb;
            cp_async16(s + so,            Kh + go);
            cp_async16(s + KARR + so,     Kl + go);
            cp_async16(s + 2 * KARR + so, Vh + go);
            cp_async16(s + 3 * KARR + so, Vl + go);
        }
    };
    load_kv(0, 0);
    CP_COMMIT();

    float oacc[16][4];
    #pragma unroll
    for (int i = 0; i < 16; i++)
        #pragma unroll
        for (int j = 0; j < 4; j++) oacc[i][j] = 0.0f;
    float m0 = -INFINITY, m1 = -INFINITY, l0 = 0.0f, l1 = 0.0f;

    for (int kt = 0; kt < nkv; kt++) {
        __syncthreads();
        if (kt + 1 < nkv) { load_kv(kt + 1, (kt + 1) & 1); CP_COMMIT(); CP_WAIT(1); }
        else              { CP_WAIT(0); }
        __syncthreads();

        const uint32_t st  = sKV0 + (kt & 1) * FSTG;
        const uint32_t sKh = st, sKl = st + KARR, sVh = st + 2 * KARR, sVl = st + 3 * KARR;

        float sacc[8][4];
        #pragma unroll
        for (int i = 0; i < 8; i++)
            #pragma unroll
            for (int j = 0; j < 4; j++) sacc[i][j] = 0.0f;

        #pragma unroll
        for (int kk = 0; kk < 8; kk++) {
            const uint32_t kb = kk * 32;
            uint32_t qh[4], ql[4];
            ldmatrix_x4(qh, sQh + (uint32_t)warp * 16 * FROWB + q_off + kb);
            ldmatrix_x4(ql, sQl + (uint32_t)warp * 16 * FROWB + q_off + kb);
            #pragma unroll
            for (int np = 0; np < 4; np++) {
                uint32_t kh[4], kl[4];
                ldmatrix_x4(kh, sKh + (uint32_t)np * 16 * FROWB + k_off + kb);
                ldmatrix_x4(kl, sKl + (uint32_t)np * 16 * FROWB + k_off + kb);
                mma_bf16(sacc[2*np],   qh, &kh[0]);
                mma_bf16(sacc[2*np],   qh, &kl[0]);
                mma_bf16(sacc[2*np],   ql, &kh[0]);
                mma_bf16(sacc[2*np+1], qh, &kh[2]);
                mma_bf16(sacc[2*np+1], qh, &kl[2]);
                mma_bf16(sacc[2*np+1], ql, &kh[2]);
            }
        }

        if (kt >= 2 * qt) {
            const int rg0 = q0 + warp * 16 + (lane >> 2);
            const int cg0 = kt * 64 + (lane & 3) * 2;
            #pragma unroll
            for (int nt = 0; nt < 8; nt++)
                #pragma unroll
                for (int j = 0; j < 4; j++) {
                    int col = cg0 + nt * 8 + (j & 1);
                    int row = rg0 + (j >> 1) * 8;
                    if (col > row) sacc[nt][j] = -INFINITY;
                }
        }

        float mx0 = -INFINITY, mx1 = -INFINITY;
        #pragma unroll
        for (int nt = 0; nt < 8; nt++) {
            mx0 = fmaxf(mx0, fmaxf(sacc[nt][0], sacc[nt][1]));
            mx1 = fmaxf(mx1, fmaxf(sacc[nt][2], sacc[nt][3]));
        }
        mx0 = fmaxf(mx0, __shfl_xor_sync(0xFFFFFFFF, mx0, 1));
        mx0 = fmaxf(mx0, __shfl_xor_sync(0xFFFFFFFF, mx0, 2));
        mx1 = fmaxf(mx1, __shfl_xor_sync(0xFFFFFFFF, mx1, 1));
        mx1 = fmaxf(mx1, __shfl_xor_sync(0xFFFFFFFF, mx1, 2));
        float mn0 = fmaxf(m0, mx0), mn1 = fmaxf(m1, mx1);
        float al0 = __expf(m0 - mn0), al1 = __expf(m1 - mn1);
        m0 = mn0; m1 = mn1;

        float ps0 = 0.0f, ps1 = 0.0f;
        #pragma unroll
        for (int nt = 0; nt < 8; nt++) {
            float p0 = __expf(sacc[nt][0] - mn0);
            float p1 = __expf(sacc[nt][1] - mn0);
            float p2 = __expf(sacc[nt][2] - mn1);
            float p3 = __expf(sacc[nt][3] - mn1);
            sacc[nt][0] = p0; sacc[nt][1] = p1; sacc[nt][2] = p2; sacc[nt][3] = p3;
            ps0 += p0 + p1; ps1 += p2 + p3;
        }
        ps0 += __shfl_xor_sync(0xFFFFFFFF, ps0, 1);
        ps0 += __shfl_xor_sync(0xFFFFFFFF, ps0, 2);
        ps1 += __shfl_xor_sync(0xFFFFFFFF, ps1, 1);
        ps1 += __shfl_xor_sync(0xFFFFFFFF, ps1, 2);
        l0 = l0 * al0 + ps0;
        l1 = l1 * al1 + ps1;

        #pragma unroll
        for (int i = 0; i < 16; i++) {
            oacc[i][0] *= al0; oacc[i][1] *= al0;
            oacc[i][2] *= al1; oacc[i][3] *= al1;
        }

        #pragma unroll
        for (int tk = 0; tk < 4; tk++) {
            uint32_t ah[4], al_[4];
            split2(sacc[2*tk][0],   sacc[2*tk][1],   ah[0], al_[0]);
            split2(sacc[2*tk][2],   sacc[2*tk][3],   ah[1], al_[1]);
            split2(sacc[2*tk+1][0], sacc[2*tk+1][1], ah[2], al_[2]);
            split2(sacc[2*tk+1][2], sacc[2*tk+1][3], ah[3], al_[3]);
            #pragma unroll
            for (int dp = 0; dp < 8; dp++) {
                uint32_t vh[4], vl[4];
                const uint32_t vo = (uint32_t)tk * 16 * FROWB + q_off + dp * 32;
                ldmatrix_x4_trans(vh, sVh + vo);
                ldmatrix_x4_trans(vl, sVl + vo);
                mma_bf16(oacc[2*dp],   ah,  &vh[0]);
                mma_bf16(oacc[2*dp],   ah,  &vl[0]);
                mma_bf16(oacc[2*dp],   al_, &vh[0]);
                mma_bf16(oacc[2*dp+1], ah,  &vh[2]);
                mma_bf16(oacc[2*dp+1], ah,  &vl[2]);
                mma_bf16(oacc[2*dp+1], al_, &vh[2]);
            }
        }
    }

    const float il0 = 1.0f / l0, il1 = 1.0f / l1;
    const int r0 = q0 + warp * 16 + (lane >> 2);
    const int c0 = h * HD_ + (lane & 3) * 2;
    #pragma unroll
    for (int nt = 0; nt < 16; nt++) {
        float o0 = oacc[nt][0] * il0, o1 = oacc[nt][1] * il0;
        float o2 = oacc[nt][2] * il1, o3 = oacc[nt][3] * il1;
        uint32_t h0, l0r, h1, l1r;
        split2h(o0, o1, h0, l0r);
        split2h(o2, o3, h1, l1r);
        size_t i0 = (size_t)(b * S_ + r0)     * E_ + c0 + nt * 8;
        size_t i1 = (size_t)(b * S_ + r0 + 8) * E_ + c0 + nt * 8;
        *(uint32_t*)(Ohi + i0) = h0; *(uint32_t*)(Olo + i0) = l0r;
        *(uint32_t*)(Ohi + i1) = h1; *(uint32_t*)(Olo + i1) = l1r;
    }
}

// ---------------------------------------------------------------------------
extern "C" void kernel_launch(void* const* d_in, const int* in_sizes, int n_in,
                              void* d_out, int out_size)
{
    const float* x  = (const float*)d_in[0];
    const float* wq = (const float*)d_in[1];
    const float* bq = (const float*)d_in[2];
    const float* wk = (const float*)d_in[3];
    const float* bk = (const float*)d_in[4];
    const float* wv = (const float*)d_in[5];
    const float* bv = (const float*)d_in[6];
    const float* wo = (const float*)d_in[7];
    const float* bo = (const float*)d_in[8];
    float* out = (float*)d_out;

    float* QKVp;
    cudaGetSymbolAddress((void**)&QKVp, g_QKV);
    __half *xhi, *xlo, *aohi, *aolo, *wqT, *wkT, *wvT, *woT;
    __nv_bfloat16 *qbh, *qbl, *kbh, *kbl, *vbh, *vbl;
    cudaGetSymbolAddress((void**)&xhi,  g_xhi);
    cudaGetSymbolAddress((void**)&xlo,  g_xlo);
    cudaGetSymbolAddress((void**)&aohi, g_aohi);
    cudaGetSymbolAddress((void**)&aolo, g_aolo);
    cudaGetSymbolAddress((void**)&wqT, g_wqT);
    cudaGetSymbolAddress((void**)&wkT, g_wkT);
    cudaGetSymbolAddress((void**)&wvT, g_wvT);
    cudaGetSymbolAddress((void**)&woT, g_woT);
    cudaGetSymbolAddress((void**)&qbh, g_Qbh);
    cudaGetSymbolAddress((void**)&qbl, g_Qbl);
    cudaGetSymbolAddress((void**)&kbh, g_Kbh);
    cudaGetSymbolAddress((void**)&kbl, g_Kbl);
    cudaGetSymbolAddress((void**)&vbh, g_Vbh);
    cudaGetSymbolAddress((void**)&vbl, g_Vbl);

    cudaFuncSetAttribute(gemm_qkv_kernel,
                         cudaFuncAttributeMaxDynamicSharedMemorySize, GSMEM);
    cudaFuncSetAttribute(gemm_f16x2_kernel,
                         cudaFuncAttributeMaxDynamicSharedMemorySize, GSMEM);
    cudaFuncSetAttribute(flash_mma_kernel,
                         cudaFuncAttributeMaxDynamicSharedMemorySize, FSMEM);

    // conversions
    {
        int n4 = M_ * E_ / 4;
        convert_hilo_h_kernel<<<(n4 + 255) / 256, 256>>>(x, xhi, xlo, n4);
        dim3 blk(32, 8);
        transpose_h_kernel<<<dim3(E_ / 32, E_ / 32), blk>>>(wq, wqT, E_, E_);
        transpose_h_kv_kernel<<<dim3((KVH_ * HD_) / 32, E_ / 32, 2), blk>>>(
            wk, wv, wkT, wvT);
    }

    // Fused QKV projection (N = 3072, M-tile 256)
    gemm_qkv_kernel<<<dim3(NQKV / 128, M_ / 256), 256, GSMEM>>>(
        xhi, xlo, wqT, wkT, wvT, bq, bk, bv, QKVp);

    // RoPE + split + relayout (reads QKV buffer)
    {
        int totq = B_ * S_ * H_ * (HD_ / 2);
        int totk = B_ * S_ * KVH_ * (HD_ / 2);
        float qscale = 1.0f / sqrtf((float)HD_);
        rope_split_kernel<<<(totq + 255) / 256, 256>>>(QKVp, qbh, qbl, H_, qscale);
        rope_split_kernel<<<(totk + 255) / 256, 256>>>(QKVp + 2048, kbh, kbl, KVH_, 1.0f);
        v_split_kernel<<<(totk + 255) / 256, 256>>>(QKVp + 2560, vbh, vbl);
    }

    // Flash attention (HMMA split-bf16, Br=128) -> fp16 hi/lo output
    flash_mma_kernel<<<dim3(S_ / 128, H_, B_), 256, FSMEM>>>(
        qbh, qbl, kbh, kbl, vbh, vbl, aohi, aolo);

    // wo transpose (deferred; only needed by O-proj)
    {
        dim3 blk(32, 8);
        transpose_h_kernel<<<dim3(E_ / 32, E_ / 32), blk>>>(wo, woT, E_, E_);
    }

    // Output projection -> d_out (M-tile 256)
    gemm_f16x2_kernel<<<dim3(E_ / 128, M_ / 256), 256, GSMEM>>>(
        aohi, aolo, woT, bo, out, M_, E_, E_);
}

// round 15
// speedup vs baseline: 1.4776x; 1.1413x over previous
#include <cuda_runtime.h>
#include <cuda_fp16.h>
#include <math.h>
#include <cstdint>

#define B_   2
#define S_   2048
#define E_   2048
#define H_   16
#define KVH_ 4
#define HD_  128
#define REP_ 4
#define M_   (B_*S_)     // 4096
#define NQKV 3072        // 2048 Q + 512 K + 512 V

// ---------------------------------------------------------------------------
// Scratch (__device__ globals; no allocations allowed)
// ---------------------------------------------------------------------------
__device__ float g_QKV[M_*NQKV];

// fp16 operands: A split hi/lo, weights single fp16
__device__ __half g_xhi[M_*E_],  g_xlo[M_*E_];
__device__ __half g_aohi[M_*E_], g_aolo[M_*E_];
__device__ __half g_wqT[E_*E_];
__device__ __half g_wkT[KVH_*HD_*E_];
__device__ __half g_wvT[KVH_*HD_*E_];
__device__ __half g_woT[E_*E_];

// flash operands (all fp16 now): Q hi/lo, K single, V single
__device__ __half g_Qbh[M_*H_*HD_],  g_Qbl[M_*H_*HD_];
__device__ __half g_Kw[M_*KVH_*HD_];
__device__ __half g_Vw[M_*KVH_*HD_];

// ---------------------------------------------------------------------------
// PTX helpers (non-'a' ISA only: mma.sync / ldmatrix / cp.async)
// ---------------------------------------------------------------------------
__device__ __forceinline__ uint32_t smem_to_u32(const void* p) {
    uint32_t a;
    asm("{ .reg .u64 t; cvta.to.shared.u64 t, %1; cvt.u32.u64 %0, t; }" : "=r"(a) : "l"(p));
    return a;
}
__device__ __forceinline__ void cp_async16(uint32_t saddr, const void* gptr) {
    asm volatile("cp.async.cg.shared.global [%0], [%1], 16;\n" :: "r"(saddr), "l"(gptr));
}
#define CP_COMMIT() asm volatile("cp.async.commit_group;\n" ::: "memory")
#define CP_WAIT(n)  asm volatile("cp.async.wait_group %0;\n" :: "n"(n) : "memory")

__device__ __forceinline__ void ldmatrix_x4(uint32_t* r, uint32_t addr) {
    asm volatile("ldmatrix.sync.aligned.m8n8.x4.shared.b16 {%0,%1,%2,%3}, [%4];\n"
                 : "=r"(r[0]), "=r"(r[1]), "=r"(r[2]), "=r"(r[3]) : "r"(addr));
}
__device__ __forceinline__ void ldmatrix_x4_trans(uint32_t* r, uint32_t addr) {
    asm volatile("ldmatrix.sync.aligned.m8n8.x4.trans.shared.b16 {%0,%1,%2,%3}, [%4];\n"
                 : "=r"(r[0]), "=r"(r[1]), "=r"(r[2]), "=r"(r[3]) : "r"(addr));
}
__device__ __forceinline__ void ldmatrix_x2(uint32_t* r, uint32_t addr) {
    asm volatile("ldmatrix.sync.aligned.m8n8.x2.shared.b16 {%0,%1}, [%2];\n"
                 : "=r"(r[0]), "=r"(r[1]) : "r"(addr));
}
__device__ __forceinline__ void mma_f16(float* c, const uint32_t* a, const uint32_t* b) {
    asm volatile(
        "mma.sync.aligned.m16n8k16.row.col.f32.f16.f16.f32 "
        "{%0,%1,%2,%3}, {%4,%5,%6,%7}, {%8,%9}, {%0,%1,%2,%3};\n"
        : "+f"(c[0]), "+f"(c[1]), "+f"(c[2]), "+f"(c[3])
        : "r"(a[0]), "r"(a[1]), "r"(a[2]), "r"(a[3]), "r"(b[0]), "r"(b[1]));
}
// fp16 hi/lo split
__device__ __forceinline__ void split2h(float a, float b, uint32_t& hi, uint32_t& lo) {
    __half ha = __float2half_rn(a), hb = __float2half_rn(b);
    __half la = __float2half_rn(a - __half2float(ha));
    __half lb = __float2half_rn(b - __half2float(hb));
    __half2 h2 = __halves2half2(ha, hb);
    __half2 l2 = __halves2half2(la, lb);
    hi = *(uint32_t*)&h2;
    lo = *(uint32_t*)&l2;
}

// ---------------------------------------------------------------------------
// Conversion kernels
// ---------------------------------------------------------------------------
__global__ void convert_hilo_h_kernel(const float* __restrict__ in,
                                      __half* __restrict__ hi,
                                      __half* __restrict__ lo, int n4)
{
    int i = blockIdx.x * blockDim.x + threadIdx.x;
    if (i >= n4) return;
    float4 v = ((const float4*)in)[i];
    uint32_t h0, l0, h1, l1;
    split2h(v.x, v.y, h0, l0);
    split2h(v.z, v.w, h1, l1);
    uint32_t* ph = (uint32_t*)(hi + 4 * (size_t)i);
    uint32_t* pl = (uint32_t*)(lo + 4 * (size_t)i);
    ph[0] = h0; ph[1] = h1;
    pl[0] = l0; pl[1] = l1;
}

// W[K x N] fp32 -> WT[N x K] single fp16
__global__ void transpose_h_kernel(const float* __restrict__ W,
                                   __half* __restrict__ T,
                                   int K, int N)
{
    __shared__ float tile[32][33];
    int n0 = blockIdx.x * 32, k0 = blockIdx.y * 32;
    int tx = threadIdx.x, ty = threadIdx.y;
    #pragma unroll
    for (int r = 0; r < 4; r++)
        tile[ty + r * 8][tx] = W[(size_t)(k0 + ty + r * 8) * N + n0 + tx];
    __syncthreads();
    #pragma unroll
    for (int r = 0; r < 4; r++) {
        float v = tile[tx][ty + r * 8];
        T[(size_t)(n0 + ty + r * 8) * K + k0 + tx] = __float2half_rn(v);
    }
}

// merged K/V weight transpose (z selects tensor)
__global__ void transpose_h_kv_kernel(const float* __restrict__ Wk,
                                      const float* __restrict__ Wv,
                                      __half* __restrict__ Tk, __half* __restrict__ Tv)
{
    const int K = E_, N = KVH_ * HD_;
    const float* W = blockIdx.z ? Wv : Wk;
    __half* T = blockIdx.z ? Tv : Tk;
    __shared__ float tile[32][33];
    int n0 = blockIdx.x * 32, k0 = blockIdx.y * 32;
    int tx = threadIdx.x, ty = threadIdx.y;
    #pragma unroll
    for (int r = 0; r < 4; r++)
        tile[ty + r * 8][tx] = W[(size_t)(k0 + ty + r * 8) * N + n0 + tx];
    __syncthreads();
    #pragma unroll
    for (int r = 0; r < 4; r++) {
        float v = tile[tx][ty + r * 8];
        T[(size_t)(n0 + ty + r * 8) * K + k0 + tx] = __float2half_rn(v);
    }
}

// Q: RoPE + fp16 hi/lo split, [b][s][h][d] -> [b][h][s][d], pre-scaled
__global__ void rope_split_q_kernel(const float* __restrict__ in,
                                    __half* __restrict__ outh,
                                    __half* __restrict__ outl)
{
    int idx = blockIdx.x * blockDim.x + threadIdx.x;
    int total = B_ * S_ * H_ * (HD_ / 2);
    if (idx >= total) return;
    int d2 = idx & 63;
    int h  = (idx >> 6) % H_;
    int s  = (idx / (64 * H_)) % S_;
    int b  = idx / (64 * H_ * S_);
    float p    = powf(100000.0f, (float)(2 * d2));   // inf for 2*d2 >= 8
    float freq = 1.0f / p;                           // 0 when p == inf
    float ang  = (float)s * freq;
    float sn, cs;
    sincosf(ang, &sn, &cs);
    size_t src = (size_t)(b * S_ + s) * NQKV + h * HD_ + 2 * d2;
    float tr = in[src], ti = in[src + 1];
    const float scale = 0.08838834764831845f;        // 1/sqrt(128)
    float o0 = (tr * cs - ti * sn) * scale;
    float o1 = (tr * sn + ti * cs) * scale;
    uint32_t hi, lo;
    split2h(o0, o1, hi, lo);
    size_t dst = ((size_t)(b * H_ + h) * S_ + s) * HD_ + 2 * d2;
    *(uint32_t*)(outh + dst) = hi;
    *(uint32_t*)(outl + dst) = lo;
}

// K: RoPE + single fp16, [b][s][g][d] -> [b][g][s][d]
__global__ void rope_k_kernel(const float* __restrict__ in,
                              __half* __restrict__ out)
{
    int idx = blockIdx.x * blockDim.x + threadIdx.x;
    int total = B_ * S_ * KVH_ * (HD_ / 2);
    if (idx >= total) return;
    int d2 = idx & 63;
    int g  = (idx >> 6) % KVH_;
    int s  = (idx / (64 * KVH_)) % S_;
    int b  = idx / (64 * KVH_ * S_);
    float p    = powf(100000.0f, (float)(2 * d2));
    float freq = 1.0f / p;
    float ang  = (float)s * freq;
    float sn, cs;
    sincosf(ang, &sn, &cs);
    size_t src = (size_t)(b * S_ + s) * NQKV + 2048 + g * HD_ + 2 * d2;
    float tr = in[src], ti = in[src + 1];
    float o0 = tr * cs - ti * sn;
    float o1 = tr * sn + ti * cs;
    __half2 h2 = __halves2half2(__float2half_rn(o0), __float2half_rn(o1));
    size_t dst = ((size_t)(b * KVH_ + g) * S_ + s) * HD_ + 2 * d2;
    *(uint32_t*)(out + dst) = *(uint32_t*)&h2;
}

// V: single fp16 + relayout
__global__ void v_single_kernel(const float* __restrict__ in,
                                __half* __restrict__ out)
{
    int idx = blockIdx.x * blockDim.x + threadIdx.x;
    int total = B_ * S_ * KVH_ * (HD_ / 2);
    if (idx >= total) return;
    int d2 = idx & 63;
    int g  = (idx >> 6) % KVH_;
    int s  = (idx / (64 * KVH_)) % S_;
    int b  = idx / (64 * KVH_ * S_);
    size_t src = (size_t)(b * S_ + s) * NQKV + 2560 + g * HD_ + 2 * d2;
    float2 v = *(const float2*)(in + src);
    __half2 h2 = __halves2half2(__float2half_rn(v.x), __float2half_rn(v.y));
    size_t dst = ((size_t)(b * KVH_ + g) * S_ + s) * HD_ + 2 * d2;
    *(uint32_t*)(out + dst) = *(uint32_t*)&h2;
}

// ---------------------------------------------------------------------------
// fp16 2-MMA GEMM mainloop: C = (Ah+Al) @ B^T
// 256x128 tile, K chunks of 64, 2 stages, single sync per chunk.
// ---------------------------------------------------------------------------
#define GBK      64
#define GROWB    144                   // 128B data + 16 pad
#define GARR_A   (256 * GROWB)         // 36864
#define GARR_B   (128 * GROWB)         // 18432
#define GSTAGE   (2 * GARR_A + GARR_B) // 92160
#define GSTAGES  2
#define GSMEM    (GSTAGES * GSTAGE)    // 184320

__device__ __forceinline__ void gemm_mainloop(
    const __half* __restrict__ Ahi, const __half* __restrict__ Alo,
    const __half* __restrict__ Bw,
    int rowA0, int rowB0, int K, uint32_t sb, int tid, float acc[4][8][4])
{
    const int wid  = tid >> 5;
    const int lane = tid & 31;
    const int warp_m = wid >> 1;
    const int warp_n = wid & 1;
    const int nchunks = K / GBK;

    const int a_lr = lane & 15;
    const int a_kc = (lane >> 4) * 8;
    const int b_lr = lane & 7;
    const int b_kc = ((lane >> 3) & 3) * 8;

    auto load_stage = [&](int chunk, int stage) {
        const int k0 = chunk * GBK;
        uint32_t s = sb + stage * GSTAGE;
        #pragma unroll
        for (int t = 0; t < 8; t++) {
            int u = t * 256 + tid;
            int r = u >> 3, c = u & 7;
            cp_async16(s + r * GROWB + c * 16,
                       Ahi + (size_t)(rowA0 + r) * K + k0 + c * 8);
            cp_async16(s + GARR_A + r * GROWB + c * 16,
                       Alo + (size_t)(rowA0 + r) * K + k0 + c * 8);
        }
        #pragma unroll
        for (int t = 0; t < 4; t++) {
            int u = t * 256 + tid;
            int r = u >> 3, c = u & 7;
            cp_async16(s + 2 * GARR_A + r * GROWB + c * 16,
                       Bw + (size_t)(rowB0 + r) * K + k0 + c * 8);
        }
    };

    load_stage(0, 0);
    CP_COMMIT();

    for (int i = 0; i < nchunks; i++) {
        CP_WAIT(0);
        __syncthreads();

        if (i + 1 < nchunks) load_stage(i + 1, (i + 1) & 1);
        CP_COMMIT();

        const int stage = i & 1;
        const uint32_t sAhi = sb + stage * GSTAGE;
        const uint32_t sAlo = sAhi + GARR_A;
        const uint32_t sBw  = sAlo + GARR_A;

        #pragma unroll
        for (int ks = 0; ks < 4; ks++) {
            const int kb = ks * 32;
            uint32_t ah[4][4], al[4][4];
            #pragma unroll
            for (int mt = 0; mt < 4; mt++) {
                uint32_t aoff = (uint32_t)(warp_m * 64 + mt * 16 + a_lr) * GROWB + a_kc * 2 + kb;
                ldmatrix_x4(ah[mt], sAhi + aoff);
                ldmatrix_x4(al[mt], sAlo + aoff);
            }
            uint32_t bw[2][2];
            {
                uint32_t boff = (uint32_t)(warp_n * 64 + b_lr) * GROWB + b_kc * 2 + kb;
                ldmatrix_x2(bw[0], sBw + boff);
            }
            #pragma unroll
            for (int nt = 0; nt < 8; nt++) {
                const int cur = nt & 1;
                if (nt < 7) {
                    uint32_t boff = (uint32_t)(warp_n * 64 + (nt + 1) * 8 + b_lr) * GROWB + b_kc * 2 + kb;
                    ldmatrix_x2(bw[cur ^ 1], sBw + boff);
                }
                #pragma unroll
                for (int mt = 0; mt < 4; mt++) {
                    mma_f16(acc[mt][nt], ah[mt], bw[cur]);
                    mma_f16(acc[mt][nt], al[mt], bw[cur]);
                }
            }
        }
    }
}

// Generic GEMM (O projection)
__global__ void __launch_bounds__(256, 1)
gemm_f16x2_kernel(const __half* __restrict__ Ahi,
                  const __half* __restrict__ Alo,
                  const __half* __restrict__ Bw,
                  const float* __restrict__ bias,
                  float* __restrict__ C,
                  int M, int N, int K)
{
    extern __shared__ char smem[];
    const uint32_t sb = smem_to_u32(smem);
    const int tid  = threadIdx.x;
    const int wid  = tid >> 5;
    const int lane = tid & 31;
    const int rowA0 = blockIdx.y * 256;
    const int rowB0 = blockIdx.x * 128;

    float acc[4][8][4];
    #pragma unroll
    for (int i = 0; i < 4; i++)
        #pragma unroll
        for (int j = 0; j < 8; j++)
            #pragma unroll
            for (int k = 0; k < 4; k++) acc[i][j][k] = 0.0f;

    gemm_mainloop(Ahi, Alo, Bw, rowA0, rowB0, K, sb, tid, acc);

    const int warp_m = wid >> 1, warp_n = wid & 1;
    #pragma unroll
    for (int mt = 0; mt < 4; mt++)
        #pragma unroll
        for (int nt = 0; nt < 8; nt++) {
            int row = rowA0 + warp_m * 64 + mt * 16 + (lane >> 2);
            int col = rowB0 + warp_n * 64 + nt * 8 + (lane & 3) * 2;
            float2 b01 = *(const float2*)&bias[col];
            float2 o0 = {acc[mt][nt][0] + b01.x, acc[mt][nt][1] + b01.y};
            float2 o1 = {acc[mt][nt][2] + b01.x, acc[mt][nt][3] + b01.y};
            *(float2*)&C[(size_t)row * N + col]       = o0;
            *(float2*)&C[(size_t)(row + 8) * N + col] = o1;
        }
}

// Fused QKV projection
__global__ void __launch_bounds__(256, 1)
gemm_qkv_kernel(const __half* __restrict__ xhi,
                const __half* __restrict__ xlo,
                const __half* __restrict__ wqT,
                const __half* __restrict__ wkT,
                const __half* __restrict__ wvT,
                const float* __restrict__ bq, const float* __restrict__ bk,
                const float* __restrict__ bv,
                float* __restrict__ C)
{
    extern __shared__ char smem[];
    const uint32_t sb = smem_to_u32(smem);
    const int tid  = threadIdx.x;
    const int wid  = tid >> 5;
    const int lane = tid & 31;
    const int cCol = blockIdx.x;
    const int rowA0 = blockIdx.y * 256;

    const __half* Bw;
    const float* bias;
    int rowB0;
    if (cCol < 16)      { Bw = wqT; bias = bq; rowB0 = cCol * 128; }
    else if (cCol < 20) { Bw = wkT; bias = bk; rowB0 = (cCol - 16) * 128; }
    else                { Bw = wvT; bias = bv; rowB0 = (cCol - 20) * 128; }

    float acc[4][8][4];
    #pragma unroll
    for (int i = 0; i < 4; i++)
        #pragma unroll
        for (int j = 0; j < 8; j++)
            #pragma unroll
            for (int k = 0; k < 4; k++) acc[i][j][k] = 0.0f;

    gemm_mainloop(xhi, xlo, Bw, rowA0, rowB0, E_, sb, tid, acc);

    const int warp_m = wid >> 1, warp_n = wid & 1;
    #pragma unroll
    for (int mt = 0; mt < 4; mt++)
        #pragma unroll
        for (int nt = 0; nt < 8; nt++) {
            int row  = rowA0 + warp_m * 64 + mt * 16 + (lane >> 2);
            int bcol = rowB0 + warp_n * 64 + nt * 8 + (lane & 3) * 2;
            int col  = cCol * 128 + warp_n * 64 + nt * 8 + (lane & 3) * 2;
            float2 b01 = *(const float2*)&bias[bcol];
            float2 o0 = {acc[mt][nt][0] + b01.x, acc[mt][nt][1] + b01.y};
            float2 o1 = {acc[mt][nt][2] + b01.x, acc[mt][nt][3] + b01.y};
            *(float2*)&C[(size_t)row * NQKV + col]       = o0;
            *(float2*)&C[(size_t)(row + 8) * NQKV + col] = o1;
        }
}

// ---------------------------------------------------------------------------
// Flash attention, fp16 2-MMA both GEMMs. Br=128, Bc=64, HD=128, 8 warps.
// Q split hi/lo fp16 (exact), K single fp16, P split hi/lo (exact), V single.
// ---------------------------------------------------------------------------
#define FROWB  272
#define QARR   (128 * FROWB)        // 34816
#define KARR   (64 * FROWB)         // 17408
#define FSTG   (2 * KARR)           // 34816 (Kw, Vw)
#define FSMEM  (2 * QARR + 2 * FSTG)  // 139264

__global__ void __launch_bounds__(256, 1)
flash_mma_kernel(const __half* __restrict__ Qh, const __half* __restrict__ Ql,
                 const __half* __restrict__ Kw, const __half* __restrict__ Vw,
                 __half* __restrict__ Ohi, __half* __restrict__ Olo)
{
    extern __shared__ char smem[];
    const uint32_t sb = smem_to_u32(smem);
    const int tid  = threadIdx.x;
    const int lane = tid & 31;
    const int warp = tid >> 5;
    const int qt = (int)gridDim.x - 1 - (int)blockIdx.x;   // heavy tiles first
    const int h = blockIdx.y, b = blockIdx.z;
    const int g  = h >> 2;
    const int q0 = qt * 128;
    const int nkv = 2 * qt + 2;

    const uint32_t sQh = sb, sQl = sb + QARR;
    const uint32_t sKV0 = sb + 2 * QARR;

    const size_t qbase  = ((size_t)(b * H_ + h) * S_ + q0) * HD_;
    const size_t kvbase = ((size_t)(b * KVH_ + g) * S_) * HD_;

    const uint32_t q_off = (uint32_t)(lane & 15) * FROWB + (lane >> 4) * 16;
    const uint32_t k_off = (uint32_t)((lane & 7) | ((lane >> 1) & 8)) * FROWB + ((lane >> 3) & 1) * 16;

    // -- prologue: Q tile (128 rows) + KV stage 0 --
    #pragma unroll
    for (int t = 0; t < 8; t++) {
        int u = t * 256 + tid;                  // 0..2047
        int r = u >> 4, cb = (u & 15) * 16, ce = (u & 15) * 8;
        cp_async16(sQh + r * FROWB + cb, Qh + qbase + (size_t)r * HD_ + ce);
        cp_async16(sQl + r * FROWB + cb, Ql + qbase + (size_t)r * HD_ + ce);
    }
    auto load_kv = [&](int kt, int buf) {
        uint32_t s = sKV0 + buf * FSTG;
        const size_t base = kvbase + (size_t)kt * 64 * HD_;
        #pragma unroll
        for (int t = 0; t < 4; t++) {
            int u = t * 256 + tid;              // 0..1023
            int r = u >> 4, cb = (u & 15) * 16, ce = (u & 15) * 8;
            size_t go = base + (size_t)r * HD_ + ce;
            uint32_t so = r * FROWB + cb;
            cp_async16(s + so,        Kw + go);
            cp_async16(s + KARR + so, Vw + go);
        }
    };
    load_kv(0, 0);
    CP_COMMIT();

    float oacc[16][4];
    #pragma unroll
    for (int i = 0; i < 16; i++)
        #pragma unroll
        for (int j = 0; j < 4; j++) oacc[i][j] = 0.0f;
    float m0 = -INFINITY, m1 = -INFINITY, l0 = 0.0f, l1 = 0.0f;

    for (int kt = 0; kt < nkv; kt++) {
        __syncthreads();
        if (kt + 1 < nkv) { load_kv(kt + 1, (kt + 1) & 1); CP_COMMIT(); CP_WAIT(1); }
        else              { CP_WAIT(0); }
        __syncthreads();

        const uint32_t st  = sKV0 + (kt & 1) * FSTG;
        const uint32_t sKw = st, sVw = st + KARR;

        // ---- S = Q K^T (Q hi/lo fp16 x K fp16: 2-term) ----
        float sacc[8][4];
        #pragma unroll
        for (int i = 0; i < 8; i++)
            #pragma unroll
            for (int j = 0; j < 4; j++) sacc[i][j] = 0.0f;

        #pragma unroll
        for (int kk = 0; kk < 8; kk++) {
            const uint32_t kb = kk * 32;
            uint32_t qh[4], ql[4];
            ldmatrix_x4(qh, sQh + (uint32_t)warp * 16 * FROWB + q_off + kb);
            ldmatrix_x4(ql, sQl + (uint32_t)warp * 16 * FROWB + q_off + kb);
            #pragma unroll
            for (int np = 0; np < 4; np++) {
                uint32_t kw[4];
                ldmatrix_x4(kw, sKw + (uint32_t)np * 16 * FROWB + k_off + kb);
                mma_f16(sacc[2*np],   qh, &kw[0]);
                mma_f16(sacc[2*np],   ql, &kw[0]);
                mma_f16(sacc[2*np+1], qh, &kw[2]);
                mma_f16(sacc[2*np+1], ql, &kw[2]);
            }
        }

        // ---- causal mask (diagonal region spans kv chunks 2qt, 2qt+1) ----
        if (kt >= 2 * qt) {
            const int rg0 = q0 + warp * 16 + (lane >> 2);
            const int cg0 = kt * 64 + (lane & 3) * 2;
            #pragma unroll
            for (int nt = 0; nt < 8; nt++)
                #pragma unroll
                for (int j = 0; j < 4; j++) {
                    int col = cg0 + nt * 8 + (j & 1);
                    int row = rg0 + (j >> 1) * 8;
                    if (col > row) sacc[nt][j] = -INFINITY;
                }
        }

        // ---- online softmax ----
        float mx0 = -INFINITY, mx1 = -INFINITY;
        #pragma unroll
        for (int nt = 0; nt < 8; nt++) {
            mx0 = fmaxf(mx0, fmaxf(sacc[nt][0], sacc[nt][1]));
            mx1 = fmaxf(mx1, fmaxf(sacc[nt][2], sacc[nt][3]));
        }
        mx0 = fmaxf(mx0, __shfl_xor_sync(0xFFFFFFFF, mx0, 1));
        mx0 = fmaxf(mx0, __shfl_xor_sync(0xFFFFFFFF, mx0, 2));
        mx1 = fmaxf(mx1, __shfl_xor_sync(0xFFFFFFFF, mx1, 1));
        mx1 = fmaxf(mx1, __shfl_xor_sync(0xFFFFFFFF, mx1, 2));
        float mn0 = fmaxf(m0, mx0), mn1 = fmaxf(m1, mx1);
        float al0 = __expf(m0 - mn0), al1 = __expf(m1 - mn1);
        m0 = mn0; m1 = mn1;

        float ps0 = 0.0f, ps1 = 0.0f;
        #pragma unroll
        for (int nt = 0; nt < 8; nt++) {
            float p0 = __expf(sacc[nt][0] - mn0);
            float p1 = __expf(sacc[nt][1] - mn0);
            float p2 = __expf(sacc[nt][2] - mn1);
            float p3 = __expf(sacc[nt][3] - mn1);
            sacc[nt][0] = p0; sacc[nt][1] = p1; sacc[nt][2] = p2; sacc[nt][3] = p3;
            ps0 += p0 + p1; ps1 += p2 + p3;
        }
        ps0 += __shfl_xor_sync(0xFFFFFFFF, ps0, 1);
        ps0 += __shfl_xor_sync(0xFFFFFFFF, ps0, 2);
        ps1 += __shfl_xor_sync(0xFFFFFFFF, ps1, 1);
        ps1 += __shfl_xor_sync(0xFFFFFFFF, ps1, 2);
        l0 = l0 * al0 + ps0;
        l1 = l1 * al1 + ps1;

        #pragma unroll
        for (int i = 0; i < 16; i++) {
            oacc[i][0] *= al0; oacc[i][1] *= al0;
            oacc[i][2] *= al1; oacc[i][3] *= al1;
        }

        // ---- O += P V (P hi/lo fp16 x V fp16: 2-term) ----
        #pragma unroll
        for (int tk = 0; tk < 4; tk++) {
            uint32_t ah[4], al_[4];
            split2h(sacc[2*tk][0],   sacc[2*tk][1],   ah[0], al_[0]);
            split2h(sacc[2*tk][2],   sacc[2*tk][3],   ah[1], al_[1]);
            split2h(sacc[2*tk+1][0], sacc[2*tk+1][1], ah[2], al_[2]);
            split2h(sacc[2*tk+1][2], sacc[2*tk+1][3], ah[3], al_[3]);
            #pragma unroll
            for (int dp = 0; dp < 8; dp++) {
                uint32_t vw[4];
                const uint32_t vo = (uint32_t)tk * 16 * FROWB + q_off + dp * 32;
                ldmatrix_x4_trans(vw, sVw + vo);
                mma_f16(oacc[2*dp],   ah,  &vw[0]);
                mma_f16(oacc[2*dp],   al_, &vw[0]);
                mma_f16(oacc[2*dp+1], ah,  &vw[2]);
                mma_f16(oacc[2*dp+1], al_, &vw[2]);
            }
        }
    }

    // ---- epilogue: O / l -> fp16 hi/lo at [b][s][h*HD] ----
    const float il0 = 1.0f / l0, il1 = 1.0f / l1;
    const int r0 = q0 + warp * 16 + (lane >> 2);
    const int c0 = h * HD_ + (lane & 3) * 2;
    #pragma unroll
    for (int nt = 0; nt < 16; nt++) {
        float o0 = oacc[nt][0] * il0, o1 = oacc[nt][1] * il0;
        float o2 = oacc[nt][2] * il1, o3 = oacc[nt][3] * il1;
        uint32_t h0, l0r, h1, l1r;
        split2h(o0, o1, h0, l0r);
        split2h(o2, o3, h1, l1r);
        size_t i0 = (size_t)(b * S_ + r0)     * E_ + c0 + nt * 8;
        size_t i1 = (size_t)(b * S_ + r0 + 8) * E_ + c0 + nt * 8;
        *(uint32_t*)(Ohi + i0) = h0; *(uint32_t*)(Olo + i0) = l0r;
        *(uint32_t*)(Ohi + i1) = h1; *(uint32_t*)(Olo + i1) = l1r;
    }
}

// ---------------------------------------------------------------------------
extern "C" void kernel_launch(void* const* d_in, const int* in_sizes, int n_in,
                              void* d_out, int out_size)
{
    const float* x  = (const float*)d_in[0];
    const float* wq = (const float*)d_in[1];
    const float* bq = (const float*)d_in[2];
    const float* wk = (const float*)d_in[3];
    const float* bk = (const float*)d_in[4];
    const float* wv = (const float*)d_in[5];
    const float* bv = (const float*)d_in[6];
    const float* wo = (const float*)d_in[7];
    const float* bo = (const float*)d_in[8];
    float* out = (float*)d_out;

    float* QKVp;
    cudaGetSymbolAddress((void**)&QKVp, g_QKV);
    __half *xhi, *xlo, *aohi, *aolo, *wqT, *wkT, *wvT, *woT;
    __half *qbh, *qbl, *kw, *vw;
    cudaGetSymbolAddress((void**)&xhi,  g_xhi);
    cudaGetSymbolAddress((void**)&xlo,  g_xlo);
    cudaGetSymbolAddress((void**)&aohi, g_aohi);
    cudaGetSymbolAddress((void**)&aolo, g_aolo);
    cudaGetSymbolAddress((void**)&wqT, g_wqT);
    cudaGetSymbolAddress((void**)&wkT, g_wkT);
    cudaGetSymbolAddress((void**)&wvT, g_wvT);
    cudaGetSymbolAddress((void**)&woT, g_woT);
    cudaGetSymbolAddress((void**)&qbh, g_Qbh);
    cudaGetSymbolAddress((void**)&qbl, g_Qbl);
    cudaGetSymbolAddress((void**)&kw,  g_Kw);
    cudaGetSymbolAddress((void**)&vw,  g_Vw);

    cudaFuncSetAttribute(gemm_qkv_kernel,
                         cudaFuncAttributeMaxDynamicSharedMemorySize, GSMEM);
    cudaFuncSetAttribute(gemm_f16x2_kernel,
                         cudaFuncAttributeMaxDynamicSharedMemorySize, GSMEM);
    cudaFuncSetAttribute(flash_mma_kernel,
                         cudaFuncAttributeMaxDynamicSharedMemorySize, FSMEM);

    // conversions
    {
        int n4 = M_ * E_ / 4;
        convert_hilo_h_kernel<<<(n4 + 255) / 256, 256>>>(x, xhi, xlo, n4);
        dim3 blk(32, 8);
        transpose_h_kernel<<<dim3(E_ / 32, E_ / 32), blk>>>(wq, wqT, E_, E_);
        transpose_h_kv_kernel<<<dim3((KVH_ * HD_) / 32, E_ / 32, 2), blk>>>(
            wk, wv, wkT, wvT);
    }

    // Fused QKV projection (N = 3072, M-tile 256)
    gemm_qkv_kernel<<<dim3(NQKV / 128, M_ / 256), 256, GSMEM>>>(
        xhi, xlo, wqT, wkT, wvT, bq, bk, bv, QKVp);

    // RoPE + relayout
    {
        int totq = B_ * S_ * H_ * (HD_ / 2);
        int totk = B_ * S_ * KVH_ * (HD_ / 2);
        rope_split_q_kernel<<<(totq + 255) / 256, 256>>>(QKVp, qbh, qbl);
        rope_k_kernel<<<(totk + 255) / 256, 256>>>(QKVp, kw);
        v_single_kernel<<<(totk + 255) / 256, 256>>>(QKVp, vw);
    }

    // Flash attention (fp16 2-MMA) -> fp16 hi/lo output
    flash_mma_kernel<<<dim3(S_ / 128, H_, B_), 256, FSMEM>>>(
        qbh, qbl, kw, vw, aohi, aolo);

    // wo transpose (deferred; only needed by O-proj)
    {
        dim3 blk(32, 8);
        transpose_h_kernel<<<dim3(E_ / 32, E_ / 32), blk>>>(wo, woT, E_, E_);
    }

    // Output projection -> d_out (M-tile 256)
    gemm_f16x2_kernel<<<dim3(E_ / 128, M_ / 256), 256, GSMEM>>>(
        aohi, aolo, woT, bo, out, M_, E_, E_);
}

// round 16
// speedup vs baseline: 1.5357x; 1.0393x over previous
#include <cuda_runtime.h>
#include <cuda_fp16.h>
#include <math.h>
#include <cstdint>

#define B_   2
#define S_   2048
#define E_   2048
#define H_   16
#define KVH_ 4
#define HD_  128
#define REP_ 4
#define M_   (B_*S_)     // 4096
#define NQKV 3072        // 2048 Q + 512 K + 512 V

// ---------------------------------------------------------------------------
// Scratch (__device__ globals; no allocations allowed)
// ---------------------------------------------------------------------------
__device__ float g_QKV[M_*NQKV];

// fp16 operands: A split hi/lo, weights single fp16
__device__ __half g_xhi[M_*E_],  g_xlo[M_*E_];
__device__ __half g_aohi[M_*E_], g_aolo[M_*E_];
__device__ __half g_wqT[E_*E_];
__device__ __half g_wkT[KVH_*HD_*E_];
__device__ __half g_wvT[KVH_*HD_*E_];
__device__ __half g_woT[E_*E_];

// flash operands: Q hi/lo, K single, V single
__device__ __half g_Qbh[M_*H_*HD_],  g_Qbl[M_*H_*HD_];
__device__ __half g_Kw[M_*KVH_*HD_];
__device__ __half g_Vw[M_*KVH_*HD_];

// ---------------------------------------------------------------------------
// PTX helpers (non-'a' ISA only: mma.sync / ldmatrix / cp.async)
// ---------------------------------------------------------------------------
__device__ __forceinline__ uint32_t smem_to_u32(const void* p) {
    uint32_t a;
    asm("{ .reg .u64 t; cvta.to.shared.u64 t, %1; cvt.u32.u64 %0, t; }" : "=r"(a) : "l"(p));
    return a;
}
__device__ __forceinline__ void cp_async16(uint32_t saddr, const void* gptr) {
    asm volatile("cp.async.cg.shared.global [%0], [%1], 16;\n" :: "r"(saddr), "l"(gptr));
}
#define CP_COMMIT() asm volatile("cp.async.commit_group;\n" ::: "memory")
#define CP_WAIT(n)  asm volatile("cp.async.wait_group %0;\n" :: "n"(n) : "memory")

__device__ __forceinline__ void ldmatrix_x4(uint32_t* r, uint32_t addr) {
    asm volatile("ldmatrix.sync.aligned.m8n8.x4.shared.b16 {%0,%1,%2,%3}, [%4];\n"
                 : "=r"(r[0]), "=r"(r[1]), "=r"(r[2]), "=r"(r[3]) : "r"(addr));
}
__device__ __forceinline__ void ldmatrix_x4_trans(uint32_t* r, uint32_t addr) {
    asm volatile("ldmatrix.sync.aligned.m8n8.x4.trans.shared.b16 {%0,%1,%2,%3}, [%4];\n"
                 : "=r"(r[0]), "=r"(r[1]), "=r"(r[2]), "=r"(r[3]) : "r"(addr));
}
__device__ __forceinline__ void ldmatrix_x2(uint32_t* r, uint32_t addr) {
    asm volatile("ldmatrix.sync.aligned.m8n8.x2.shared.b16 {%0,%1}, [%2];\n"
                 : "=r"(r[0]), "=r"(r[1]) : "r"(addr));
}
__device__ __forceinline__ void mma_f16(float* c, const uint32_t* a, const uint32_t* b) {
    asm volatile(
        "mma.sync.aligned.m16n8k16.row.col.f32.f16.f16.f32 "
        "{%0,%1,%2,%3}, {%4,%5,%6,%7}, {%8,%9}, {%0,%1,%2,%3};\n"
        : "+f"(c[0]), "+f"(c[1]), "+f"(c[2]), "+f"(c[3])
        : "r"(a[0]), "r"(a[1]), "r"(a[2]), "r"(a[3]), "r"(b[0]), "r"(b[1]));
}
// fp16 hi/lo split
__device__ __forceinline__ void split2h(float a, float b, uint32_t& hi, uint32_t& lo) {
    __half ha = __float2half_rn(a), hb = __float2half_rn(b);
    __half la = __float2half_rn(a - __half2float(ha));
    __half lb = __float2half_rn(b - __half2float(hb));
    __half2 h2 = __halves2half2(ha, hb);
    __half2 l2 = __halves2half2(la, lb);
    hi = *(uint32_t*)&h2;
    lo = *(uint32_t*)&l2;
}

// ---------------------------------------------------------------------------
// Conversion kernels
// ---------------------------------------------------------------------------
__global__ void convert_hilo_h_kernel(const float* __restrict__ in,
                                      __half* __restrict__ hi,
                                      __half* __restrict__ lo, int n4)
{
    int i = blockIdx.x * blockDim.x + threadIdx.x;
    if (i >= n4) return;
    float4 v = ((const float4*)in)[i];
    uint32_t h0, l0, h1, l1;
    split2h(v.x, v.y, h0, l0);
    split2h(v.z, v.w, h1, l1);
    uint32_t* ph = (uint32_t*)(hi + 4 * (size_t)i);
    uint32_t* pl = (uint32_t*)(lo + 4 * (size_t)i);
    ph[0] = h0; ph[1] = h1;
    pl[0] = l0; pl[1] = l1;
}

// W[K x N] fp32 -> WT[N x K] single fp16
__global__ void transpose_h_kernel(const float* __restrict__ W,
                                   __half* __restrict__ T,
                                   int K, int N)
{
    __shared__ float tile[32][33];
    int n0 = blockIdx.x * 32, k0 = blockIdx.y * 32;
    int tx = threadIdx.x, ty = threadIdx.y;
    #pragma unroll
    for (int r = 0; r < 4; r++)
        tile[ty + r * 8][tx] = W[(size_t)(k0 + ty + r * 8) * N + n0 + tx];
    __syncthreads();
    #pragma unroll
    for (int r = 0; r < 4; r++) {
        float v = tile[tx][ty + r * 8];
        T[(size_t)(n0 + ty + r * 8) * K + k0 + tx] = __float2half_rn(v);
    }
}

// merged K/V weight transpose (z selects tensor)
__global__ void transpose_h_kv_kernel(const float* __restrict__ Wk,
                                      const float* __restrict__ Wv,
                                      __half* __restrict__ Tk, __half* __restrict__ Tv)
{
    const int K = E_, N = KVH_ * HD_;
    const float* W = blockIdx.z ? Wv : Wk;
    __half* T = blockIdx.z ? Tv : Tk;
    __shared__ float tile[32][33];
    int n0 = blockIdx.x * 32, k0 = blockIdx.y * 32;
    int tx = threadIdx.x, ty = threadIdx.y;
    #pragma unroll
    for (int r = 0; r < 4; r++)
        tile[ty + r * 8][tx] = W[(size_t)(k0 + ty + r * 8) * N + n0 + tx];
    __syncthreads();
    #pragma unroll
    for (int r = 0; r < 4; r++) {
        float v = tile[tx][ty + r * 8];
        T[(size_t)(n0 + ty + r * 8) * K + k0 + tx] = __float2half_rn(v);
    }
}

// Q: RoPE + fp16 hi/lo split, [b][s][h][d] -> [b][h][s][d], pre-scaled
__global__ void rope_split_q_kernel(const float* __restrict__ in,
                                    __half* __restrict__ outh,
                                    __half* __restrict__ outl)
{
    int idx = blockIdx.x * blockDim.x + threadIdx.x;
    int total = B_ * S_ * H_ * (HD_ / 2);
    if (idx >= total) return;
    int d2 = idx & 63;
    int h  = (idx >> 6) % H_;
    int s  = (idx / (64 * H_)) % S_;
    int b  = idx / (64 * H_ * S_);
    float p    = powf(100000.0f, (float)(2 * d2));   // inf for 2*d2 >= 8
    float freq = 1.0f / p;                           // 0 when p == inf
    float ang  = (float)s * freq;
    float sn, cs;
    sincosf(ang, &sn, &cs);
    size_t src = (size_t)(b * S_ + s) * NQKV + h * HD_ + 2 * d2;
    float tr = in[src], ti = in[src + 1];
    const float scale = 0.08838834764831845f;        // 1/sqrt(128)
    float o0 = (tr * cs - ti * sn) * scale;
    float o1 = (tr * sn + ti * cs) * scale;
    uint32_t hi, lo;
    split2h(o0, o1, hi, lo);
    size_t dst = ((size_t)(b * H_ + h) * S_ + s) * HD_ + 2 * d2;
    *(uint32_t*)(outh + dst) = hi;
    *(uint32_t*)(outl + dst) = lo;
}

// K: RoPE + single fp16, [b][s][g][d] -> [b][g][s][d]
__global__ void rope_k_kernel(const float* __restrict__ in,
                              __half* __restrict__ out)
{
    int idx = blockIdx.x * blockDim.x + threadIdx.x;
    int total = B_ * S_ * KVH_ * (HD_ / 2);
    if (idx >= total) return;
    int d2 = idx & 63;
    int g  = (idx >> 6) % KVH_;
    int s  = (idx / (64 * KVH_)) % S_;
    int b  = idx / (64 * KVH_ * S_);
    float p    = powf(100000.0f, (float)(2 * d2));
    float freq = 1.0f / p;
    float ang  = (float)s * freq;
    float sn, cs;
    sincosf(ang, &sn, &cs);
    size_t src = (size_t)(b * S_ + s) * NQKV + 2048 + g * HD_ + 2 * d2;
    float tr = in[src], ti = in[src + 1];
    float o0 = tr * cs - ti * sn;
    float o1 = tr * sn + ti * cs;
    __half2 h2 = __halves2half2(__float2half_rn(o0), __float2half_rn(o1));
    size_t dst = ((size_t)(b * KVH_ + g) * S_ + s) * HD_ + 2 * d2;
    *(uint32_t*)(out + dst) = *(uint32_t*)&h2;
}

// V: single fp16 + relayout
__global__ void v_single_kernel(const float* __restrict__ in,
                                __half* __restrict__ out)
{
    int idx = blockIdx.x * blockDim.x + threadIdx.x;
    int total = B_ * S_ * KVH_ * (HD_ / 2);
    if (idx >= total) return;
    int d2 = idx & 63;
    int g  = (idx >> 6) % KVH_;
    int s  = (idx / (64 * KVH_)) % S_;
    int b  = idx / (64 * KVH_ * S_);
    size_t src = (size_t)(b * S_ + s) * NQKV + 2560 + g * HD_ + 2 * d2;
    float2 v = *(const float2*)(in + src);
    __half2 h2 = __halves2half2(__float2half_rn(v.x), __float2half_rn(v.y));
    size_t dst = ((size_t)(b * KVH_ + g) * S_ + s) * HD_ + 2 * d2;
    *(uint32_t*)(out + dst) = *(uint32_t*)&h2;
}

// ---------------------------------------------------------------------------
// fp16 2-MMA GEMM mainloop: C = (Ah+Al) @ B^T
// 128x128 tile, 8 warps (warp tile 64x32), GBK=64, 2 stages, single sync,
// 108 KB smem -> 2 CTAs/SM = 4 warps/SMSP.
// ---------------------------------------------------------------------------
#define GBK      64
#define GROWB    144                   // 128B data + 16 pad
#define GARR     (128 * GROWB)         // 18432
#define GSTAGE   (3 * GARR)            // 55296 (Ahi, Alo, B)
#define GSTAGES  2
#define GSMEM    (GSTAGES * GSTAGE)    // 110592 -> 2 CTAs/SM

__device__ __forceinline__ void gemm_mainloop(
    const __half* __restrict__ Ahi, const __half* __restrict__ Alo,
    const __half* __restrict__ Bw,
    int rowA0, int rowB0, int K, uint32_t sb, int tid, float acc[4][4][4])
{
    const int wid  = tid >> 5;
    const int lane = tid & 31;
    const int warp_m = wid >> 2;        // 0..1 -> 64 rows each
    const int warp_n = wid & 3;         // 0..3 -> 32 cols each
    const int nchunks = K / GBK;

    const int a_lr = lane & 15;
    const int a_kc = (lane >> 4) * 8;
    const int b_lr = lane & 7;
    const int b_kc = ((lane >> 3) & 3) * 8;

    auto load_stage = [&](int chunk, int stage) {
        const int k0 = chunk * GBK;
        uint32_t s = sb + stage * GSTAGE;
        // each array: 128 rows x 8 c16 = 1024 -> 4/thread
        #pragma unroll
        for (int t = 0; t < 4; t++) {
            int u = t * 256 + tid;
            int r = u >> 3, c = u & 7;
            cp_async16(s + r * GROWB + c * 16,
                       Ahi + (size_t)(rowA0 + r) * K + k0 + c * 8);
            cp_async16(s + GARR + r * GROWB + c * 16,
                       Alo + (size_t)(rowA0 + r) * K + k0 + c * 8);
            cp_async16(s + 2 * GARR + r * GROWB + c * 16,
                       Bw + (size_t)(rowB0 + r) * K + k0 + c * 8);
        }
    };

    load_stage(0, 0);
    CP_COMMIT();

    for (int i = 0; i < nchunks; i++) {
        CP_WAIT(0);
        __syncthreads();

        if (i + 1 < nchunks) load_stage(i + 1, (i + 1) & 1);
        CP_COMMIT();

        const int stage = i & 1;
        const uint32_t sAhi = sb + stage * GSTAGE;
        const uint32_t sAlo = sAhi + GARR;
        const uint32_t sBw  = sAlo + GARR;

        #pragma unroll
        for (int ks = 0; ks < 4; ks++) {
            const int kb = ks * 32;
            uint32_t ah[4][4], al[4][4];
            #pragma unroll
            for (int mt = 0; mt < 4; mt++) {
                uint32_t aoff = (uint32_t)(warp_m * 64 + mt * 16 + a_lr) * GROWB + a_kc * 2 + kb;
                ldmatrix_x4(ah[mt], sAhi + aoff);
                ldmatrix_x4(al[mt], sAlo + aoff);
            }
            uint32_t bw[4][2];
            #pragma unroll
            for (int nt = 0; nt < 4; nt++) {
                uint32_t boff = (uint32_t)(warp_n * 32 + nt * 8 + b_lr) * GROWB + b_kc * 2 + kb;
                ldmatrix_x2(bw[nt], sBw + boff);
            }
            #pragma unroll
            for (int mt = 0; mt < 4; mt++)
                #pragma unroll
                for (int nt = 0; nt < 4; nt++) {
                    mma_f16(acc[mt][nt], ah[mt], bw[nt]);
                    mma_f16(acc[mt][nt], al[mt], bw[nt]);
                }
        }
    }
}

// Generic GEMM (O projection): C[M,N] row stride N, M-tile = 128
__global__ void __launch_bounds__(256, 2)
gemm_f16x2_kernel(const __half* __restrict__ Ahi,
                  const __half* __restrict__ Alo,
                  const __half* __restrict__ Bw,
                  const float* __restrict__ bias,
                  float* __restrict__ C,
                  int M, int N, int K)
{
    extern __shared__ char smem[];
    const uint32_t sb = smem_to_u32(smem);
    const int tid  = threadIdx.x;
    const int wid  = tid >> 5;
    const int lane = tid & 31;
    const int rowA0 = blockIdx.y * 128;
    const int rowB0 = blockIdx.x * 128;

    float acc[4][4][4];
    #pragma unroll
    for (int i = 0; i < 4; i++)
        #pragma unroll
        for (int j = 0; j < 4; j++)
            #pragma unroll
            for (int k = 0; k < 4; k++) acc[i][j][k] = 0.0f;

    gemm_mainloop(Ahi, Alo, Bw, rowA0, rowB0, K, sb, tid, acc);

    const int warp_m = wid >> 2, warp_n = wid & 3;
    #pragma unroll
    for (int mt = 0; mt < 4; mt++)
        #pragma unroll
        for (int nt = 0; nt < 4; nt++) {
            int row = rowA0 + warp_m * 64 + mt * 16 + (lane >> 2);
            int col = rowB0 + warp_n * 32 + nt * 8 + (lane & 3) * 2;
            float2 b01 = *(const float2*)&bias[col];
            float2 o0 = {acc[mt][nt][0] + b01.x, acc[mt][nt][1] + b01.y};
            float2 o1 = {acc[mt][nt][2] + b01.x, acc[mt][nt][3] + b01.y};
            *(float2*)&C[(size_t)row * N + col]       = o0;
            *(float2*)&C[(size_t)(row + 8) * N + col] = o1;
        }
}

// Fused QKV projection: writes into QKV buffer [M][3072], M-tile = 128
__global__ void __launch_bounds__(256, 2)
gemm_qkv_kernel(const __half* __restrict__ xhi,
                const __half* __restrict__ xlo,
                const __half* __restrict__ wqT,
                const __half* __restrict__ wkT,
                const __half* __restrict__ wvT,
                const float* __restrict__ bq, const float* __restrict__ bk,
                const float* __restrict__ bv,
                float* __restrict__ C)
{
    extern __shared__ char smem[];
    const uint32_t sb = smem_to_u32(smem);
    const int tid  = threadIdx.x;
    const int wid  = tid >> 5;
    const int lane = tid & 31;
    const int cCol = blockIdx.x;         // 0..23
    const int rowA0 = blockIdx.y * 128;

    const __half* Bw;
    const float* bias;
    int rowB0;
    if (cCol < 16)      { Bw = wqT; bias = bq; rowB0 = cCol * 128; }
    else if (cCol < 20) { Bw = wkT; bias = bk; rowB0 = (cCol - 16) * 128; }
    else                { Bw = wvT; bias = bv; rowB0 = (cCol - 20) * 128; }

    float acc[4][4][4];
    #pragma unroll
    for (int i = 0; i < 4; i++)
        #pragma unroll
        for (int j = 0; j < 4; j++)
            #pragma unroll
            for (int k = 0; k < 4; k++) acc[i][j][k] = 0.0f;

    gemm_mainloop(xhi, xlo, Bw, rowA0, rowB0, E_, sb, tid, acc);

    const int warp_m = wid >> 2, warp_n = wid & 3;
    #pragma unroll
    for (int mt = 0; mt < 4; mt++)
        #pragma unroll
        for (int nt = 0; nt < 4; nt++) {
            int row  = rowA0 + warp_m * 64 + mt * 16 + (lane >> 2);
            int bcol = rowB0 + warp_n * 32 + nt * 8 + (lane & 3) * 2;
            int col  = cCol * 128 + warp_n * 32 + nt * 8 + (lane & 3) * 2;
            float2 b01 = *(const float2*)&bias[bcol];
            float2 o0 = {acc[mt][nt][0] + b01.x, acc[mt][nt][1] + b01.y};
            float2 o1 = {acc[mt][nt][2] + b01.x, acc[mt][nt][3] + b01.y};
            *(float2*)&C[(size_t)row * NQKV + col]       = o0;
            *(float2*)&C[(size_t)(row + 8) * NQKV + col] = o1;
        }
}

// ---------------------------------------------------------------------------
// Flash attention, fp16 2-MMA both GEMMs (unchanged from round 15).
// ---------------------------------------------------------------------------
#define FROWB  272
#define QARR   (128 * FROWB)        // 34816
#define KARR   (64 * FROWB)         // 17408
#define FSTG   (2 * KARR)           // 34816 (Kw, Vw)
#define FSMEM  (2 * QARR + 2 * FSTG)  // 139264

__global__ void __launch_bounds__(256, 1)
flash_mma_kernel(const __half* __restrict__ Qh, const __half* __restrict__ Ql,
                 const __half* __restrict__ Kw, const __half* __restrict__ Vw,
                 __half* __restrict__ Ohi, __half* __restrict__ Olo)
{
    extern __shared__ char smem[];
    const uint32_t sb = smem_to_u32(smem);
    const int tid  = threadIdx.x;
    const int lane = tid & 31;
    const int warp = tid >> 5;
    const int qt = (int)gridDim.x - 1 - (int)blockIdx.x;   // heavy tiles first
    const int h = blockIdx.y, b = blockIdx.z;
    const int g  = h >> 2;
    const int q0 = qt * 128;
    const int nkv = 2 * qt + 2;

    const uint32_t sQh = sb, sQl = sb + QARR;
    const uint32_t sKV0 = sb + 2 * QARR;

    const size_t qbase  = ((size_t)(b * H_ + h) * S_ + q0) * HD_;
    const size_t kvbase = ((size_t)(b * KVH_ + g) * S_) * HD_;

    const uint32_t q_off = (uint32_t)(lane & 15) * FROWB + (lane >> 4) * 16;
    const uint32_t k_off = (uint32_t)((lane & 7) | ((lane >> 1) & 8)) * FROWB + ((lane >> 3) & 1) * 16;

    #pragma unroll
    for (int t = 0; t < 8; t++) {
        int u = t * 256 + tid;
        int r = u >> 4, cb = (u & 15) * 16, ce = (u & 15) * 8;
        cp_async16(sQh + r * FROWB + cb, Qh + qbase + (size_t)r * HD_ + ce);
        cp_async16(sQl + r * FROWB + cb, Ql + qbase + (size_t)r * HD_ + ce);
    }
    auto load_kv = [&](int kt, int buf) {
        uint32_t s = sKV0 + buf * FSTG;
        const size_t base = kvbase + (size_t)kt * 64 * HD_;
        #pragma unroll
        for (int t = 0; t < 4; t++) {
            int u = t * 256 + tid;
            int r = u >> 4, cb = (u & 15) * 16, ce = (u & 15) * 8;
            size_t go = base + (size_t)r * HD_ + ce;
            uint32_t so = r * FROWB + cb;
            cp_async16(s + so,        Kw + go);
            cp_async16(s + KARR + so, Vw + go);
        }
    };
    load_kv(0, 0);
    CP_COMMIT();

    float oacc[16][4];
    #pragma unroll
    for (int i = 0; i < 16; i++)
        #pragma unroll
        for (int j = 0; j < 4; j++) oacc[i][j] = 0.0f;
    float m0 = -INFINITY, m1 = -INFINITY, l0 = 0.0f, l1 = 0.0f;

    for (int kt = 0; kt < nkv; kt++) {
        __syncthreads();
        if (kt + 1 < nkv) { load_kv(kt + 1, (kt + 1) & 1); CP_COMMIT(); CP_WAIT(1); }
        else              { CP_WAIT(0); }
        __syncthreads();

        const uint32_t st  = sKV0 + (kt & 1) * FSTG;
        const uint32_t sKw = st, sVw = st + KARR;

        float sacc[8][4];
        #pragma unroll
        for (int i = 0; i < 8; i++)
            #pragma unroll
            for (int j = 0; j < 4; j++) sacc[i][j] = 0.0f;

        #pragma unroll
        for (int kk = 0; kk < 8; kk++) {
            const uint32_t kb = kk * 32;
            uint32_t qh[4], ql[4];
            ldmatrix_x4(qh, sQh + (uint32_t)warp * 16 * FROWB + q_off + kb);
            ldmatrix_x4(ql, sQl + (uint32_t)warp * 16 * FROWB + q_off + kb);
            #pragma unroll
            for (int np = 0; np < 4; np++) {
                uint32_t kw[4];
                ldmatrix_x4(kw, sKw + (uint32_t)np * 16 * FROWB + k_off + kb);
                mma_f16(sacc[2*np],   qh, &kw[0]);
                mma_f16(sacc[2*np],   ql, &kw[0]);
                mma_f16(sacc[2*np+1], qh, &kw[2]);
                mma_f16(sacc[2*np+1], ql, &kw[2]);
            }
        }

        if (kt >= 2 * qt) {
            const int rg0 = q0 + warp * 16 + (lane >> 2);
            const int cg0 = kt * 64 + (lane & 3) * 2;
            #pragma unroll
            for (int nt = 0; nt < 8; nt++)
                #pragma unroll
                for (int j = 0; j < 4; j++) {
                    int col = cg0 + nt * 8 + (j & 1);
                    int row = rg0 + (j >> 1) * 8;
                    if (col > row) sacc[nt][j] = -INFINITY;
                }
        }

        float mx0 = -INFINITY, mx1 = -INFINITY;
        #pragma unroll
        for (int nt = 0; nt < 8; nt++) {
            mx0 = fmaxf(mx0, fmaxf(sacc[nt][0], sacc[nt][1]));
            mx1 = fmaxf(mx1, fmaxf(sacc[nt][2], sacc[nt][3]));
        }
        mx0 = fmaxf(mx0, __shfl_xor_sync(0xFFFFFFFF, mx0, 1));
        mx0 = fmaxf(mx0, __shfl_xor_sync(0xFFFFFFFF, mx0, 2));
        mx1 = fmaxf(mx1, __shfl_xor_sync(0xFFFFFFFF, mx1, 1));
        mx1 = fmaxf(mx1, __shfl_xor_sync(0xFFFFFFFF, mx1, 2));
        float mn0 = fmaxf(m0, mx0), mn1 = fmaxf(m1, mx1);
        float al0 = __expf(m0 - mn0), al1 = __expf(m1 - mn1);
        m0 = mn0; m1 = mn1;

        float ps0 = 0.0f, ps1 = 0.0f;
        #pragma unroll
        for (int nt = 0; nt < 8; nt++) {
            float p0 = __expf(sacc[nt][0] - mn0);
            float p1 = __expf(sacc[nt][1] - mn0);
            float p2 = __expf(sacc[nt][2] - mn1);
            float p3 = __expf(sacc[nt][3] - mn1);
            sacc[nt][0] = p0; sacc[nt][1] = p1; sacc[nt][2] = p2; sacc[nt][3] = p3;
            ps0 += p0 + p1; ps1 += p2 + p3;
        }
        ps0 += __shfl_xor_sync(0xFFFFFFFF, ps0, 1);
        ps0 += __shfl_xor_sync(0xFFFFFFFF, ps0, 2);
        ps1 += __shfl_xor_sync(0xFFFFFFFF, ps1, 1);
        ps1 += __shfl_xor_sync(0xFFFFFFFF, ps1, 2);
        l0 = l0 * al0 + ps0;
        l1 = l1 * al1 + ps1;

        #pragma unroll
        for (int i = 0; i < 16; i++) {
            oacc[i][0] *= al0; oacc[i][1] *= al0;
            oacc[i][2] *= al1; oacc[i][3] *= al1;
        }

        #pragma unroll
        for (int tk = 0; tk < 4; tk++) {
            uint32_t ah[4], al_[4];
            split2h(sacc[2*tk][0],   sacc[2*tk][1],   ah[0], al_[0]);
            split2h(sacc[2*tk][2],   sacc[2*tk][3],   ah[1], al_[1]);
            split2h(sacc[2*tk+1][0], sacc[2*tk+1][1], ah[2], al_[2]);
            split2h(sacc[2*tk+1][2], sacc[2*tk+1][3], ah[3], al_[3]);
            #pragma unroll
            for (int dp = 0; dp < 8; dp++) {
                uint32_t vw[4];
                const uint32_t vo = (uint32_t)tk * 16 * FROWB + q_off + dp * 32;
                ldmatrix_x4_trans(vw, sVw + vo);
                mma_f16(oacc[2*dp],   ah,  &vw[0]);
                mma_f16(oacc[2*dp],   al_, &vw[0]);
                mma_f16(oacc[2*dp+1], ah,  &vw[2]);
                mma_f16(oacc[2*dp+1], al_, &vw[2]);
            }
        }
    }

    const float il0 = 1.0f / l0, il1 = 1.0f / l1;
    const int r0 = q0 + warp * 16 + (lane >> 2);
    const int c0 = h * HD_ + (lane & 3) * 2;
    #pragma unroll
    for (int nt = 0; nt < 16; nt++) {
        float o0 = oacc[nt][0] * il0, o1 = oacc[nt][1] * il0;
        float o2 = oacc[nt][2] * il1, o3 = oacc[nt][3] * il1;
        uint32_t h0, l0r, h1, l1r;
        split2h(o0, o1, h0, l0r);
        split2h(o2, o3, h1, l1r);
        size_t i0 = (size_t)(b * S_ + r0)     * E_ + c0 + nt * 8;
        size_t i1 = (size_t)(b * S_ + r0 + 8) * E_ + c0 + nt * 8;
        *(uint32_t*)(Ohi + i0) = h0; *(uint32_t*)(Olo + i0) = l0r;
        *(uint32_t*)(Ohi + i1) = h1; *(uint32_t*)(Olo + i1) = l1r;
    }
}

// ---------------------------------------------------------------------------
extern "C" void kernel_launch(void* const* d_in, const int* in_sizes, int n_in,
                              void* d_out, int out_size)
{
    const float* x  = (const float*)d_in[0];
    const float* wq = (const float*)d_in[1];
    const float* bq = (const float*)d_in[2];
    const float* wk = (const float*)d_in[3];
    const float* bk = (const float*)d_in[4];
    const float* wv = (const float*)d_in[5];
    const float* bv = (const float*)d_in[6];
    const float* wo = (const float*)d_in[7];
    const float* bo = (const float*)d_in[8];
    float* out = (float*)d_out;

    float* QKVp;
    cudaGetSymbolAddress((void**)&QKVp, g_QKV);
    __half *xhi, *xlo, *aohi, *aolo, *wqT, *wkT, *wvT, *woT;
    __half *qbh, *qbl, *kw, *vw;
    cudaGetSymbolAddress((void**)&xhi,  g_xhi);
    cudaGetSymbolAddress((void**)&xlo,  g_xlo);
    cudaGetSymbolAddress((void**)&aohi, g_aohi);
    cudaGetSymbolAddress((void**)&aolo, g_aolo);
    cudaGetSymbolAddress((void**)&wqT, g_wqT);
    cudaGetSymbolAddress((void**)&wkT, g_wkT);
    cudaGetSymbolAddress((void**)&wvT, g_wvT);
    cudaGetSymbolAddress((void**)&woT, g_woT);
    cudaGetSymbolAddress((void**)&qbh, g_Qbh);
    cudaGetSymbolAddress((void**)&qbl, g_Qbl);
    cudaGetSymbolAddress((void**)&kw,  g_Kw);
    cudaGetSymbolAddress((void**)&vw,  g_Vw);

    cudaFuncSetAttribute(gemm_qkv_kernel,
                         cudaFuncAttributeMaxDynamicSharedMemorySize, GSMEM);
    cudaFuncSetAttribute(gemm_f16x2_kernel,
                         cudaFuncAttributeMaxDynamicSharedMemorySize, GSMEM);
    cudaFuncSetAttribute(flash_mma_kernel,
                         cudaFuncAttributeMaxDynamicSharedMemorySize, FSMEM);

    // conversions
    {
        int n4 = M_ * E_ / 4;
        convert_hilo_h_kernel<<<(n4 + 255) / 256, 256>>>(x, xhi, xlo, n4);
        dim3 blk(32, 8);
        transpose_h_kernel<<<dim3(E_ / 32, E_ / 32), blk>>>(wq, wqT, E_, E_);
        transpose_h_kv_kernel<<<dim3((KVH_ * HD_) / 32, E_ / 32, 2), blk>>>(
            wk, wv, wkT, wvT);
    }

    // Fused QKV projection (N = 3072, M-tile 128)
    gemm_qkv_kernel<<<dim3(NQKV / 128, M_ / 128), 256, GSMEM>>>(
        xhi, xlo, wqT, wkT, wvT, bq, bk, bv, QKVp);

    // RoPE + relayout
    {
        int totq = B_ * S_ * H_ * (HD_ / 2);
        int totk = B_ * S_ * KVH_ * (HD_ / 2);
        rope_split_q_kernel<<<(totq + 255) / 256, 256>>>(QKVp, qbh, qbl);
        rope_k_kernel<<<(totk + 255) / 256, 256>>>(QKVp, kw);
        v_single_kernel<<<(totk + 255) / 256, 256>>>(QKVp, vw);
    }

    // Flash attention (fp16 2-MMA) -> fp16 hi/lo output
    flash_mma_kernel<<<dim3(S_ / 128, H_, B_), 256, FSMEM>>>(
        qbh, qbl, kw, vw, aohi, aolo);

    // wo transpose (deferred; only needed by O-proj)
    {
        dim3 blk(32, 8);
        transpose_h_kernel<<<dim3(E_ / 32, E_ / 32), blk>>>(wo, woT, E_, E_);
    }

    // Output projection -> d_out (M-tile 128)
    gemm_f16x2_kernel<<<dim3(E_ / 128, M_ / 128), 256, GSMEM>>>(
        aohi, aolo, woT, bo, out, M_, E_, E_);
}

// round 17
// speedup vs baseline: 1.7111x; 1.1142x over previous
#include <cuda_runtime.h>
#include <cuda_fp16.h>
#include <math.h>
#include <cstdint>

#define B_   2
#define S_   2048
#define E_   2048
#define H_   16
#define KVH_ 4
#define HD_  128
#define REP_ 4
#define M_   (B_*S_)     // 4096
#define NQKV 3072        // 2048 Q + 512 K + 512 V

// ---------------------------------------------------------------------------
// Scratch (__device__ globals; no allocations allowed)
// ---------------------------------------------------------------------------
__device__ float g_QKV[M_*NQKV];

// fp16 operands: A split hi/lo, weights single fp16
__device__ __half g_xhi[M_*E_],  g_xlo[M_*E_];
__device__ __half g_aohi[M_*E_], g_aolo[M_*E_];
__device__ __half g_wqT[E_*E_];
__device__ __half g_wkT[KVH_*HD_*E_];
__device__ __half g_wvT[KVH_*HD_*E_];
__device__ __half g_woT[E_*E_];

// flash operands (all single fp16): Q, K, V
__device__ __half g_Qw[M_*H_*HD_];
__device__ __half g_Kw[M_*KVH_*HD_];
__device__ __half g_Vw[M_*KVH_*HD_];

// ---------------------------------------------------------------------------
// PTX helpers (non-'a' ISA only: mma.sync / ldmatrix / cp.async)
// ---------------------------------------------------------------------------
__device__ __forceinline__ uint32_t smem_to_u32(const void* p) {
    uint32_t a;
    asm("{ .reg .u64 t; cvta.to.shared.u64 t, %1; cvt.u32.u64 %0, t; }" : "=r"(a) : "l"(p));
    return a;
}
__device__ __forceinline__ void cp_async16(uint32_t saddr, const void* gptr) {
    asm volatile("cp.async.cg.shared.global [%0], [%1], 16;\n" :: "r"(saddr), "l"(gptr));
}
#define CP_COMMIT() asm volatile("cp.async.commit_group;\n" ::: "memory")
#define CP_WAIT(n)  asm volatile("cp.async.wait_group %0;\n" :: "n"(n) : "memory")

__device__ __forceinline__ void ldmatrix_x4(uint32_t* r, uint32_t addr) {
    asm volatile("ldmatrix.sync.aligned.m8n8.x4.shared.b16 {%0,%1,%2,%3}, [%4];\n"
                 : "=r"(r[0]), "=r"(r[1]), "=r"(r[2]), "=r"(r[3]) : "r"(addr));
}
__device__ __forceinline__ void ldmatrix_x4_trans(uint32_t* r, uint32_t addr) {
    asm volatile("ldmatrix.sync.aligned.m8n8.x4.trans.shared.b16 {%0,%1,%2,%3}, [%4];\n"
                 : "=r"(r[0]), "=r"(r[1]), "=r"(r[2]), "=r"(r[3]) : "r"(addr));
}
__device__ __forceinline__ void ldmatrix_x2(uint32_t* r, uint32_t addr) {
    asm volatile("ldmatrix.sync.aligned.m8n8.x2.shared.b16 {%0,%1}, [%2];\n"
                 : "=r"(r[0]), "=r"(r[1]) : "r"(addr));
}
__device__ __forceinline__ void mma_f16(float* c, const uint32_t* a, const uint32_t* b) {
    asm volatile(
        "mma.sync.aligned.m16n8k16.row.col.f32.f16.f16.f32 "
        "{%0,%1,%2,%3}, {%4,%5,%6,%7}, {%8,%9}, {%0,%1,%2,%3};\n"
        : "+f"(c[0]), "+f"(c[1]), "+f"(c[2]), "+f"(c[3])
        : "r"(a[0]), "r"(a[1]), "r"(a[2]), "r"(a[3]), "r"(b[0]), "r"(b[1]));
}
// fp16 hi/lo split
__device__ __forceinline__ void split2h(float a, float b, uint32_t& hi, uint32_t& lo) {
    __half ha = __float2half_rn(a), hb = __float2half_rn(b);
    __half la = __float2half_rn(a - __half2float(ha));
    __half lb = __float2half_rn(b - __half2float(hb));
    __half2 h2 = __halves2half2(ha, hb);
    __half2 l2 = __halves2half2(la, lb);
    hi = *(uint32_t*)&h2;
    lo = *(uint32_t*)&l2;
}
// fp16 single pack
__device__ __forceinline__ uint32_t pack2h(float a, float b) {
    __half2 h2 = __halves2half2(__float2half_rn(a), __float2half_rn(b));
    return *(uint32_t*)&h2;
}

// ---------------------------------------------------------------------------
// Conversion kernels
// ---------------------------------------------------------------------------
__global__ void convert_hilo_h_kernel(const float* __restrict__ in,
                                      __half* __restrict__ hi,
                                      __half* __restrict__ lo, int n4)
{
    int i = blockIdx.x * blockDim.x + threadIdx.x;
    if (i >= n4) return;
    float4 v = ((const float4*)in)[i];
    uint32_t h0, l0, h1, l1;
    split2h(v.x, v.y, h0, l0);
    split2h(v.z, v.w, h1, l1);
    uint32_t* ph = (uint32_t*)(hi + 4 * (size_t)i);
    uint32_t* pl = (uint32_t*)(lo + 4 * (size_t)i);
    ph[0] = h0; ph[1] = h1;
    pl[0] = l0; pl[1] = l1;
}

// W[K x N] fp32 -> WT[N x K] single fp16
__global__ void transpose_h_kernel(const float* __restrict__ W,
                                   __half* __restrict__ T,
                                   int K, int N)
{
    __shared__ float tile[32][33];
    int n0 = blockIdx.x * 32, k0 = blockIdx.y * 32;
    int tx = threadIdx.x, ty = threadIdx.y;
    #pragma unroll
    for (int r = 0; r < 4; r++)
        tile[ty + r * 8][tx] = W[(size_t)(k0 + ty + r * 8) * N + n0 + tx];
    __syncthreads();
    #pragma unroll
    for (int r = 0; r < 4; r++) {
        float v = tile[tx][ty + r * 8];
        T[(size_t)(n0 + ty + r * 8) * K + k0 + tx] = __float2half_rn(v);
    }
}

// merged K/V weight transpose (z selects tensor)
__global__ void transpose_h_kv_kernel(const float* __restrict__ Wk,
                                      const float* __restrict__ Wv,
                                      __half* __restrict__ Tk, __half* __restrict__ Tv)
{
    const int K = E_, N = KVH_ * HD_;
    const float* W = blockIdx.z ? Wv : Wk;
    __half* T = blockIdx.z ? Tv : Tk;
    __shared__ float tile[32][33];
    int n0 = blockIdx.x * 32, k0 = blockIdx.y * 32;
    int tx = threadIdx.x, ty = threadIdx.y;
    #pragma unroll
    for (int r = 0; r < 4; r++)
        tile[ty + r * 8][tx] = W[(size_t)(k0 + ty + r * 8) * N + n0 + tx];
    __syncthreads();
    #pragma unroll
    for (int r = 0; r < 4; r++) {
        float v = tile[tx][ty + r * 8];
        T[(size_t)(n0 + ty + r * 8) * K + k0 + tx] = __float2half_rn(v);
    }
}

// Q: RoPE + single fp16, [b][s][h][d] -> [b][h][s][d], pre-scaled
__global__ void rope_q_kernel(const float* __restrict__ in,
                              __half* __restrict__ out)
{
    int idx = blockIdx.x * blockDim.x + threadIdx.x;
    int total = B_ * S_ * H_ * (HD_ / 2);
    if (idx >= total) return;
    int d2 = idx & 63;
    int h  = (idx >> 6) % H_;
    int s  = (idx / (64 * H_)) % S_;
    int b  = idx / (64 * H_ * S_);
    float p    = powf(100000.0f, (float)(2 * d2));   // inf for 2*d2 >= 8
    float freq = 1.0f / p;                           // 0 when p == inf
    float ang  = (float)s * freq;
    float sn, cs;
    sincosf(ang, &sn, &cs);
    size_t src = (size_t)(b * S_ + s) * NQKV + h * HD_ + 2 * d2;
    float tr = in[src], ti = in[src + 1];
    const float scale = 0.08838834764831845f;        // 1/sqrt(128)
    float o0 = (tr * cs - ti * sn) * scale;
    float o1 = (tr * sn + ti * cs) * scale;
    size_t dst = ((size_t)(b * H_ + h) * S_ + s) * HD_ + 2 * d2;
    *(uint32_t*)(out + dst) = pack2h(o0, o1);
}

// K: RoPE + single fp16, [b][s][g][d] -> [b][g][s][d]
__global__ void rope_k_kernel(const float* __restrict__ in,
                              __half* __restrict__ out)
{
    int idx = blockIdx.x * blockDim.x + threadIdx.x;
    int total = B_ * S_ * KVH_ * (HD_ / 2);
    if (idx >= total) return;
    int d2 = idx & 63;
    int g  = (idx >> 6) % KVH_;
    int s  = (idx / (64 * KVH_)) % S_;
    int b  = idx / (64 * KVH_ * S_);
    float p    = powf(100000.0f, (float)(2 * d2));
    float freq = 1.0f / p;
    float ang  = (float)s * freq;
    float sn, cs;
    sincosf(ang, &sn, &cs);
    size_t src = (size_t)(b * S_ + s) * NQKV + 2048 + g * HD_ + 2 * d2;
    float tr = in[src], ti = in[src + 1];
    float o0 = tr * cs - ti * sn;
    float o1 = tr * sn + ti * cs;
    size_t dst = ((size_t)(b * KVH_ + g) * S_ + s) * HD_ + 2 * d2;
    *(uint32_t*)(out + dst) = pack2h(o0, o1);
}

// V: single fp16 + relayout
__global__ void v_single_kernel(const float* __restrict__ in,
                                __half* __restrict__ out)
{
    int idx = blockIdx.x * blockDim.x + threadIdx.x;
    int total = B_ * S_ * KVH_ * (HD_ / 2);
    if (idx >= total) return;
    int d2 = idx & 63;
    int g  = (idx >> 6) % KVH_;
    int s  = (idx / (64 * KVH_)) % S_;
    int b  = idx / (64 * KVH_ * S_);
    size_t src = (size_t)(b * S_ + s) * NQKV + 2560 + g * HD_ + 2 * d2;
    float2 v = *(const float2*)(in + src);
    size_t dst = ((size_t)(b * KVH_ + g) * S_ + s) * HD_ + 2 * d2;
    *(uint32_t*)(out + dst) = pack2h(v.x, v.y);
}

// ---------------------------------------------------------------------------
// fp16 2-MMA GEMM mainloop (unchanged from round 16):
// 128x128 tile, 8 warps, GBK=64, 2 stages, single sync, 2 CTAs/SM.
// ---------------------------------------------------------------------------
#define GBK      64
#define GROWB    144                   // 128B data + 16 pad
#define GARR     (128 * GROWB)         // 18432
#define GSTAGE   (3 * GARR)            // 55296 (Ahi, Alo, B)
#define GSTAGES  2
#define GSMEM    (GSTAGES * GSTAGE)    // 110592 -> 2 CTAs/SM

__device__ __forceinline__ void gemm_mainloop(
    const __half* __restrict__ Ahi, const __half* __restrict__ Alo,
    const __half* __restrict__ Bw,
    int rowA0, int rowB0, int K, uint32_t sb, int tid, float acc[4][4][4])
{
    const int wid  = tid >> 5;
    const int lane = tid & 31;
    const int warp_m = wid >> 2;
    const int warp_n = wid & 3;
    const int nchunks = K / GBK;

    const int a_lr = lane & 15;
    const int a_kc = (lane >> 4) * 8;
    const int b_lr = lane & 7;
    const int b_kc = ((lane >> 3) & 3) * 8;

    auto load_stage = [&](int chunk, int stage) {
        const int k0 = chunk * GBK;
        uint32_t s = sb + stage * GSTAGE;
        #pragma unroll
        for (int t = 0; t < 4; t++) {
            int u = t * 256 + tid;
            int r = u >> 3, c = u & 7;
            cp_async16(s + r * GROWB + c * 16,
                       Ahi + (size_t)(rowA0 + r) * K + k0 + c * 8);
            cp_async16(s + GARR + r * GROWB + c * 16,
                       Alo + (size_t)(rowA0 + r) * K + k0 + c * 8);
            cp_async16(s + 2 * GARR + r * GROWB + c * 16,
                       Bw + (size_t)(rowB0 + r) * K + k0 + c * 8);
        }
    };

    load_stage(0, 0);
    CP_COMMIT();

    for (int i = 0; i < nchunks; i++) {
        CP_WAIT(0);
        __syncthreads();

        if (i + 1 < nchunks) load_stage(i + 1, (i + 1) & 1);
        CP_COMMIT();

        const int stage = i & 1;
        const uint32_t sAhi = sb + stage * GSTAGE;
        const uint32_t sAlo = sAhi + GARR;
        const uint32_t sBw  = sAlo + GARR;

        #pragma unroll
        for (int ks = 0; ks < 4; ks++) {
            const int kb = ks * 32;
            uint32_t ah[4][4], al[4][4];
            #pragma unroll
            for (int mt = 0; mt < 4; mt++) {
                uint32_t aoff = (uint32_t)(warp_m * 64 + mt * 16 + a_lr) * GROWB + a_kc * 2 + kb;
                ldmatrix_x4(ah[mt], sAhi + aoff);
                ldmatrix_x4(al[mt], sAlo + aoff);
            }
            uint32_t bw[4][2];
            #pragma unroll
            for (int nt = 0; nt < 4; nt++) {
                uint32_t boff = (uint32_t)(warp_n * 32 + nt * 8 + b_lr) * GROWB + b_kc * 2 + kb;
                ldmatrix_x2(bw[nt], sBw + boff);
            }
            #pragma unroll
            for (int mt = 0; mt < 4; mt++)
                #pragma unroll
                for (int nt = 0; nt < 4; nt++) {
                    mma_f16(acc[mt][nt], ah[mt], bw[nt]);
                    mma_f16(acc[mt][nt], al[mt], bw[nt]);
                }
        }
    }
}

// Generic GEMM (O projection): C[M,N] row stride N, M-tile = 128
__global__ void __launch_bounds__(256, 2)
gemm_f16x2_kernel(const __half* __restrict__ Ahi,
                  const __half* __restrict__ Alo,
                  const __half* __restrict__ Bw,
                  const float* __restrict__ bias,
                  float* __restrict__ C,
                  int M, int N, int K)
{
    extern __shared__ char smem[];
    const uint32_t sb = smem_to_u32(smem);
    const int tid  = threadIdx.x;
    const int wid  = tid >> 5;
    const int lane = tid & 31;
    const int rowA0 = blockIdx.y * 128;
    const int rowB0 = blockIdx.x * 128;

    float acc[4][4][4];
    #pragma unroll
    for (int i = 0; i < 4; i++)
        #pragma unroll
        for (int j = 0; j < 4; j++)
            #pragma unroll
            for (int k = 0; k < 4; k++) acc[i][j][k] = 0.0f;

    gemm_mainloop(Ahi, Alo, Bw, rowA0, rowB0, K, sb, tid, acc);

    const int warp_m = wid >> 2, warp_n = wid & 3;
    #pragma unroll
    for (int mt = 0; mt < 4; mt++)
        #pragma unroll
        for (int nt = 0; nt < 4; nt++) {
            int row = rowA0 + warp_m * 64 + mt * 16 + (lane >> 2);
            int col = rowB0 + warp_n * 32 + nt * 8 + (lane & 3) * 2;
            float2 b01 = *(const float2*)&bias[col];
            float2 o0 = {acc[mt][nt][0] + b01.x, acc[mt][nt][1] + b01.y};
            float2 o1 = {acc[mt][nt][2] + b01.x, acc[mt][nt][3] + b01.y};
            *(float2*)&C[(size_t)row * N + col]       = o0;
            *(float2*)&C[(size_t)(row + 8) * N + col] = o1;
        }
}

// Fused QKV projection: writes into QKV buffer [M][3072], M-tile = 128
__global__ void __launch_bounds__(256, 2)
gemm_qkv_kernel(const __half* __restrict__ xhi,
                const __half* __restrict__ xlo,
                const __half* __restrict__ wqT,
                const __half* __restrict__ wkT,
                const __half* __restrict__ wvT,
                const float* __restrict__ bq, const float* __restrict__ bk,
                const float* __restrict__ bv,
                float* __restrict__ C)
{
    extern __shared__ char smem[];
    const uint32_t sb = smem_to_u32(smem);
    const int tid  = threadIdx.x;
    const int wid  = tid >> 5;
    const int lane = tid & 31;
    const int cCol = blockIdx.x;         // 0..23
    const int rowA0 = blockIdx.y * 128;

    const __half* Bw;
    const float* bias;
    int rowB0;
    if (cCol < 16)      { Bw = wqT; bias = bq; rowB0 = cCol * 128; }
    else if (cCol < 20) { Bw = wkT; bias = bk; rowB0 = (cCol - 16) * 128; }
    else                { Bw = wvT; bias = bv; rowB0 = (cCol - 20) * 128; }

    float acc[4][4][4];
    #pragma unroll
    for (int i = 0; i < 4; i++)
        #pragma unroll
        for (int j = 0; j < 4; j++)
            #pragma unroll
            for (int k = 0; k < 4; k++) acc[i][j][k] = 0.0f;

    gemm_mainloop(xhi, xlo, Bw, rowA0, rowB0, E_, sb, tid, acc);

    const int warp_m = wid >> 2, warp_n = wid & 3;
    #pragma unroll
    for (int mt = 0; mt < 4; mt++)
        #pragma unroll
        for (int nt = 0; nt < 4; nt++) {
            int row  = rowA0 + warp_m * 64 + mt * 16 + (lane >> 2);
            int bcol = rowB0 + warp_n * 32 + nt * 8 + (lane & 3) * 2;
            int col  = cCol * 128 + warp_n * 32 + nt * 8 + (lane & 3) * 2;
            float2 b01 = *(const float2*)&bias[bcol];
            float2 o0 = {acc[mt][nt][0] + b01.x, acc[mt][nt][1] + b01.y};
            float2 o1 = {acc[mt][nt][2] + b01.x, acc[mt][nt][3] + b01.y};
            *(float2*)&C[(size_t)row * NQKV + col]       = o0;
            *(float2*)&C[(size_t)(row + 8) * NQKV + col] = o1;
        }
}

// ---------------------------------------------------------------------------
// Flash attention, plain fp16 1-MMA per product. Br=128, Bc=64, 8 warps.
// Q single fp16 (pre-scaled), K single, P single, V single.
// ---------------------------------------------------------------------------
#define FROWB  272
#define QARR   (128 * FROWB)        // 34816 (single Q)
#define KARR   (64 * FROWB)         // 17408
#define FSTG   (2 * KARR)           // 34816 (Kw, Vw)
#define FSMEM  (QARR + 2 * FSTG)    // 104448

__global__ void __launch_bounds__(256, 1)
flash_mma_kernel(const __half* __restrict__ Qw,
                 const __half* __restrict__ Kw, const __half* __restrict__ Vw,
                 __half* __restrict__ Ohi, __half* __restrict__ Olo)
{
    extern __shared__ char smem[];
    const uint32_t sb = smem_to_u32(smem);
    const int tid  = threadIdx.x;
    const int lane = tid & 31;
    const int warp = tid >> 5;
    const int qt = (int)gridDim.x - 1 - (int)blockIdx.x;   // heavy tiles first
    const int h = blockIdx.y, b = blockIdx.z;
    const int g  = h >> 2;
    const int q0 = qt * 128;
    const int nkv = 2 * qt + 2;

    const uint32_t sQw = sb;
    const uint32_t sKV0 = sb + QARR;

    const size_t qbase  = ((size_t)(b * H_ + h) * S_ + q0) * HD_;
    const size_t kvbase = ((size_t)(b * KVH_ + g) * S_) * HD_;

    const uint32_t q_off = (uint32_t)(lane & 15) * FROWB + (lane >> 4) * 16;
    const uint32_t k_off = (uint32_t)((lane & 7) | ((lane >> 1) & 8)) * FROWB + ((lane >> 3) & 1) * 16;

    // -- prologue: Q tile (128 rows, single) + KV stage 0 --
    #pragma unroll
    for (int t = 0; t < 8; t++) {
        int u = t * 256 + tid;                  // 0..2047
        int r = u >> 4, cb = (u & 15) * 16, ce = (u & 15) * 8;
        cp_async16(sQw + r * FROWB + cb, Qw + qbase + (size_t)r * HD_ + ce);
    }
    auto load_kv = [&](int kt, int buf) {
        uint32_t s = sKV0 + buf * FSTG;
        const size_t base = kvbase + (size_t)kt * 64 * HD_;
        #pragma unroll
        for (int t = 0; t < 4; t++) {
            int u = t * 256 + tid;              // 0..1023
            int r = u >> 4, cb = (u & 15) * 16, ce = (u & 15) * 8;
            size_t go = base + (size_t)r * HD_ + ce;
            uint32_t so = r * FROWB + cb;
            cp_async16(s + so,        Kw + go);
            cp_async16(s + KARR + so, Vw + go);
        }
    };
    load_kv(0, 0);
    CP_COMMIT();

    float oacc[16][4];
    #pragma unroll
    for (int i = 0; i < 16; i++)
        #pragma unroll
        for (int j = 0; j < 4; j++) oacc[i][j] = 0.0f;
    float m0 = -INFINITY, m1 = -INFINITY, l0 = 0.0f, l1 = 0.0f;

    for (int kt = 0; kt < nkv; kt++) {
        __syncthreads();
        if (kt + 1 < nkv) { load_kv(kt + 1, (kt + 1) & 1); CP_COMMIT(); CP_WAIT(1); }
        else              { CP_WAIT(0); }
        __syncthreads();

        const uint32_t st  = sKV0 + (kt & 1) * FSTG;
        const uint32_t sKw = st, sVw = st + KARR;

        // ---- S = Q K^T (single fp16 x single fp16) ----
        float sacc[8][4];
        #pragma unroll
        for (int i = 0; i < 8; i++)
            #pragma unroll
            for (int j = 0; j < 4; j++) sacc[i][j] = 0.0f;

        #pragma unroll
        for (int kk = 0; kk < 8; kk++) {
            const uint32_t kb = kk * 32;
            uint32_t qh[4];
            ldmatrix_x4(qh, sQw + (uint32_t)warp * 16 * FROWB + q_off + kb);
            #pragma unroll
            for (int np = 0; np < 4; np++) {
                uint32_t kw[4];
                ldmatrix_x4(kw, sKw + (uint32_t)np * 16 * FROWB + k_off + kb);
                mma_f16(sacc[2*np],   qh, &kw[0]);
                mma_f16(sacc[2*np+1], qh, &kw[2]);
            }
        }

        // ---- causal mask (diagonal region spans kv chunks 2qt, 2qt+1) ----
        if (kt >= 2 * qt) {
            const int rg0 = q0 + warp * 16 + (lane >> 2);
            const int cg0 = kt * 64 + (lane & 3) * 2;
            #pragma unroll
            for (int nt = 0; nt < 8; nt++)
                #pragma unroll
                for (int j = 0; j < 4; j++) {
                    int col = cg0 + nt * 8 + (j & 1);
                    int row = rg0 + (j >> 1) * 8;
                    if (col > row) sacc[nt][j] = -INFINITY;
                }
        }

        // ---- online softmax ----
        float mx0 = -INFINITY, mx1 = -INFINITY;
        #pragma unroll
        for (int nt = 0; nt < 8; nt++) {
            mx0 = fmaxf(mx0, fmaxf(sacc[nt][0], sacc[nt][1]));
            mx1 = fmaxf(mx1, fmaxf(sacc[nt][2], sacc[nt][3]));
        }
        mx0 = fmaxf(mx0, __shfl_xor_sync(0xFFFFFFFF, mx0, 1));
        mx0 = fmaxf(mx0, __shfl_xor_sync(0xFFFFFFFF, mx0, 2));
        mx1 = fmaxf(mx1, __shfl_xor_sync(0xFFFFFFFF, mx1, 1));
        mx1 = fmaxf(mx1, __shfl_xor_sync(0xFFFFFFFF, mx1, 2));
        float mn0 = fmaxf(m0, mx0), mn1 = fmaxf(m1, mx1);
        float al0 = __expf(m0 - mn0), al1 = __expf(m1 - mn1);
        m0 = mn0; m1 = mn1;

        float ps0 = 0.0f, ps1 = 0.0f;
        #pragma unroll
        for (int nt = 0; nt < 8; nt++) {
            float p0 = __expf(sacc[nt][0] - mn0);
            float p1 = __expf(sacc[nt][1] - mn0);
            float p2 = __expf(sacc[nt][2] - mn1);
            float p3 = __expf(sacc[nt][3] - mn1);
            sacc[nt][0] = p0; sacc[nt][1] = p1; sacc[nt][2] = p2; sacc[nt][3] = p3;
            ps0 += p0 + p1; ps1 += p2 + p3;
        }
        ps0 += __shfl_xor_sync(0xFFFFFFFF, ps0, 1);
        ps0 += __shfl_xor_sync(0xFFFFFFFF, ps0, 2);
        ps1 += __shfl_xor_sync(0xFFFFFFFF, ps1, 1);
        ps1 += __shfl_xor_sync(0xFFFFFFFF, ps1, 2);
        l0 = l0 * al0 + ps0;
        l1 = l1 * al1 + ps1;

        #pragma unroll
        for (int i = 0; i < 16; i++) {
            oacc[i][0] *= al0; oacc[i][1] *= al0;
            oacc[i][2] *= al1; oacc[i][3] *= al1;
        }

        // ---- O += P V (P single fp16 x V single fp16) ----
        #pragma unroll
        for (int tk = 0; tk < 4; tk++) {
            uint32_t ah[4];
            ah[0] = pack2h(sacc[2*tk][0],   sacc[2*tk][1]);
            ah[1] = pack2h(sacc[2*tk][2],   sacc[2*tk][3]);
            ah[2] = pack2h(sacc[2*tk+1][0], sacc[2*tk+1][1]);
            ah[3] = pack2h(sacc[2*tk+1][2], sacc[2*tk+1][3]);
            #pragma unroll
            for (int dp = 0; dp < 8; dp++) {
                uint32_t vw[4];
                const uint32_t vo = (uint32_t)tk * 16 * FROWB + q_off + dp * 32;
                ldmatrix_x4_trans(vw, sVw + vo);
                mma_f16(oacc[2*dp],   ah, &vw[0]);
                mma_f16(oacc[2*dp+1], ah, &vw[2]);
            }
        }
    }

    // ---- epilogue: O / l -> fp16 hi/lo at [b][s][h*HD] ----
    const float il0 = 1.0f / l0, il1 = 1.0f / l1;
    const int r0 = q0 + warp * 16 + (lane >> 2);
    const int c0 = h * HD_ + (lane & 3) * 2;
    #pragma unroll
    for (int nt = 0; nt < 16; nt++) {
        float o0 = oacc[nt][0] * il0, o1 = oacc[nt][1] * il0;
        float o2 = oacc[nt][2] * il1, o3 = oacc[nt][3] * il1;
        uint32_t h0, l0r, h1, l1r;
        split2h(o0, o1, h0, l0r);
        split2h(o2, o3, h1, l1r);
        size_t i0 = (size_t)(b * S_ + r0)     * E_ + c0 + nt * 8;
        size_t i1 = (size_t)(b * S_ + r0 + 8) * E_ + c0 + nt * 8;
        *(uint32_t*)(Ohi + i0) = h0; *(uint32_t*)(Olo + i0) = l0r;
        *(uint32_t*)(Ohi + i1) = h1; *(uint32_t*)(Olo + i1) = l1r;
    }
}

// ---------------------------------------------------------------------------
extern "C" void kernel_launch(void* const* d_in, const int* in_sizes, int n_in,
                              void* d_out, int out_size)
{
    const float* x  = (const float*)d_in[0];
    const float* wq = (const float*)d_in[1];
    const float* bq = (const float*)d_in[2];
    const float* wk = (const float*)d_in[3];
    const float* bk = (const float*)d_in[4];
    const float* wv = (const float*)d_in[5];
    const float* bv = (const float*)d_in[6];
    const float* wo = (const float*)d_in[7];
    const float* bo = (const float*)d_in[8];
    float* out = (float*)d_out;

    float* QKVp;
    cudaGetSymbolAddress((void**)&QKVp, g_QKV);
    __half *xhi, *xlo, *aohi, *aolo, *wqT, *wkT, *wvT, *woT;
    __half *qw, *kw, *vw;
    cudaGetSymbolAddress((void**)&xhi,  g_xhi);
    cudaGetSymbolAddress((void**)&xlo,  g_xlo);
    cudaGetSymbolAddress((void**)&aohi, g_aohi);
    cudaGetSymbolAddress((void**)&aolo, g_aolo);
    cudaGetSymbolAddress((void**)&wqT, g_wqT);
    cudaGetSymbolAddress((void**)&wkT, g_wkT);
    cudaGetSymbolAddress((void**)&wvT, g_wvT);
    cudaGetSymbolAddress((void**)&woT, g_woT);
    cudaGetSymbolAddress((void**)&qw,  g_Qw);
    cudaGetSymbolAddress((void**)&kw,  g_Kw);
    cudaGetSymbolAddress((void**)&vw,  g_Vw);

    cudaFuncSetAttribute(gemm_qkv_kernel,
                         cudaFuncAttributeMaxDynamicSharedMemorySize, GSMEM);
    cudaFuncSetAttribute(gemm_f16x2_kernel,
                         cudaFuncAttributeMaxDynamicSharedMemorySize, GSMEM);
    cudaFuncSetAttribute(flash_mma_kernel,
                         cudaFuncAttributeMaxDynamicSharedMemorySize, FSMEM);

    // conversions
    {
        int n4 = M_ * E_ / 4;
        convert_hilo_h_kernel<<<(n4 + 255) / 256, 256>>>(x, xhi, xlo, n4);
        dim3 blk(32, 8);
        transpose_h_kernel<<<dim3(E_ / 32, E_ / 32), blk>>>(wq, wqT, E_, E_);
        transpose_h_kv_kernel<<<dim3((KVH_ * HD_) / 32, E_ / 32, 2), blk>>>(
            wk, wv, wkT, wvT);
    }

    // Fused QKV projection (N = 3072, M-tile 128)
    gemm_qkv_kernel<<<dim3(NQKV / 128, M_ / 128), 256, GSMEM>>>(
        xhi, xlo, wqT, wkT, wvT, bq, bk, bv, QKVp);

    // RoPE + relayout (all single fp16)
    {
        int totq = B_ * S_ * H_ * (HD_ / 2);
        int totk = B_ * S_ * KVH_ * (HD_ / 2);
        rope_q_kernel<<<(totq + 255) / 256, 256>>>(QKVp, qw);
        rope_k_kernel<<<(totk + 255) / 256, 256>>>(QKVp, kw);
        v_single_kernel<<<(totk + 255) / 256, 256>>>(QKVp, vw);
    }

    // Flash attention (fp16 1-MMA per product) -> fp16 hi/lo output
    flash_mma_kernel<<<dim3(S_ / 128, H_, B_), 256, FSMEM>>>(
        qw, kw, vw, aohi, aolo);

    // wo transpose (deferred; only needed by O-proj)
    {
        dim3 blk(32, 8);
        transpose_h_kernel<<<dim3(E_ / 32, E_ / 32), blk>>>(wo, woT, E_, E_);
    }

    // Output projection -> d_out (M-tile 128)
    gemm_f16x2_kernel<<<dim3(E_ / 128, M_ / 128), 256, GSMEM>>>(
        aohi, aolo, woT, bo, out, M_, E_, E_);
}